// round 7
// baseline (speedup 1.0000x reference)
#include <cuda_runtime.h>
#include <cuda_bf16.h>
#include <cstdint>

#define NB      256      // batch
#define SEQ     65
#define HID     512
#define HEADS   8
#define NP      64       // patches
#define PDIM    256
#define ROWS    (NB*SEQ) // 16640
#define OUTD    10

// ---------------- scratch (__device__ globals; no runtime alloc) ----------------
__device__ float g_Z [NB*SEQ*HID];            // 34 MB
__device__ float g_Zn[NB*SEQ*HID];            // 34 MB
__device__ float g_R [NB*SEQ*HID];            // 34 MB
__device__ float g_E [NB*NP*HID];             // 33.5 MB
__device__ float g_Q [HEADS*ROWS*HID];        // 272 MB  [h][n*SEQ+s][e]
__device__ float g_K [HEADS*ROWS*HID];        // 272 MB
__device__ float g_V [HEADS*ROWS*HID];        // 272 MB
__device__ float g_Hc[(long)ROWS*HEADS*HID];  // 272 MB  [n*SEQ+s][h*HID+e]

// ---------------- tf32 helpers ----------------
__device__ __forceinline__ uint32_t f2tf(float f)
{
    uint32_t u;
    asm("cvt.rna.tf32.f32 %0, %1;" : "=r"(u) : "f"(f));
    return u;
}

__device__ __forceinline__ void mma_tf32(float c[4], const uint32_t a[4], const uint32_t b[2])
{
    asm volatile(
        "mma.sync.aligned.m16n8k8.row.col.f32.tf32.tf32.f32 "
        "{%0,%1,%2,%3},{%4,%5,%6,%7},{%8,%9},{%0,%1,%2,%3};"
        : "+f"(c[0]), "+f"(c[1]), "+f"(c[2]), "+f"(c[3])
        : "r"(a[0]), "r"(a[1]), "r"(a[2]), "r"(a[3]),
          "r"(b[0]), "r"(b[1]));
}

// ---------------- 3xTF32 tensor-core GEMM: 128x128 block, BK=16, 8 warps (4x2) ----------------
// C[z] = A[z] @ B[z] (+bias[z]) (+res)    A:[M,K] lda k-contig, B:[K,N] ldb n-contig
// Error-compensated: a = a_hi + a_lo (both tf32); acc += a_hi*b_hi + a_hi*b_lo + a_lo*b_hi
// Requires M%128==0, N%128==0, K%16==0 (true at all call sites)
__global__ __launch_bounds__(256)
void gemm_tc(const float* __restrict__ A, const float* __restrict__ B,
             float* __restrict__ C, int K, int lda, int ldb, int ldc,
             const float* __restrict__ bias, long biasStride,
             const float* __restrict__ res, int ldres,
             long strideA, long strideB, long strideC)
{
    // fragment-order SMEM, [hilo] doubled for error compensation
    __shared__ uint32_t Af[2][2][8][32][4];   // [hilo][ksub][msub][lane][slot]  16 KB
    __shared__ uint32_t Bf[2][2][16][32][2];  // [hilo][ksub][nsub][lane][slot]  16 KB

    const float* Az = A + (long)blockIdx.z * strideA;
    const float* Bz = B + (long)blockIdx.z * strideB;
    float* Cz = C + (long)blockIdx.z * strideC;
    const float* bz = bias ? (bias + (long)blockIdx.z * biasStride) : nullptr;

    const int tid = threadIdx.x;
    const int wid = tid >> 5, lane = tid & 31;
    const int warp_m = wid >> 1, warp_n = wid & 1;   // 4 x 2 warps
    const int m0 = blockIdx.x * 128, n0 = blockIdx.y * 128;

    float acc[2][8][4];
#pragma unroll
    for (int mi = 0; mi < 2; mi++)
#pragma unroll
        for (int ni = 0; ni < 8; ni++)
#pragma unroll
            for (int j = 0; j < 4; j++) acc[mi][ni][j] = 0.f;

    for (int k0 = 0; k0 < K; k0 += 16) {
        // ---- A tile 128x16 -> Af hi/lo (fragment order), 2 float4 per thread ----
#pragma unroll
        for (int l = 0; l < 2; l++) {
            int idx = tid + l * 256;
            int row = idx >> 2, kc = (idx & 3) * 4;
            float4 f = *(const float4*)&Az[(long)(m0 + row) * lda + k0 + kc];
            int msub = row >> 4, r = row & 15;
            float vv[4] = {f.x, f.y, f.z, f.w};
#pragma unroll
            for (int j = 0; j < 4; j++) {
                int k = kc + j, ksub = k >> 3, c = k & 7;
                int li = ((r & 7) << 2) | (c & 3);
                int sl = (r >> 3) | ((c >> 2) << 1);
                uint32_t hi = f2tf(vv[j]);
                uint32_t lo = f2tf(vv[j] - __uint_as_float(hi));
                Af[0][ksub][msub][li][sl] = hi;
                Af[1][ksub][msub][li][sl] = lo;
            }
        }
        // ---- B tile 16x128 -> Bf hi/lo (fragment order), 2 float4 per thread ----
#pragma unroll
        for (int l = 0; l < 2; l++) {
            int idx = tid + l * 256;
            int kk = idx >> 5, nc = (idx & 31) * 4;
            float4 f = *(const float4*)&Bz[(long)(k0 + kk) * ldb + n0 + nc];
            int ksub = kk >> 3, ck = kk & 7, slot = ck >> 2;
            float vv[4] = {f.x, f.y, f.z, f.w};
#pragma unroll
            for (int j = 0; j < 4; j++) {
                int n = nc + j, nsub = n >> 3, cn = n & 7;
                int li = (cn << 2) | (ck & 3);
                uint32_t hi = f2tf(vv[j]);
                uint32_t lo = f2tf(vv[j] - __uint_as_float(hi));
                Bf[0][ksub][nsub][li][slot] = hi;
                Bf[1][ksub][nsub][li][slot] = lo;
            }
        }
        __syncthreads();

#pragma unroll
        for (int ks = 0; ks < 2; ks++) {
            uint32_t ah[2][4], al[2][4], bh[8][2], bl[8][2];
#pragma unroll
            for (int mi = 0; mi < 2; mi++) {
                uint4 t = *(const uint4*)&Af[0][ks][(warp_m << 1) + mi][lane][0];
                ah[mi][0] = t.x; ah[mi][1] = t.y; ah[mi][2] = t.z; ah[mi][3] = t.w;
                uint4 u = *(const uint4*)&Af[1][ks][(warp_m << 1) + mi][lane][0];
                al[mi][0] = u.x; al[mi][1] = u.y; al[mi][2] = u.z; al[mi][3] = u.w;
            }
#pragma unroll
            for (int ni = 0; ni < 8; ni++) {
                uint2 t = *(const uint2*)&Bf[0][ks][(warp_n << 3) + ni][lane][0];
                bh[ni][0] = t.x; bh[ni][1] = t.y;
                uint2 u = *(const uint2*)&Bf[1][ks][(warp_n << 3) + ni][lane][0];
                bl[ni][0] = u.x; bl[ni][1] = u.y;
            }
#pragma unroll
            for (int mi = 0; mi < 2; mi++)
#pragma unroll
                for (int ni = 0; ni < 8; ni++) {
                    mma_tf32(acc[mi][ni], al[mi], bh[ni]);   // lo*hi
                    mma_tf32(acc[mi][ni], ah[mi], bl[ni]);   // hi*lo
                    mma_tf32(acc[mi][ni], ah[mi], bh[ni]);   // hi*hi
                }
        }
        __syncthreads();
    }

    // ---- epilogue ----
    const int r = lane >> 2, c2 = (lane & 3) << 1;
#pragma unroll
    for (int mi = 0; mi < 2; mi++) {
#pragma unroll
        for (int hh = 0; hh < 2; hh++) {
            int m = m0 + warp_m * 32 + mi * 16 + hh * 8 + r;
#pragma unroll
            for (int ni = 0; ni < 8; ni++) {
                int col = n0 + warp_n * 64 + ni * 8 + c2;
                float x0 = acc[mi][ni][hh * 2 + 0];
                float x1 = acc[mi][ni][hh * 2 + 1];
                if (bz) { x0 += bz[col]; x1 += bz[col + 1]; }
                if (res) {
                    float2 rr = *(const float2*)&res[(long)m * ldres + col];
                    x0 += rr.x; x1 += rr.y;
                }
                float2 o; o.x = x0; o.y = x1;
                *(float2*)&Cz[(long)m * ldc + col] = o;
            }
        }
    }
}

// ---------------- assemble Z = concat(cls, E) + pos ----------------
__global__ void assemble_kernel(const float* __restrict__ cls, const float* __restrict__ pos)
{
    long idx = (long)blockIdx.x * 256 + threadIdx.x;
    if (idx >= (long)NB * SEQ * HID) return;
    int e = (int)(idx % HID);
    long r = idx / HID;
    int s = (int)(r % SEQ);
    long n = r / SEQ;
    float v = pos[s * HID + e];
    if (s == 0) v += cls[e];
    else        v += g_E[(n * NP + (s - 1)) * (long)HID + e];
    g_Z[idx] = v;
}

// ---------------- LayerNorm over whole (SEQ,HID) slab per sample ----------------
__global__ __launch_bounds__(1024)
void ln_kernel(const float* __restrict__ in, float* __restrict__ out,
               const float* __restrict__ w, const float* __restrict__ b)
{
    const int n = blockIdx.x;
    const float* x = in + (long)n * SEQ * HID;
    float* y = out + (long)n * SEQ * HID;
    float s = 0.f, ss = 0.f;
    for (int i = threadIdx.x; i < SEQ * HID; i += 1024) {
        float v = x[i]; s += v; ss += v * v;
    }
    __shared__ float red[64];
#pragma unroll
    for (int o = 16; o; o >>= 1) {
        s  += __shfl_down_sync(0xffffffffu, s, o);
        ss += __shfl_down_sync(0xffffffffu, ss, o);
    }
    int wid = threadIdx.x >> 5, lane = threadIdx.x & 31;
    if (lane == 0) { red[wid] = s; red[32 + wid] = ss; }
    __syncthreads();
    if (threadIdx.x == 0) {
        float S = 0.f, SS = 0.f;
        for (int i = 0; i < 32; i++) { S += red[i]; SS += red[32 + i]; }
        float inv = 1.0f / (SEQ * HID);
        float mu = S * inv;
        float var = SS * inv - mu * mu;
        red[0] = mu; red[1] = rsqrtf(var + 1e-5f);
    }
    __syncthreads();
    float mu = red[0], rinv = red[1];
    for (int i = threadIdx.x; i < SEQ * HID; i += 1024)
        y[i] = (x[i] - mu) * rinv * w[i] + b[i];
}

// ---------------- attention per (h, n): register-tiled SIMT ----------------
// scores = q @ k^T * scale -> softmax -> O = attn @ v -> Hc[:, h*512:(h+1)*512]
__global__ __launch_bounds__(256)
void attn_kernel()
{
    const int h = blockIdx.x, n = blockIdx.y;
    const float* q = g_Q + ((long)h * ROWS + (long)n * SEQ) * HID;
    const float* k = g_K + ((long)h * ROWS + (long)n * SEQ) * HID;
    const float* v = g_V + ((long)h * ROWS + (long)n * SEQ) * HID;
    float* out = g_Hc + (long)n * SEQ * (HEADS * HID) + h * HID;

    __shared__ float sc[SEQ][SEQ + 3];   // 65x68, 17.7 KB
    __shared__ float work[SEQ][66];      // q cols [0,32), k cols [33,65)

    const int tid = threadIdx.x;
    const int tx = tid & 15, ty = tid >> 4;

    // --- scores: 5x5 register microtile per thread over 80x80 padded grid ---
    float acc[5][5];
#pragma unroll
    for (int i = 0; i < 5; i++)
#pragma unroll
        for (int j = 0; j < 5; j++) acc[i][j] = 0.f;

    int rs[5], cs[5];
#pragma unroll
    for (int i = 0; i < 5; i++) {
        int s = ty + 16 * i; rs[i] = (s < SEQ) ? s : SEQ - 1;
        int t = tx + 16 * i; cs[i] = (t < SEQ) ? t : SEQ - 1;
    }

    for (int k0 = 0; k0 < HID; k0 += 32) {
        for (int i = tid; i < SEQ * 32; i += 256) {
            int s = i >> 5, j = i & 31;
            work[s][j]      = q[s * HID + k0 + j];
            work[s][33 + j] = k[s * HID + k0 + j];
        }
        __syncthreads();
#pragma unroll 4
        for (int j = 0; j < 32; j++) {
            float qv[5], kv[5];
#pragma unroll
            for (int i = 0; i < 5; i++) qv[i] = work[rs[i]][j];
#pragma unroll
            for (int i = 0; i < 5; i++) kv[i] = work[cs[i]][33 + j];
#pragma unroll
            for (int i = 0; i < 5; i++)
#pragma unroll
                for (int jj = 0; jj < 5; jj++) acc[i][jj] += qv[i] * kv[jj];
        }
        __syncthreads();
    }

#pragma unroll
    for (int i = 0; i < 5; i++) {
        int s = ty + 16 * i;
        if (s < SEQ) {
#pragma unroll
            for (int jj = 0; jj < 5; jj++) {
                int t = tx + 16 * jj;
                if (t < SEQ) sc[s][t] = acc[i][jj];
            }
        }
    }
    __syncthreads();

    // --- softmax rows (scale = 1/512^2 per reference) ---
    if (tid < SEQ) {
        const float scale = 1.0f / (512.0f * 512.0f);
        float m = -1e30f;
        for (int t = 0; t < SEQ; t++) m = fmaxf(m, sc[tid][t] * scale);
        float sum = 0.f;
        for (int t = 0; t < SEQ; t++) {
            float e = __expf(sc[tid][t] * scale - m);
            sc[tid][t] = e; sum += e;
        }
        float rr = 1.0f / sum;
        for (int t = 0; t < SEQ; t++) sc[tid][t] *= rr;
    }
    __syncthreads();

    // --- O = attn @ v : 5x4 microtile, e in 64-wide chunks ---
    for (int e0 = 0; e0 < HID; e0 += 64) {
        for (int i = tid; i < SEQ * 64; i += 256) {
            int t = i >> 6, j = i & 63;
            work[t][j] = v[t * HID + e0 + j];
        }
        __syncthreads();
        float acc2[5][4];
#pragma unroll
        for (int i = 0; i < 5; i++)
#pragma unroll
            for (int j = 0; j < 4; j++) acc2[i][j] = 0.f;

        for (int t = 0; t < SEQ; t++) {
            float sv[5], vv[4];
#pragma unroll
            for (int i = 0; i < 5; i++) sv[i] = sc[rs[i]][t];
#pragma unroll
            for (int j = 0; j < 4; j++) vv[j] = work[t][tx + 16 * j];
#pragma unroll
            for (int i = 0; i < 5; i++)
#pragma unroll
                for (int j = 0; j < 4; j++) acc2[i][j] += sv[i] * vv[j];
        }
#pragma unroll
        for (int i = 0; i < 5; i++) {
            int s = ty + 16 * i;
            if (s < SEQ) {
#pragma unroll
                for (int j = 0; j < 4; j++)
                    out[(long)s * (HEADS * HID) + e0 + tx + 16 * j] = acc2[i][j];
            }
        }
        __syncthreads();
    }
}

// ---------------- classification head ----------------
__global__ void head_kernel(const float* __restrict__ Wh, const float* __restrict__ bh,
                            float* __restrict__ out)
{
    const int n = blockIdx.x;
    const int o = threadIdx.y;       // 10
    const int lane = threadIdx.x;    // 32
    const float* z = g_Z + (long)n * SEQ * HID;  // row s=0
    float a = 0.f;
    for (int e = lane; e < HID; e += 32) a += z[e] * Wh[e * OUTD + o];
#pragma unroll
    for (int off = 16; off; off >>= 1) a += __shfl_down_sync(0xffffffffu, a, off);
    if (lane == 0) out[n * OUTD + o] = tanhf(a + bh[o]);
}

// ---------------- host launcher ----------------
static float* sym_addr(const void* symbol)
{
    void* p = nullptr;
    cudaGetSymbolAddress(&p, symbol);
    return (float*)p;
}

extern "C" void kernel_launch(void* const* d_in, const int* in_sizes, int n_in,
                              void* d_out, int out_size)
{
    const float* X    = (const float*)d_in[0];
    const float* Wp   = (const float*)d_in[1];
    const float* bp   = (const float*)d_in[2];
    const float* cls  = (const float*)d_in[3];
    const float* pos  = (const float*)d_in[4];
    const float* ln1w = (const float*)d_in[5];
    const float* ln1b = (const float*)d_in[6];
    const float* Wq   = (const float*)d_in[7];
    const float* bq   = (const float*)d_in[8];
    const float* Wk   = (const float*)d_in[9];
    const float* bk   = (const float*)d_in[10];
    const float* Wv   = (const float*)d_in[11];
    const float* bv   = (const float*)d_in[12];
    const float* Wo   = (const float*)d_in[13];
    const float* bo   = (const float*)d_in[14];
    const float* ln2w = (const float*)d_in[15];
    const float* ln2b = (const float*)d_in[16];
    const float* W2   = (const float*)d_in[17];
    const float* b2   = (const float*)d_in[18];
    const float* Wh   = (const float*)d_in[19];
    const float* bh   = (const float*)d_in[20];
    float* out = (float*)d_out;

    float* Z  = sym_addr(g_Z);
    float* Zn = sym_addr(g_Zn);
    float* R  = sym_addr(g_R);
    float* E  = sym_addr(g_E);
    float* Q  = sym_addr(g_Q);
    float* Kb = sym_addr(g_K);
    float* V  = sym_addr(g_V);
    float* Hc = sym_addr(g_Hc);

    const long WSTRIDE = (long)HID * HID;   // per-head weight stride
    const long QSTRIDE = (long)ROWS * HID;  // per-head activation stride

    // 1) patch embed: E = X(as [16384,256]) @ Wp + bp
    {
        dim3 grid((NB * NP) / 128, HID / 128, 1);
        gemm_tc<<<grid, 256>>>(X, Wp, E, PDIM, PDIM, HID, HID,
                               bp, 0, nullptr, 0, 0, 0, 0);
    }
    // 2) Z = concat(cls, E) + pos
    {
        long total = (long)NB * SEQ * HID;
        assemble_kernel<<<(unsigned)((total + 255) / 256), 256>>>(cls, pos);
    }

    dim3 gQKV(ROWS / 128, HID / 128, HEADS);
    dim3 gRow(ROWS / 128, HID / 128, 1);

    for (int blk = 0; blk < 6; blk++) {
        // LN1: Z -> Zn
        ln_kernel<<<NB, 1024>>>(Z, Zn, ln1w, ln1b);

        // Q/K/V per-head GEMMs batched over blockIdx.z
        gemm_tc<<<gQKV, 256>>>(Zn, Wq, Q, HID, HID, HID, HID,
                               bq, HID, nullptr, 0, 0, WSTRIDE, QSTRIDE);
        gemm_tc<<<gQKV, 256>>>(Zn, Wk, Kb, HID, HID, HID, HID,
                               bk, HID, nullptr, 0, 0, WSTRIDE, QSTRIDE);
        gemm_tc<<<gQKV, 256>>>(Zn, Wv, V, HID, HID, HID, HID,
                               bv, HID, nullptr, 0, 0, WSTRIDE, QSTRIDE);

        // attention -> Hcat
        attn_kernel<<<dim3(HEADS, NB), 256>>>();

        // R = Hcat @ Wo + bo + Z (fused residual), K = 4096
        gemm_tc<<<gRow, 256>>>(Hc, Wo, R, HEADS * HID, HEADS * HID, HID, HID,
                               bo, 0, Z, HID, 0, 0, 0);

        // LN2: R -> Zn
        ln_kernel<<<NB, 1024>>>(R, Zn, ln2w, ln2b);

        // Z = Zn @ W2 + b2
        gemm_tc<<<gRow, 256>>>(Zn, W2, Z, HID, HID, HID, HID,
                               b2, 0, nullptr, 0, 0, 0, 0);
    }

    // head: out = tanh(Z[:,0] @ Wh + bh)
    head_kernel<<<NB, dim3(32, 10)>>>(Wh, bh, out);
    (void)in_sizes; (void)n_in; (void)out_size;
}

// round 8
// speedup vs baseline: 2.5768x; 2.5768x over previous
#include <cuda_runtime.h>
#include <cuda_bf16.h>
#include <cstdint>

#define NB      256      // batch
#define SEQ     65
#define HID     512
#define HEADS   8
#define NP      64       // patches
#define PDIM    256
#define ROWS    (NB*SEQ) // 16640
#define OUTD    10

// ---------------- scratch (__device__ globals; no runtime alloc) ----------------
__device__ float g_Z [NB*SEQ*HID];            // 34 MB
__device__ float g_Zn[NB*SEQ*HID];            // 34 MB
__device__ float g_R [NB*SEQ*HID];            // 34 MB
__device__ float g_E [NB*NP*HID];             // 33.5 MB
__device__ float g_Q [HEADS*ROWS*HID];        // 272 MB  [h][n*SEQ+s][e]
__device__ float g_K [HEADS*ROWS*HID];        // 272 MB
__device__ float g_V [HEADS*ROWS*HID];        // 272 MB
__device__ float g_Hc[(long)ROWS*HEADS*HID];  // 272 MB  [n*SEQ+s][h*HID+e]

// ---------------- helpers ----------------
__device__ __forceinline__ uint32_t s2u(const void* p)
{
    uint32_t a;
    asm("{ .reg .u64 t; cvta.to.shared.u64 t, %1; cvt.u32.u64 %0, t; }" : "=r"(a) : "l"(p));
    return a;
}

__device__ __forceinline__ void ldsm4(uint32_t& r0, uint32_t& r1, uint32_t& r2, uint32_t& r3,
                                      uint32_t addr)
{
    asm volatile("ldmatrix.sync.aligned.m8n8.x4.shared.b16 {%0,%1,%2,%3}, [%4];"
                 : "=r"(r0), "=r"(r1), "=r"(r2), "=r"(r3) : "r"(addr));
}

__device__ __forceinline__ void ldsm4t(uint32_t& r0, uint32_t& r1, uint32_t& r2, uint32_t& r3,
                                       uint32_t addr)
{
    asm volatile("ldmatrix.sync.aligned.m8n8.x4.trans.shared.b16 {%0,%1,%2,%3}, [%4];"
                 : "=r"(r0), "=r"(r1), "=r"(r2), "=r"(r3) : "r"(addr));
}

__device__ __forceinline__ void mma_bf16(float c[4], const uint32_t a[4], const uint32_t b[2])
{
    asm volatile(
        "mma.sync.aligned.m16n8k16.row.col.f32.bf16.bf16.f32 "
        "{%0,%1,%2,%3},{%4,%5,%6,%7},{%8,%9},{%0,%1,%2,%3};"
        : "+f"(c[0]), "+f"(c[1]), "+f"(c[2]), "+f"(c[3])
        : "r"(a[0]), "r"(a[1]), "r"(a[2]), "r"(a[3]),
          "r"(b[0]), "r"(b[1]));
}

// split two consecutive f32 into packed bf16x2 hi and lo planes (x = lower address)
__device__ __forceinline__ void split2(float x, float y, uint32_t& hi, uint32_t& lo)
{
    __nv_bfloat16 hx = __float2bfloat16(x);
    __nv_bfloat16 hy = __float2bfloat16(y);
    float rx = x - __bfloat162float(hx);
    float ry = y - __bfloat162float(hy);
    __nv_bfloat162 h2; h2.x = hx; h2.y = hy;
    __nv_bfloat162 l2; l2.x = __float2bfloat16(rx); l2.y = __float2bfloat16(ry);
    hi = *reinterpret_cast<uint32_t*>(&h2);
    lo = *reinterpret_cast<uint32_t*>(&l2);
}

// ---------------- bf16-pair (error-compensated) tensor GEMM ----------------
// C[z] = A[z] @ B[z] (+bias[z]) (+res)   A:[M,K] lda k-contig, B:[K,N] ldb n-contig
// acc += a_hi*b_hi + a_hi*b_lo + a_lo*b_hi  (bf16 splits, f32 accum)
// Tiles: BM=128, BN=64, BK=32. Requires M%128==0, N%64==0, K%32==0.
#define BMT 128
#define BNT 64
#define BKT 32

__global__ __launch_bounds__(256, 2)
void gemm_bf(const float* __restrict__ A, const float* __restrict__ B,
             float* __restrict__ C, int K, int lda, int ldb, int ldc,
             const float* __restrict__ bias, long biasStride,
             const float* __restrict__ res, int ldres,
             long strideA, long strideB, long strideC)
{
    __shared__ __align__(16) __nv_bfloat16 smA[2][128][40];  // [plane][m][k+pad]  20.5 KB
    __shared__ __align__(16) __nv_bfloat16 smB[2][32][72];   // [plane][k][n+pad]   9.2 KB

    const float* Az = A + (long)blockIdx.z * strideA;
    const float* Bz = B + (long)blockIdx.z * strideB;
    float* Cz = C + (long)blockIdx.z * strideC;
    const float* bz = bias ? (bias + (long)blockIdx.z * biasStride) : nullptr;

    const int tid = threadIdx.x, lane = tid & 31, wid = tid >> 5;
    const int warp_m = wid >> 1, warp_n = wid & 1;           // 4 x 2 warps, 32x32 warp tile
    const int m0 = blockIdx.x * BMT, n0 = blockIdx.y * BNT;

    // loader mapping
    const int arow = tid & 127, ahalf = tid >> 7;   // A: 16 k-elems at k=ahalf*16
    const int bkrow = tid & 31, bseg = tid >> 5;    // B: 8 n-elems at n=bseg*8

    // ldmatrix lane address components
    const int lrow = (lane & 7) + ((lane >> 3) & 1) * 8;
    const int lcol = (lane >> 4) * 8;

    const uint32_t AL_D = 128 * 40 * 2;   // plane delta bytes
    const uint32_t BL_D = 32 * 72 * 2;

    uint32_t aAddr[2], bAddr[2];
#pragma unroll
    for (int mi = 0; mi < 2; mi++)
        aAddr[mi] = s2u(&smA[0][warp_m * 32 + mi * 16 + lrow][lcol]);
#pragma unroll
    for (int nb = 0; nb < 2; nb++)
        bAddr[nb] = s2u(&smB[0][lrow][warp_n * 32 + nb * 16 + lcol]);

    uint32_t aSt = s2u(&smA[0][arow][ahalf * 16]);
    uint32_t bSt = s2u(&smB[0][bkrow][bseg * 8]);

    float acc[2][4][4];
#pragma unroll
    for (int mi = 0; mi < 2; mi++)
#pragma unroll
        for (int ni = 0; ni < 4; ni++)
#pragma unroll
            for (int j = 0; j < 4; j++) acc[mi][ni][j] = 0.f;

    for (int k0 = 0; k0 < K; k0 += BKT) {
        // ---- load + split A: 4 float4 per thread ----
        {
            const float4* pA = (const float4*)(Az + (long)(m0 + arow) * lda + k0 + ahalf * 16);
            uint32_t hi[8], lo[8];
#pragma unroll
            for (int j = 0; j < 4; j++) {
                float4 f = pA[j];
                split2(f.x, f.y, hi[j * 2 + 0], lo[j * 2 + 0]);
                split2(f.z, f.w, hi[j * 2 + 1], lo[j * 2 + 1]);
            }
            uint4* dh = (uint4*)(uintptr_t)0;  // placeholder to keep types clear
            (void)dh;
            uint4 v0 = make_uint4(hi[0], hi[1], hi[2], hi[3]);
            uint4 v1 = make_uint4(hi[4], hi[5], hi[6], hi[7]);
            uint4 w0 = make_uint4(lo[0], lo[1], lo[2], lo[3]);
            uint4 w1 = make_uint4(lo[4], lo[5], lo[6], lo[7]);
            asm volatile("st.shared.v4.b32 [%0], {%1,%2,%3,%4};" :: "r"(aSt), "r"(v0.x), "r"(v0.y), "r"(v0.z), "r"(v0.w));
            asm volatile("st.shared.v4.b32 [%0], {%1,%2,%3,%4};" :: "r"(aSt + 16), "r"(v1.x), "r"(v1.y), "r"(v1.z), "r"(v1.w));
            asm volatile("st.shared.v4.b32 [%0], {%1,%2,%3,%4};" :: "r"(aSt + AL_D), "r"(w0.x), "r"(w0.y), "r"(w0.z), "r"(w0.w));
            asm volatile("st.shared.v4.b32 [%0], {%1,%2,%3,%4};" :: "r"(aSt + AL_D + 16), "r"(w1.x), "r"(w1.y), "r"(w1.z), "r"(w1.w));
        }
        // ---- load + split B: 2 float4 per thread ----
        {
            const float4* pB = (const float4*)(Bz + (long)(k0 + bkrow) * ldb + n0 + bseg * 8);
            uint32_t hi[4], lo[4];
#pragma unroll
            for (int j = 0; j < 2; j++) {
                float4 f = pB[j];
                split2(f.x, f.y, hi[j * 2 + 0], lo[j * 2 + 0]);
                split2(f.z, f.w, hi[j * 2 + 1], lo[j * 2 + 1]);
            }
            asm volatile("st.shared.v4.b32 [%0], {%1,%2,%3,%4};" :: "r"(bSt), "r"(hi[0]), "r"(hi[1]), "r"(hi[2]), "r"(hi[3]));
            asm volatile("st.shared.v4.b32 [%0], {%1,%2,%3,%4};" :: "r"(bSt + BL_D), "r"(lo[0]), "r"(lo[1]), "r"(lo[2]), "r"(lo[3]));
        }
        __syncthreads();

#pragma unroll
        for (int ks = 0; ks < 2; ks++) {
            uint32_t ah[2][4], al[2][4], bh[4][2], bl[4][2];
#pragma unroll
            for (int mi = 0; mi < 2; mi++) {
                ldsm4(ah[mi][0], ah[mi][1], ah[mi][2], ah[mi][3], aAddr[mi] + ks * 32);
                ldsm4(al[mi][0], al[mi][1], al[mi][2], al[mi][3], aAddr[mi] + AL_D + ks * 32);
            }
#pragma unroll
            for (int nb = 0; nb < 2; nb++) {
                uint32_t r0, r1, r2, r3;
                ldsm4t(r0, r1, r2, r3, bAddr[nb] + ks * (16 * 72 * 2));
                bh[nb * 2 + 0][0] = r0; bh[nb * 2 + 0][1] = r1;
                bh[nb * 2 + 1][0] = r2; bh[nb * 2 + 1][1] = r3;
                ldsm4t(r0, r1, r2, r3, bAddr[nb] + BL_D + ks * (16 * 72 * 2));
                bl[nb * 2 + 0][0] = r0; bl[nb * 2 + 0][1] = r1;
                bl[nb * 2 + 1][0] = r2; bl[nb * 2 + 1][1] = r3;
            }
#pragma unroll
            for (int mi = 0; mi < 2; mi++)
#pragma unroll
                for (int ni = 0; ni < 4; ni++) {
                    mma_bf16(acc[mi][ni], al[mi], bh[ni]);   // lo*hi
                    mma_bf16(acc[mi][ni], ah[mi], bl[ni]);   // hi*lo
                    mma_bf16(acc[mi][ni], ah[mi], bh[ni]);   // hi*hi
                }
        }
        __syncthreads();
    }

    // ---- epilogue ----
    const int r = lane >> 2, c2 = (lane & 3) << 1;
#pragma unroll
    for (int mi = 0; mi < 2; mi++) {
#pragma unroll
        for (int hh = 0; hh < 2; hh++) {
            int m = m0 + warp_m * 32 + mi * 16 + hh * 8 + r;
#pragma unroll
            for (int ni = 0; ni < 4; ni++) {
                int col = n0 + warp_n * 32 + ni * 8 + c2;
                float x0 = acc[mi][ni][hh * 2 + 0];
                float x1 = acc[mi][ni][hh * 2 + 1];
                if (bz) { x0 += bz[col]; x1 += bz[col + 1]; }
                if (res) {
                    float2 rr = *(const float2*)&res[(long)m * ldres + col];
                    x0 += rr.x; x1 += rr.y;
                }
                float2 o; o.x = x0; o.y = x1;
                *(float2*)&Cz[(long)m * ldc + col] = o;
            }
        }
    }
}

// ---------------- assemble Z = concat(cls, E) + pos ----------------
__global__ void assemble_kernel(const float* __restrict__ cls, const float* __restrict__ pos)
{
    long idx = (long)blockIdx.x * 256 + threadIdx.x;
    if (idx >= (long)NB * SEQ * HID) return;
    int e = (int)(idx % HID);
    long r = idx / HID;
    int s = (int)(r % SEQ);
    long n = r / SEQ;
    float v = pos[s * HID + e];
    if (s == 0) v += cls[e];
    else        v += g_E[(n * NP + (s - 1)) * (long)HID + e];
    g_Z[idx] = v;
}

// ---------------- LayerNorm over whole (SEQ,HID) slab per sample ----------------
__global__ __launch_bounds__(1024)
void ln_kernel(const float* __restrict__ in, float* __restrict__ out,
               const float* __restrict__ w, const float* __restrict__ b)
{
    const int n = blockIdx.x;
    const float* x = in + (long)n * SEQ * HID;
    float* y = out + (long)n * SEQ * HID;
    float s = 0.f, ss = 0.f;
    for (int i = threadIdx.x; i < SEQ * HID; i += 1024) {
        float v = x[i]; s += v; ss += v * v;
    }
    __shared__ float red[64];
#pragma unroll
    for (int o = 16; o; o >>= 1) {
        s  += __shfl_down_sync(0xffffffffu, s, o);
        ss += __shfl_down_sync(0xffffffffu, ss, o);
    }
    int wid = threadIdx.x >> 5, lane = threadIdx.x & 31;
    if (lane == 0) { red[wid] = s; red[32 + wid] = ss; }
    __syncthreads();
    if (threadIdx.x == 0) {
        float S = 0.f, SS = 0.f;
        for (int i = 0; i < 32; i++) { S += red[i]; SS += red[32 + i]; }
        float inv = 1.0f / (SEQ * HID);
        float mu = S * inv;
        float var = SS * inv - mu * mu;
        red[0] = mu; red[1] = rsqrtf(var + 1e-5f);
    }
    __syncthreads();
    float mu = red[0], rinv = red[1];
    for (int i = threadIdx.x; i < SEQ * HID; i += 1024)
        y[i] = (x[i] - mu) * rinv * w[i] + b[i];
}

// ---------------- attention per (h, n): register-tiled SIMT ----------------
__global__ __launch_bounds__(256)
void attn_kernel()
{
    const int h = blockIdx.x, n = blockIdx.y;
    const float* q = g_Q + ((long)h * ROWS + (long)n * SEQ) * HID;
    const float* k = g_K + ((long)h * ROWS + (long)n * SEQ) * HID;
    const float* v = g_V + ((long)h * ROWS + (long)n * SEQ) * HID;
    float* out = g_Hc + (long)n * SEQ * (HEADS * HID) + h * HID;

    __shared__ float sc[SEQ][SEQ + 3];
    __shared__ float work[SEQ][66];

    const int tid = threadIdx.x;
    const int tx = tid & 15, ty = tid >> 4;

    float acc[5][5];
#pragma unroll
    for (int i = 0; i < 5; i++)
#pragma unroll
        for (int j = 0; j < 5; j++) acc[i][j] = 0.f;

    int rs[5], cs[5];
#pragma unroll
    for (int i = 0; i < 5; i++) {
        int s = ty + 16 * i; rs[i] = (s < SEQ) ? s : SEQ - 1;
        int t = tx + 16 * i; cs[i] = (t < SEQ) ? t : SEQ - 1;
    }

    for (int k0 = 0; k0 < HID; k0 += 32) {
        for (int i = tid; i < SEQ * 32; i += 256) {
            int s = i >> 5, j = i & 31;
            work[s][j]      = q[s * HID + k0 + j];
            work[s][33 + j] = k[s * HID + k0 + j];
        }
        __syncthreads();
#pragma unroll 4
        for (int j = 0; j < 32; j++) {
            float qv[5], kv[5];
#pragma unroll
            for (int i = 0; i < 5; i++) qv[i] = work[rs[i]][j];
#pragma unroll
            for (int i = 0; i < 5; i++) kv[i] = work[cs[i]][33 + j];
#pragma unroll
            for (int i = 0; i < 5; i++)
#pragma unroll
                for (int jj = 0; jj < 5; jj++) acc[i][jj] += qv[i] * kv[jj];
        }
        __syncthreads();
    }

#pragma unroll
    for (int i = 0; i < 5; i++) {
        int s = ty + 16 * i;
        if (s < SEQ) {
#pragma unroll
            for (int jj = 0; jj < 5; jj++) {
                int t = tx + 16 * jj;
                if (t < SEQ) sc[s][t] = acc[i][jj];
            }
        }
    }
    __syncthreads();

    if (tid < SEQ) {
        const float scale = 1.0f / (512.0f * 512.0f);
        float m = -1e30f;
        for (int t = 0; t < SEQ; t++) m = fmaxf(m, sc[tid][t] * scale);
        float sum = 0.f;
        for (int t = 0; t < SEQ; t++) {
            float e = __expf(sc[tid][t] * scale - m);
            sc[tid][t] = e; sum += e;
        }
        float rr = 1.0f / sum;
        for (int t = 0; t < SEQ; t++) sc[tid][t] *= rr;
    }
    __syncthreads();

    for (int e0 = 0; e0 < HID; e0 += 64) {
        for (int i = tid; i < SEQ * 64; i += 256) {
            int t = i >> 6, j = i & 63;
            work[t][j] = v[t * HID + e0 + j];
        }
        __syncthreads();
        float acc2[5][4];
#pragma unroll
        for (int i = 0; i < 5; i++)
#pragma unroll
            for (int j = 0; j < 4; j++) acc2[i][j] = 0.f;

        for (int t = 0; t < SEQ; t++) {
            float sv[5], vv[4];
#pragma unroll
            for (int i = 0; i < 5; i++) sv[i] = sc[rs[i]][t];
#pragma unroll
            for (int j = 0; j < 4; j++) vv[j] = work[t][tx + 16 * j];
#pragma unroll
            for (int i = 0; i < 5; i++)
#pragma unroll
                for (int j = 0; j < 4; j++) acc2[i][j] += sv[i] * vv[j];
        }
#pragma unroll
        for (int i = 0; i < 5; i++) {
            int s = ty + 16 * i;
            if (s < SEQ) {
#pragma unroll
                for (int j = 0; j < 4; j++)
                    out[(long)s * (HEADS * HID) + e0 + tx + 16 * j] = acc2[i][j];
            }
        }
        __syncthreads();
    }
}

// ---------------- classification head ----------------
__global__ void head_kernel(const float* __restrict__ Wh, const float* __restrict__ bh,
                            float* __restrict__ out)
{
    const int n = blockIdx.x;
    const int o = threadIdx.y;       // 10
    const int lane = threadIdx.x;    // 32
    const float* z = g_Z + (long)n * SEQ * HID;  // row s=0
    float a = 0.f;
    for (int e = lane; e < HID; e += 32) a += z[e] * Wh[e * OUTD + o];
#pragma unroll
    for (int off = 16; off; off >>= 1) a += __shfl_down_sync(0xffffffffu, a, off);
    if (lane == 0) out[n * OUTD + o] = tanhf(a + bh[o]);
}

// ---------------- host launcher ----------------
static float* sym_addr(const void* symbol)
{
    void* p = nullptr;
    cudaGetSymbolAddress(&p, symbol);
    return (float*)p;
}

extern "C" void kernel_launch(void* const* d_in, const int* in_sizes, int n_in,
                              void* d_out, int out_size)
{
    const float* X    = (const float*)d_in[0];
    const float* Wp   = (const float*)d_in[1];
    const float* bp   = (const float*)d_in[2];
    const float* cls  = (const float*)d_in[3];
    const float* pos  = (const float*)d_in[4];
    const float* ln1w = (const float*)d_in[5];
    const float* ln1b = (const float*)d_in[6];
    const float* Wq   = (const float*)d_in[7];
    const float* bq   = (const float*)d_in[8];
    const float* Wk   = (const float*)d_in[9];
    const float* bk   = (const float*)d_in[10];
    const float* Wv   = (const float*)d_in[11];
    const float* bv   = (const float*)d_in[12];
    const float* Wo   = (const float*)d_in[13];
    const float* bo   = (const float*)d_in[14];
    const float* ln2w = (const float*)d_in[15];
    const float* ln2b = (const float*)d_in[16];
    const float* W2   = (const float*)d_in[17];
    const float* b2   = (const float*)d_in[18];
    const float* Wh   = (const float*)d_in[19];
    const float* bh   = (const float*)d_in[20];
    float* out = (float*)d_out;

    float* Z  = sym_addr(g_Z);
    float* Zn = sym_addr(g_Zn);
    float* R  = sym_addr(g_R);
    float* E  = sym_addr(g_E);
    float* Q  = sym_addr(g_Q);
    float* Kb = sym_addr(g_K);
    float* V  = sym_addr(g_V);
    float* Hc = sym_addr(g_Hc);

    const long WSTRIDE = (long)HID * HID;   // per-head weight stride
    const long QSTRIDE = (long)ROWS * HID;  // per-head activation stride

    // 1) patch embed: E = X(as [16384,256]) @ Wp + bp
    {
        dim3 grid((NB * NP) / BMT, HID / BNT, 1);
        gemm_bf<<<grid, 256>>>(X, Wp, E, PDIM, PDIM, HID, HID,
                               bp, 0, nullptr, 0, 0, 0, 0);
    }
    // 2) Z = concat(cls, E) + pos
    {
        long total = (long)NB * SEQ * HID;
        assemble_kernel<<<(unsigned)((total + 255) / 256), 256>>>(cls, pos);
    }

    dim3 gQKV(ROWS / BMT, HID / BNT, HEADS);
    dim3 gRow(ROWS / BMT, HID / BNT, 1);

    for (int blk = 0; blk < 6; blk++) {
        // LN1: Z -> Zn
        ln_kernel<<<NB, 1024>>>(Z, Zn, ln1w, ln1b);

        // Q/K/V per-head GEMMs batched over blockIdx.z
        gemm_bf<<<gQKV, 256>>>(Zn, Wq, Q, HID, HID, HID, HID,
                               bq, HID, nullptr, 0, 0, WSTRIDE, QSTRIDE);
        gemm_bf<<<gQKV, 256>>>(Zn, Wk, Kb, HID, HID, HID, HID,
                               bk, HID, nullptr, 0, 0, WSTRIDE, QSTRIDE);
        gemm_bf<<<gQKV, 256>>>(Zn, Wv, V, HID, HID, HID, HID,
                               bv, HID, nullptr, 0, 0, WSTRIDE, QSTRIDE);

        // attention -> Hcat
        attn_kernel<<<dim3(HEADS, NB), 256>>>();

        // R = Hcat @ Wo + bo + Z (fused residual), K = 4096
        gemm_bf<<<gRow, 256>>>(Hc, Wo, R, HEADS * HID, HEADS * HID, HID, HID,
                               bo, 0, Z, HID, 0, 0, 0);

        // LN2: R -> Zn
        ln_kernel<<<NB, 1024>>>(R, Zn, ln2w, ln2b);

        // Z = Zn @ W2 + b2
        gemm_bf<<<gRow, 256>>>(Zn, W2, Z, HID, HID, HID, HID,
                               b2, 0, nullptr, 0, 0, 0, 0);
    }

    // head: out = tanh(Z[:,0] @ Wh + bh)
    head_kernel<<<NB, dim3(32, 10)>>>(Wh, bh, out);
    (void)in_sizes; (void)n_in; (void)out_size;
}

// round 10
// speedup vs baseline: 4.9147x; 1.9073x over previous
#include <cuda_runtime.h>
#include <cuda_bf16.h>
#include <cstdint>

#define NB      256      // batch
#define SEQ     65
#define HID     512
#define HEADS   8
#define NP      64       // patches
#define PDIM    256
#define ROWS    (NB*SEQ) // 16640
#define OUTD    10

// ---------------- fp32 scratch ----------------
__device__ float g_Z [NB*SEQ*HID];
__device__ float g_R [NB*SEQ*HID];
__device__ float g_E [NB*NP*HID];
__device__ float g_Q [HEADS*ROWS*HID];
__device__ float g_K [HEADS*ROWS*HID];
__device__ float g_V [HEADS*ROWS*HID];

// ---------------- bf16 hi/lo planes ----------------
// activations (A operand), sized for the largest use: Hc planes [16640, 4096]
__device__ __nv_bfloat16 g_Ah[(long)ROWS*HEADS*HID];
__device__ __nv_bfloat16 g_Al[(long)ROWS*HEADS*HID];
// weights (B operand), SAME layout as input ([K,N], n-contig), elementwise split
__device__ __nv_bfloat16 g_Wph[PDIM*HID],        g_Wpl[PDIM*HID];
__device__ __nv_bfloat16 g_Wqh[HEADS*HID*HID],   g_Wql[HEADS*HID*HID];
__device__ __nv_bfloat16 g_Wkh[HEADS*HID*HID],   g_Wkl[HEADS*HID*HID];
__device__ __nv_bfloat16 g_Wvh[HEADS*HID*HID],   g_Wvl[HEADS*HID*HID];
__device__ __nv_bfloat16 g_Woh[HEADS*HID*HID],   g_Wol[HEADS*HID*HID];
__device__ __nv_bfloat16 g_W2h[HID*HID],         g_W2l[HID*HID];

// ---------------- PTX helpers ----------------
__device__ __forceinline__ uint32_t s2u(const void* p)
{
    uint32_t a;
    asm("{ .reg .u64 t; cvta.to.shared.u64 t, %1; cvt.u32.u64 %0, t; }" : "=r"(a) : "l"(p));
    return a;
}

__device__ __forceinline__ void cp16(uint32_t dst, const void* src)
{
    asm volatile("cp.async.cg.shared.global [%0], [%1], 16;" :: "r"(dst), "l"(src));
}

__device__ __forceinline__ void ldsm4(uint32_t& r0, uint32_t& r1, uint32_t& r2, uint32_t& r3,
                                      uint32_t addr)
{
    asm volatile("ldmatrix.sync.aligned.m8n8.x4.shared.b16 {%0,%1,%2,%3}, [%4];"
                 : "=r"(r0), "=r"(r1), "=r"(r2), "=r"(r3) : "r"(addr));
}

__device__ __forceinline__ void ldsm4t(uint32_t& r0, uint32_t& r1, uint32_t& r2, uint32_t& r3,
                                       uint32_t addr)
{
    asm volatile("ldmatrix.sync.aligned.m8n8.x4.trans.shared.b16 {%0,%1,%2,%3}, [%4];"
                 : "=r"(r0), "=r"(r1), "=r"(r2), "=r"(r3) : "r"(addr));
}

__device__ __forceinline__ void mma_bf16(float c[4], const uint32_t a[4], const uint32_t b[2])
{
    asm volatile(
        "mma.sync.aligned.m16n8k16.row.col.f32.bf16.bf16.f32 "
        "{%0,%1,%2,%3},{%4,%5,%6,%7},{%8,%9},{%0,%1,%2,%3};"
        : "+f"(c[0]), "+f"(c[1]), "+f"(c[2]), "+f"(c[3])
        : "r"(a[0]), "r"(a[1]), "r"(a[2]), "r"(a[3]),
          "r"(b[0]), "r"(b[1]));
}

// ---------------- bf16-pair GEMM with cp.async double-buffering ----------------
// C[z] = A @ B[z] (+bias[z]) (+res)
// A planes: [M,K] k-contig bf16; B planes: [K,N] n-contig bf16 (ldb = N stride)
// Tiles: 128x128, BK=32. warps 2x4, warp tile 64x32 (mi=4, ni=4).
// Requires M%128==0, N%128==0, K%32==0.
#define APL  10240            // A plane bytes: 128 rows * 40 elems * 2B
#define BPL  8704             // B plane bytes: 32 rows * 136 elems * 2B
#define STG  (2*APL + 2*BPL)  // 37888 per stage
#define GSM  (2*STG)          // 75776 dynamic smem

__global__ __launch_bounds__(256)
void gemm_cp(const __nv_bfloat16* __restrict__ Ah, const __nv_bfloat16* __restrict__ Al,
             const __nv_bfloat16* __restrict__ Bh, const __nv_bfloat16* __restrict__ Bl,
             float* __restrict__ C, int K, int ldb, int ldc,
             const float* __restrict__ bias, long biasStride,
             const float* __restrict__ res, int ldres,
             long strideB, long strideC)
{
    extern __shared__ __align__(16) char smem[];
    const uint32_t sb = s2u(smem);

    const int tid = threadIdx.x, lane = tid & 31, wid = tid >> 5;
    const int warp_m = wid >> 2, warp_n = wid & 3;   // 2 x 4, warp tile 64x32
    const int m0 = blockIdx.x * 128, n0 = blockIdx.y * 128;

    const __nv_bfloat16* Bhz = Bh + (long)blockIdx.z * strideB;
    const __nv_bfloat16* Blz = Bl + (long)blockIdx.z * strideB;
    float* Cz = C + (long)blockIdx.z * strideC;
    const float* bz = bias ? (bias + (long)blockIdx.z * biasStride) : nullptr;

    const int lrow = (lane & 7) + ((lane >> 3) & 1) * 8;
    const int lcol = (lane >> 4) * 8;

    float acc[4][4][4];
#pragma unroll
    for (int mi = 0; mi < 4; mi++)
#pragma unroll
        for (int ni = 0; ni < 4; ni++)
#pragma unroll
            for (int j = 0; j < 4; j++) acc[mi][ni][j] = 0.f;

    const int NCH = K >> 5;

    // ---- async tile copy: 8 x cp.async(16B) per thread ----
    auto issue = [&](int c) {
        const uint32_t st = sb + (uint32_t)(c & 1) * STG;
        const int k0 = c << 5;
        // A: 2 planes * 128 rows * 4 chunks(8 elems) = 1024 ops
#pragma unroll
        for (int l = 0; l < 4; l++) {
            int idx = l * 256 + tid;
            int p = idx >> 9, rem = idx & 511, row = rem >> 2, ch = rem & 3;
            const __nv_bfloat16* src = (p ? Al : Ah) + (long)(m0 + row) * K + k0 + ch * 8;
            cp16(st + (uint32_t)(p * APL + row * 80 + ch * 16), src);
        }
        // B: 2 planes * 32 k-rows * 16 chunks(8 n) = 1024 ops
#pragma unroll
        for (int l = 0; l < 4; l++) {
            int idx = l * 256 + tid;
            int p = idx >> 9, rem = idx & 511, kr = rem >> 4, ch = rem & 15;
            const __nv_bfloat16* src = (p ? Blz : Bhz) + (long)(k0 + kr) * ldb + n0 + ch * 8;
            cp16(st + (uint32_t)(2 * APL + p * BPL + kr * 272 + ch * 16), src);
        }
    };

    issue(0);
    asm volatile("cp.async.commit_group;" ::: "memory");

    for (int c = 0; c < NCH; c++) {
        if (c + 1 < NCH) issue(c + 1);
        asm volatile("cp.async.commit_group;" ::: "memory");
        asm volatile("cp.async.wait_group 1;" ::: "memory");
        __syncthreads();

        const uint32_t st = sb + (uint32_t)(c & 1) * STG;
        const uint32_t aS = st + (uint32_t)((warp_m * 64 + lrow) * 80 + lcol * 2);
        const uint32_t bS = st + 2 * APL + (uint32_t)(lrow * 272 + (warp_n * 32 + lcol) * 2);

#pragma unroll
        for (int ks = 0; ks < 2; ks++) {
            uint32_t ah[4][4], al[4][4], bh[4][2], bl[4][2];
#pragma unroll
            for (int mi = 0; mi < 4; mi++) {
                ldsm4(ah[mi][0], ah[mi][1], ah[mi][2], ah[mi][3], aS + mi * (16 * 80) + ks * 32);
                ldsm4(al[mi][0], al[mi][1], al[mi][2], al[mi][3], aS + APL + mi * (16 * 80) + ks * 32);
            }
#pragma unroll
            for (int nb = 0; nb < 2; nb++) {
                uint32_t r0, r1, r2, r3;
                ldsm4t(r0, r1, r2, r3, bS + nb * 32 + ks * (16 * 272));
                bh[nb * 2 + 0][0] = r0; bh[nb * 2 + 0][1] = r1;
                bh[nb * 2 + 1][0] = r2; bh[nb * 2 + 1][1] = r3;
                ldsm4t(r0, r1, r2, r3, bS + BPL + nb * 32 + ks * (16 * 272));
                bl[nb * 2 + 0][0] = r0; bl[nb * 2 + 0][1] = r1;
                bl[nb * 2 + 1][0] = r2; bl[nb * 2 + 1][1] = r3;
            }
#pragma unroll
            for (int mi = 0; mi < 4; mi++)
#pragma unroll
                for (int ni = 0; ni < 4; ni++) {
                    mma_bf16(acc[mi][ni], al[mi], bh[ni]);   // lo*hi
                    mma_bf16(acc[mi][ni], ah[mi], bl[ni]);   // hi*lo
                    mma_bf16(acc[mi][ni], ah[mi], bh[ni]);   // hi*hi
                }
        }
        __syncthreads();
    }

    // ---- epilogue ----
    const int r = lane >> 2, c2 = (lane & 3) << 1;
#pragma unroll
    for (int mi = 0; mi < 4; mi++) {
#pragma unroll
        for (int hh = 0; hh < 2; hh++) {
            int m = m0 + warp_m * 64 + mi * 16 + hh * 8 + r;
#pragma unroll
            for (int ni = 0; ni < 4; ni++) {
                int col = n0 + warp_n * 32 + ni * 8 + c2;
                float x0 = acc[mi][ni][hh * 2 + 0];
                float x1 = acc[mi][ni][hh * 2 + 1];
                if (bz) { x0 += bz[col]; x1 += bz[col + 1]; }
                if (res) {
                    float2 rr = *(const float2*)&res[(long)m * ldres + col];
                    x0 += rr.x; x1 += rr.y;
                }
                float2 o; o.x = x0; o.y = x1;
                *(float2*)&Cz[(long)m * ldc + col] = o;
            }
        }
    }
}

// ---------------- elementwise fp32 -> bf16 hi/lo planes ----------------
__global__ void conva(const float* __restrict__ A, __nv_bfloat16* __restrict__ hi,
                      __nv_bfloat16* __restrict__ lo, long n4)
{
    long i = (long)blockIdx.x * 256 + threadIdx.x;
    if (i >= n4) return;
    float4 f = ((const float4*)A)[i];
    float v[4] = {f.x, f.y, f.z, f.w};
    uint32_t hw[2], lw[2];
#pragma unroll
    for (int p = 0; p < 2; p++) {
        __nv_bfloat16 h0 = __float2bfloat16(v[p * 2 + 0]);
        __nv_bfloat16 h1 = __float2bfloat16(v[p * 2 + 1]);
        __nv_bfloat16 l0 = __float2bfloat16(v[p * 2 + 0] - __bfloat162float(h0));
        __nv_bfloat16 l1 = __float2bfloat16(v[p * 2 + 1] - __bfloat162float(h1));
        hw[p] = (uint32_t)__bfloat16_as_ushort(h0) | ((uint32_t)__bfloat16_as_ushort(h1) << 16);
        lw[p] = (uint32_t)__bfloat16_as_ushort(l0) | ((uint32_t)__bfloat16_as_ushort(l1) << 16);
    }
    ((uint2*)hi)[i] = make_uint2(hw[0], hw[1]);
    ((uint2*)lo)[i] = make_uint2(lw[0], lw[1]);
}

// ---------------- assemble Z = concat(cls, E) + pos ----------------
__global__ void assemble_kernel(const float* __restrict__ cls, const float* __restrict__ pos)
{
    long idx = (long)blockIdx.x * 256 + threadIdx.x;
    if (idx >= (long)NB * SEQ * HID) return;
    int e = (int)(idx % HID);
    long r = idx / HID;
    int s = (int)(r % SEQ);
    long n = r / SEQ;
    float v = pos[s * HID + e];
    if (s == 0) v += cls[e];
    else        v += g_E[(n * NP + (s - 1)) * (long)HID + e];
    g_Z[idx] = v;
}

// ---------------- LayerNorm -> bf16 hi/lo planes directly ----------------
__global__ __launch_bounds__(1024)
void ln_split(const float* __restrict__ in,
              __nv_bfloat16* __restrict__ oh, __nv_bfloat16* __restrict__ ol,
              const float* __restrict__ w, const float* __restrict__ b)
{
    const int n = blockIdx.x;
    const float* x = in + (long)n * SEQ * HID;
    __nv_bfloat16* yh = oh + (long)n * SEQ * HID;
    __nv_bfloat16* yl = ol + (long)n * SEQ * HID;
    float s = 0.f, ss = 0.f;
    for (int i = threadIdx.x; i < SEQ * HID; i += 1024) {
        float v = x[i]; s += v; ss += v * v;
    }
    __shared__ float red[64];
#pragma unroll
    for (int o = 16; o; o >>= 1) {
        s  += __shfl_down_sync(0xffffffffu, s, o);
        ss += __shfl_down_sync(0xffffffffu, ss, o);
    }
    int wid = threadIdx.x >> 5, lane = threadIdx.x & 31;
    if (lane == 0) { red[wid] = s; red[32 + wid] = ss; }
    __syncthreads();
    if (threadIdx.x == 0) {
        float S = 0.f, SS = 0.f;
        for (int i = 0; i < 32; i++) { S += red[i]; SS += red[32 + i]; }
        float inv = 1.0f / (SEQ * HID);
        float mu = S * inv;
        float var = SS * inv - mu * mu;
        red[0] = mu; red[1] = rsqrtf(var + 1e-5f);
    }
    __syncthreads();
    float mu = red[0], rinv = red[1];
    for (int i = threadIdx.x; i < SEQ * HID; i += 1024) {
        float y = (x[i] - mu) * rinv * w[i] + b[i];
        __nv_bfloat16 h = __float2bfloat16(y);
        yh[i] = h;
        yl[i] = __float2bfloat16(y - __bfloat162float(h));
    }
}

// ---------------- attention per (h, n) -> Hc planes directly ----------------
__global__ __launch_bounds__(256)
void attn_kernel()
{
    const int h = blockIdx.x, n = blockIdx.y;
    const float* q = g_Q + ((long)h * ROWS + (long)n * SEQ) * HID;
    const float* k = g_K + ((long)h * ROWS + (long)n * SEQ) * HID;
    const float* v = g_V + ((long)h * ROWS + (long)n * SEQ) * HID;
    __nv_bfloat16* oh = g_Ah + (long)n * SEQ * (HEADS * HID) + h * HID;
    __nv_bfloat16* ol = g_Al + (long)n * SEQ * (HEADS * HID) + h * HID;

    __shared__ float sc[SEQ][SEQ + 3];
    __shared__ float work[SEQ][66];

    const int tid = threadIdx.x;
    const int tx = tid & 15, ty = tid >> 4;

    float acc[5][5];
#pragma unroll
    for (int i = 0; i < 5; i++)
#pragma unroll
        for (int j = 0; j < 5; j++) acc[i][j] = 0.f;

    int rs[5], cs[5];
#pragma unroll
    for (int i = 0; i < 5; i++) {
        int s = ty + 16 * i; rs[i] = (s < SEQ) ? s : SEQ - 1;
        int t = tx + 16 * i; cs[i] = (t < SEQ) ? t : SEQ - 1;
    }

    for (int k0 = 0; k0 < HID; k0 += 32) {
        for (int i = tid; i < SEQ * 32; i += 256) {
            int s = i >> 5, j = i & 31;
            work[s][j]      = q[s * HID + k0 + j];
            work[s][33 + j] = k[s * HID + k0 + j];
        }
        __syncthreads();
#pragma unroll 4
        for (int j = 0; j < 32; j++) {
            float qv[5], kv[5];
#pragma unroll
            for (int i = 0; i < 5; i++) qv[i] = work[rs[i]][j];
#pragma unroll
            for (int i = 0; i < 5; i++) kv[i] = work[cs[i]][33 + j];
#pragma unroll
            for (int i = 0; i < 5; i++)
#pragma unroll
                for (int jj = 0; jj < 5; jj++) acc[i][jj] += qv[i] * kv[jj];
        }
        __syncthreads();
    }

#pragma unroll
    for (int i = 0; i < 5; i++) {
        int s = ty + 16 * i;
        if (s < SEQ) {
#pragma unroll
            for (int jj = 0; jj < 5; jj++) {
                int t = tx + 16 * jj;
                if (t < SEQ) sc[s][t] = acc[i][jj];
            }
        }
    }
    __syncthreads();

    if (tid < SEQ) {
        const float scale = 1.0f / (512.0f * 512.0f);
        float m = -1e30f;
        for (int t = 0; t < SEQ; t++) m = fmaxf(m, sc[tid][t] * scale);
        float sum = 0.f;
        for (int t = 0; t < SEQ; t++) {
            float e = __expf(sc[tid][t] * scale - m);
            sc[tid][t] = e; sum += e;
        }
        float rr = 1.0f / sum;
        for (int t = 0; t < SEQ; t++) sc[tid][t] *= rr;
    }
    __syncthreads();

    for (int e0 = 0; e0 < HID; e0 += 64) {
        for (int i = tid; i < SEQ * 64; i += 256) {
            int t = i >> 6, j = i & 63;
            work[t][j] = v[t * HID + e0 + j];
        }
        __syncthreads();
        float acc2[5][4];
#pragma unroll
        for (int i = 0; i < 5; i++)
#pragma unroll
            for (int j = 0; j < 4; j++) acc2[i][j] = 0.f;

        for (int t = 0; t < SEQ; t++) {
            float sv[5], vv[4];
#pragma unroll
            for (int i = 0; i < 5; i++) sv[i] = sc[rs[i]][t];
#pragma unroll
            for (int j = 0; j < 4; j++) vv[j] = work[t][tx + 16 * j];
#pragma unroll
            for (int i = 0; i < 5; i++)
#pragma unroll
                for (int j = 0; j < 4; j++) acc2[i][j] += sv[i] * vv[j];
        }
#pragma unroll
        for (int i = 0; i < 5; i++) {
            int s = ty + 16 * i;
            if (s < SEQ) {
#pragma unroll
                for (int j = 0; j < 4; j++) {
                    float val = acc2[i][j];
                    long o = (long)s * (HEADS * HID) + e0 + tx + 16 * j;
                    __nv_bfloat16 hv = __float2bfloat16(val);
                    oh[o] = hv;
                    ol[o] = __float2bfloat16(val - __bfloat162float(hv));
                }
            }
        }
        __syncthreads();
    }
}

// ---------------- classification head ----------------
__global__ void head_kernel(const float* __restrict__ Wh, const float* __restrict__ bh,
                            float* __restrict__ out)
{
    const int n = blockIdx.x;
    const int o = threadIdx.y;
    const int lane = threadIdx.x;
    const float* z = g_Z + (long)n * SEQ * HID;
    float a = 0.f;
    for (int e = lane; e < HID; e += 32) a += z[e] * Wh[e * OUTD + o];
#pragma unroll
    for (int off = 16; off; off >>= 1) a += __shfl_down_sync(0xffffffffu, a, off);
    if (lane == 0) out[n * OUTD + o] = tanhf(a + bh[o]);
}

// ---------------- host launcher ----------------
static float* sym_addr(const void* symbol)
{
    void* p = nullptr;
    cudaGetSymbolAddress(&p, symbol);
    return (float*)p;
}
static __nv_bfloat16* sym_addr_b(const void* symbol)
{
    void* p = nullptr;
    cudaGetSymbolAddress(&p, symbol);
    return (__nv_bfloat16*)p;
}

extern "C" void kernel_launch(void* const* d_in, const int* in_sizes, int n_in,
                              void* d_out, int out_size)
{
    const float* X    = (const float*)d_in[0];
    const float* Wp   = (const float*)d_in[1];
    const float* bp   = (const float*)d_in[2];
    const float* cls  = (const float*)d_in[3];
    const float* pos  = (const float*)d_in[4];
    const float* ln1w = (const float*)d_in[5];
    const float* ln1b = (const float*)d_in[6];
    const float* Wq   = (const float*)d_in[7];
    const float* bq   = (const float*)d_in[8];
    const float* Wk   = (const float*)d_in[9];
    const float* bk   = (const float*)d_in[10];
    const float* Wv   = (const float*)d_in[11];
    const float* bv   = (const float*)d_in[12];
    const float* Wo   = (const float*)d_in[13];
    const float* bo   = (const float*)d_in[14];
    const float* ln2w = (const float*)d_in[15];
    const float* ln2b = (const float*)d_in[16];
    const float* W2   = (const float*)d_in[17];
    const float* b2   = (const float*)d_in[18];
    const float* Wh   = (const float*)d_in[19];
    const float* bh   = (const float*)d_in[20];
    float* out = (float*)d_out;

    float* Z  = sym_addr(g_Z);
    float* R  = sym_addr(g_R);
    float* E  = sym_addr(g_E);
    float* Q  = sym_addr(g_Q);
    float* Kb = sym_addr(g_K);
    float* V  = sym_addr(g_V);
    __nv_bfloat16* Ah  = sym_addr_b(g_Ah);
    __nv_bfloat16* Al  = sym_addr_b(g_Al);
    __nv_bfloat16* Wph = sym_addr_b(g_Wph), *Wpl = sym_addr_b(g_Wpl);
    __nv_bfloat16* Wqh = sym_addr_b(g_Wqh), *Wql = sym_addr_b(g_Wql);
    __nv_bfloat16* Wkh = sym_addr_b(g_Wkh), *Wkl = sym_addr_b(g_Wkl);
    __nv_bfloat16* Wvh = sym_addr_b(g_Wvh), *Wvl = sym_addr_b(g_Wvl);
    __nv_bfloat16* Woh = sym_addr_b(g_Woh), *Wol = sym_addr_b(g_Wol);
    __nv_bfloat16* W2h = sym_addr_b(g_W2h), *W2l = sym_addr_b(g_W2l);

    cudaFuncSetAttribute(gemm_cp, cudaFuncAttributeMaxDynamicSharedMemorySize, GSM);

    const long WSTRIDE = (long)HID * HID;
    const long QSTRIDE = (long)ROWS * HID;

    // ---- weight conversions (elementwise, [K,N] layout preserved) ----
    conva<<<(PDIM * HID / 4 + 255) / 256, 256>>>(Wp, Wph, Wpl, PDIM * HID / 4);
    conva<<<(HEADS * HID * HID / 4 + 255) / 256, 256>>>(Wq, Wqh, Wql, (long)HEADS * HID * HID / 4);
    conva<<<(HEADS * HID * HID / 4 + 255) / 256, 256>>>(Wk, Wkh, Wkl, (long)HEADS * HID * HID / 4);
    conva<<<(HEADS * HID * HID / 4 + 255) / 256, 256>>>(Wv, Wvh, Wvl, (long)HEADS * HID * HID / 4);
    conva<<<(HEADS * HID * HID / 4 + 255) / 256, 256>>>(Wo, Woh, Wol, (long)HEADS * HID * HID / 4);
    conva<<<(HID * HID / 4 + 255) / 256, 256>>>(W2, W2h, W2l, HID * HID / 4);

    // ---- patch embed: E = X(as [16384,256]) @ Wp + bp ----
    {
        long n4 = (long)NB * NP * PDIM / 4;
        conva<<<(unsigned)((n4 + 255) / 256), 256>>>(X, Ah, Al, n4);
        gemm_cp<<<dim3((NB * NP) / 128, HID / 128, 1), 256, GSM>>>(
            Ah, Al, Wph, Wpl, E, PDIM, HID, HID, bp, 0, nullptr, 0, 0, 0);
    }
    // ---- Z = concat(cls, E) + pos ----
    {
        long total = (long)NB * SEQ * HID;
        assemble_kernel<<<(unsigned)((total + 255) / 256), 256>>>(cls, pos);
    }

    dim3 gQKV(ROWS / 128, HID / 128, HEADS);
    dim3 gRow(ROWS / 128, HID / 128, 1);

    for (int blk = 0; blk < 6; blk++) {
        // LN1: Z -> bf16 planes
        ln_split<<<NB, 1024>>>(Z, Ah, Al, ln1w, ln1b);

        // Q/K/V per-head GEMMs
        gemm_cp<<<gQKV, 256, GSM>>>(Ah, Al, Wqh, Wql, Q, HID, HID, HID,
                                    bq, HID, nullptr, 0, WSTRIDE, QSTRIDE);
        gemm_cp<<<gQKV, 256, GSM>>>(Ah, Al, Wkh, Wkl, Kb, HID, HID, HID,
                                    bk, HID, nullptr, 0, WSTRIDE, QSTRIDE);
        gemm_cp<<<gQKV, 256, GSM>>>(Ah, Al, Wvh, Wvl, V, HID, HID, HID,
                                    bv, HID, nullptr, 0, WSTRIDE, QSTRIDE);

        // attention -> Hc planes (bf16 hi/lo, direct)
        attn_kernel<<<dim3(HEADS, NB), 256>>>();

        // R = Hc @ Wo + bo + Z (fused residual), K = 4096
        gemm_cp<<<gRow, 256, GSM>>>(Ah, Al, Woh, Wol, R, HEADS * HID, HID, HID,
                                    bo, 0, Z, HID, 0, 0);

        // LN2: R -> planes; Z = planes @ W2 + b2
        ln_split<<<NB, 1024>>>(R, Ah, Al, ln2w, ln2b);
        gemm_cp<<<gRow, 256, GSM>>>(Ah, Al, W2h, W2l, Z, HID, HID, HID,
                                    b2, 0, nullptr, 0, 0, 0);
    }

    // head: out = tanh(Z[:,0] @ Wh + bh)
    head_kernel<<<NB, dim3(32, 10)>>>(Wh, bh, out);
    (void)in_sizes; (void)n_in; (void)out_size;
}

// round 11
// speedup vs baseline: 5.9791x; 1.2166x over previous
#include <cuda_runtime.h>
#include <cuda_bf16.h>
#include <cstdint>

#define NB      256      // batch
#define SEQ     65
#define HID     512
#define HEADS   8
#define NP      64       // patches
#define PDIM    256
#define ROWS    (NB*SEQ) // 16640
#define OUTD    10

// ---------------- fp32 scratch ----------------
__device__ float g_Z [NB*SEQ*HID];
__device__ float g_R [NB*SEQ*HID];
__device__ float g_E [NB*NP*HID];
__device__ float g_Q [HEADS*ROWS*HID];
__device__ float g_K [HEADS*ROWS*HID];
__device__ float g_V [HEADS*ROWS*HID];

// ---------------- bf16 hi/lo planes ----------------
__device__ __nv_bfloat16 g_Ah[(long)ROWS*HEADS*HID];
__device__ __nv_bfloat16 g_Al[(long)ROWS*HEADS*HID];
__device__ __nv_bfloat16 g_Wph[PDIM*HID],        g_Wpl[PDIM*HID];
__device__ __nv_bfloat16 g_Wqh[HEADS*HID*HID],   g_Wql[HEADS*HID*HID];
__device__ __nv_bfloat16 g_Wkh[HEADS*HID*HID],   g_Wkl[HEADS*HID*HID];
__device__ __nv_bfloat16 g_Wvh[HEADS*HID*HID],   g_Wvl[HEADS*HID*HID];
__device__ __nv_bfloat16 g_Woh[HEADS*HID*HID],   g_Wol[HEADS*HID*HID];
__device__ __nv_bfloat16 g_W2h[HID*HID],         g_W2l[HID*HID];

// ---------------- PTX helpers ----------------
__device__ __forceinline__ uint32_t s2u(const void* p)
{
    uint32_t a;
    asm("{ .reg .u64 t; cvta.to.shared.u64 t, %1; cvt.u32.u64 %0, t; }" : "=r"(a) : "l"(p));
    return a;
}

__device__ __forceinline__ void cp16(uint32_t dst, const void* src)
{
    asm volatile("cp.async.cg.shared.global [%0], [%1], 16;" :: "r"(dst), "l"(src));
}

__device__ __forceinline__ void ldsm4(uint32_t& r0, uint32_t& r1, uint32_t& r2, uint32_t& r3,
                                      uint32_t addr)
{
    asm volatile("ldmatrix.sync.aligned.m8n8.x4.shared.b16 {%0,%1,%2,%3}, [%4];"
                 : "=r"(r0), "=r"(r1), "=r"(r2), "=r"(r3) : "r"(addr));
}

__device__ __forceinline__ void ldsm4t(uint32_t& r0, uint32_t& r1, uint32_t& r2, uint32_t& r3,
                                       uint32_t addr)
{
    asm volatile("ldmatrix.sync.aligned.m8n8.x4.trans.shared.b16 {%0,%1,%2,%3}, [%4];"
                 : "=r"(r0), "=r"(r1), "=r"(r2), "=r"(r3) : "r"(addr));
}

__device__ __forceinline__ void mma_bf16(float c[4], const uint32_t a[4], const uint32_t b[2])
{
    asm volatile(
        "mma.sync.aligned.m16n8k16.row.col.f32.bf16.bf16.f32 "
        "{%0,%1,%2,%3},{%4,%5,%6,%7},{%8,%9},{%0,%1,%2,%3};"
        : "+f"(c[0]), "+f"(c[1]), "+f"(c[2]), "+f"(c[3])
        : "r"(a[0]), "r"(a[1]), "r"(a[2]), "r"(a[3]),
          "r"(b[0]), "r"(b[1]));
}

// ---------------- bf16 GEMM, templated compensation depth ----------------
// TERMS=3: acc += al*bh + ah*bl + ah*bh  (full error compensation)
// TERMS=1: acc += ah*bh                  (single bf16; Q/K projections only)
// A planes [M,K] k-contig; B planes [K,N] n-contig. 128x128 tiles, BK=32,
// warps 2x4 (64x32 warp tile). M%128==0, N%128==0, K%32==0.
#define APL  10240            // A plane bytes: 128 * 40 elems * 2B
#define BPL  8704             // B plane bytes: 32 * 136 elems * 2B

template<int TERMS>
__global__ __launch_bounds__(256)
void gemm_t(const __nv_bfloat16* __restrict__ Ah, const __nv_bfloat16* __restrict__ Al,
            const __nv_bfloat16* __restrict__ Bh, const __nv_bfloat16* __restrict__ Bl,
            float* __restrict__ C, int K, int ldb, int ldc,
            const float* __restrict__ bias, long biasStride,
            const float* __restrict__ res, int ldres,
            long strideB, long strideC)
{
    constexpr int NPL = (TERMS == 3) ? 2 : 1;         // planes per operand
    constexpr uint32_t BOFF = NPL * APL;              // B region offset
    constexpr uint32_t STG = NPL * (APL + BPL);       // stage bytes

    extern __shared__ __align__(16) char smem[];
    const uint32_t sb = s2u(smem);

    const int tid = threadIdx.x, lane = tid & 31, wid = tid >> 5;
    const int warp_m = wid >> 2, warp_n = wid & 3;
    const int m0 = blockIdx.x * 128, n0 = blockIdx.y * 128;

    const __nv_bfloat16* Bhz = Bh + (long)blockIdx.z * strideB;
    const __nv_bfloat16* Blz = Bl + (long)blockIdx.z * strideB;
    float* Cz = C + (long)blockIdx.z * strideC;
    const float* bz = bias ? (bias + (long)blockIdx.z * biasStride) : nullptr;

    const int lrow = (lane & 7) + ((lane >> 3) & 1) * 8;
    const int lcol = (lane >> 4) * 8;

    float acc[4][4][4];
#pragma unroll
    for (int mi = 0; mi < 4; mi++)
#pragma unroll
        for (int ni = 0; ni < 4; ni++)
#pragma unroll
            for (int j = 0; j < 4; j++) acc[mi][ni][j] = 0.f;

    const int NCH = K >> 5;

    auto issue = [&](int c) {
        const uint32_t st = sb + (uint32_t)(c & 1) * STG;
        const int k0 = c << 5;
#pragma unroll
        for (int l = 0; l < 2 * NPL; l++) {           // A: NPL*512 cp ops
            int idx = l * 256 + tid;
            int p = idx >> 9, rem = idx & 511, row = rem >> 2, ch = rem & 3;
            const __nv_bfloat16* src = (p ? Al : Ah) + (long)(m0 + row) * K + k0 + ch * 8;
            cp16(st + (uint32_t)(p * APL + row * 80 + ch * 16), src);
        }
#pragma unroll
        for (int l = 0; l < 2 * NPL; l++) {           // B: NPL*512 cp ops
            int idx = l * 256 + tid;
            int p = idx >> 9, rem = idx & 511, kr = rem >> 4, ch = rem & 15;
            const __nv_bfloat16* src = (p ? Blz : Bhz) + (long)(k0 + kr) * ldb + n0 + ch * 8;
            cp16(st + (uint32_t)(BOFF + p * BPL + kr * 272 + ch * 16), src);
        }
    };

    issue(0);
    asm volatile("cp.async.commit_group;" ::: "memory");

    for (int c = 0; c < NCH; c++) {
        if (c + 1 < NCH) issue(c + 1);
        asm volatile("cp.async.commit_group;" ::: "memory");
        asm volatile("cp.async.wait_group 1;" ::: "memory");
        __syncthreads();

        const uint32_t st = sb + (uint32_t)(c & 1) * STG;
        const uint32_t aS = st + (uint32_t)((warp_m * 64 + lrow) * 80 + lcol * 2);
        const uint32_t bS = st + BOFF + (uint32_t)(lrow * 272 + (warp_n * 32 + lcol) * 2);

#pragma unroll
        for (int ks = 0; ks < 2; ks++) {
            uint32_t ah[4][4], al[4][4], bh[4][2], bl[4][2];
#pragma unroll
            for (int mi = 0; mi < 4; mi++) {
                ldsm4(ah[mi][0], ah[mi][1], ah[mi][2], ah[mi][3], aS + mi * (16 * 80) + ks * 32);
                if (TERMS == 3)
                    ldsm4(al[mi][0], al[mi][1], al[mi][2], al[mi][3],
                          aS + APL + mi * (16 * 80) + ks * 32);
            }
#pragma unroll
            for (int nb = 0; nb < 2; nb++) {
                uint32_t r0, r1, r2, r3;
                ldsm4t(r0, r1, r2, r3, bS + nb * 32 + ks * (16 * 272));
                bh[nb * 2 + 0][0] = r0; bh[nb * 2 + 0][1] = r1;
                bh[nb * 2 + 1][0] = r2; bh[nb * 2 + 1][1] = r3;
                if (TERMS == 3) {
                    ldsm4t(r0, r1, r2, r3, bS + BPL + nb * 32 + ks * (16 * 272));
                    bl[nb * 2 + 0][0] = r0; bl[nb * 2 + 0][1] = r1;
                    bl[nb * 2 + 1][0] = r2; bl[nb * 2 + 1][1] = r3;
                }
            }
#pragma unroll
            for (int mi = 0; mi < 4; mi++)
#pragma unroll
                for (int ni = 0; ni < 4; ni++) {
                    if (TERMS == 3) {
                        mma_bf16(acc[mi][ni], al[mi], bh[ni]);
                        mma_bf16(acc[mi][ni], ah[mi], bl[ni]);
                    }
                    mma_bf16(acc[mi][ni], ah[mi], bh[ni]);
                }
        }
        __syncthreads();
    }

    const int r = lane >> 2, c2 = (lane & 3) << 1;
#pragma unroll
    for (int mi = 0; mi < 4; mi++) {
#pragma unroll
        for (int hh = 0; hh < 2; hh++) {
            int m = m0 + warp_m * 64 + mi * 16 + hh * 8 + r;
#pragma unroll
            for (int ni = 0; ni < 4; ni++) {
                int col = n0 + warp_n * 32 + ni * 8 + c2;
                float x0 = acc[mi][ni][hh * 2 + 0];
                float x1 = acc[mi][ni][hh * 2 + 1];
                if (bz) { x0 += bz[col]; x1 += bz[col + 1]; }
                if (res) {
                    float2 rr = *(const float2*)&res[(long)m * ldres + col];
                    x0 += rr.x; x1 += rr.y;
                }
                float2 o; o.x = x0; o.y = x1;
                *(float2*)&Cz[(long)m * ldc + col] = o;
            }
        }
    }
}

// ---------------- elementwise fp32 -> bf16 hi/lo planes ----------------
__global__ void conva(const float* __restrict__ A, __nv_bfloat16* __restrict__ hi,
                      __nv_bfloat16* __restrict__ lo, long n4)
{
    long i = (long)blockIdx.x * 256 + threadIdx.x;
    if (i >= n4) return;
    float4 f = ((const float4*)A)[i];
    float v[4] = {f.x, f.y, f.z, f.w};
    uint32_t hw[2], lw[2];
#pragma unroll
    for (int p = 0; p < 2; p++) {
        __nv_bfloat16 h0 = __float2bfloat16(v[p * 2 + 0]);
        __nv_bfloat16 h1 = __float2bfloat16(v[p * 2 + 1]);
        __nv_bfloat16 l0 = __float2bfloat16(v[p * 2 + 0] - __bfloat162float(h0));
        __nv_bfloat16 l1 = __float2bfloat16(v[p * 2 + 1] - __bfloat162float(h1));
        hw[p] = (uint32_t)__bfloat16_as_ushort(h0) | ((uint32_t)__bfloat16_as_ushort(h1) << 16);
        lw[p] = (uint32_t)__bfloat16_as_ushort(l0) | ((uint32_t)__bfloat16_as_ushort(l1) << 16);
    }
    ((uint2*)hi)[i] = make_uint2(hw[0], hw[1]);
    ((uint2*)lo)[i] = make_uint2(lw[0], lw[1]);
}

// ---------------- assemble Z = concat(cls, E) + pos ----------------
__global__ void assemble_kernel(const float* __restrict__ cls, const float* __restrict__ pos)
{
    long idx = (long)blockIdx.x * 256 + threadIdx.x;
    if (idx >= (long)NB * SEQ * HID) return;
    int e = (int)(idx % HID);
    long r = idx / HID;
    int s = (int)(r % SEQ);
    long n = r / SEQ;
    float v = pos[s * HID + e];
    if (s == 0) v += cls[e];
    else        v += g_E[(n * NP + (s - 1)) * (long)HID + e];
    g_Z[idx] = v;
}

// ---------------- LayerNorm -> bf16 hi/lo planes directly ----------------
__global__ __launch_bounds__(1024)
void ln_split(const float* __restrict__ in,
              __nv_bfloat16* __restrict__ oh, __nv_bfloat16* __restrict__ ol,
              const float* __restrict__ w, const float* __restrict__ b)
{
    const int n = blockIdx.x;
    const float* x = in + (long)n * SEQ * HID;
    __nv_bfloat16* yh = oh + (long)n * SEQ * HID;
    __nv_bfloat16* yl = ol + (long)n * SEQ * HID;
    float s = 0.f, ss = 0.f;
    for (int i = threadIdx.x; i < SEQ * HID; i += 1024) {
        float v = x[i]; s += v; ss += v * v;
    }
    __shared__ float red[64];
#pragma unroll
    for (int o = 16; o; o >>= 1) {
        s  += __shfl_down_sync(0xffffffffu, s, o);
        ss += __shfl_down_sync(0xffffffffu, ss, o);
    }
    int wid = threadIdx.x >> 5, lane = threadIdx.x & 31;
    if (lane == 0) { red[wid] = s; red[32 + wid] = ss; }
    __syncthreads();
    if (threadIdx.x == 0) {
        float S = 0.f, SS = 0.f;
        for (int i = 0; i < 32; i++) { S += red[i]; SS += red[32 + i]; }
        float inv = 1.0f / (SEQ * HID);
        float mu = S * inv;
        float var = SS * inv - mu * mu;
        red[0] = mu; red[1] = rsqrtf(var + 1e-5f);
    }
    __syncthreads();
    float mu = red[0], rinv = red[1];
    for (int i = threadIdx.x; i < SEQ * HID; i += 1024) {
        float y = (x[i] - mu) * rinv * w[i] + b[i];
        __nv_bfloat16 h = __float2bfloat16(y);
        yh[i] = h;
        yl[i] = __float2bfloat16(y - __bfloat162float(h));
    }
}

// ---------------- attention per (h, n) -> Hc planes directly ----------------
__global__ __launch_bounds__(256)
void attn_kernel()
{
    const int h = blockIdx.x, n = blockIdx.y;
    const float* q = g_Q + ((long)h * ROWS + (long)n * SEQ) * HID;
    const float* k = g_K + ((long)h * ROWS + (long)n * SEQ) * HID;
    const float* v = g_V + ((long)h * ROWS + (long)n * SEQ) * HID;
    __nv_bfloat16* oh = g_Ah + (long)n * SEQ * (HEADS * HID) + h * HID;
    __nv_bfloat16* ol = g_Al + (long)n * SEQ * (HEADS * HID) + h * HID;

    __shared__ float sc[SEQ][SEQ + 3];
    __shared__ float work[SEQ][66];

    const int tid = threadIdx.x;
    const int tx = tid & 15, ty = tid >> 4;

    float acc[5][5];
#pragma unroll
    for (int i = 0; i < 5; i++)
#pragma unroll
        for (int j = 0; j < 5; j++) acc[i][j] = 0.f;

    int rs[5], cs[5];
#pragma unroll
    for (int i = 0; i < 5; i++) {
        int s = ty + 16 * i; rs[i] = (s < SEQ) ? s : SEQ - 1;
        int t = tx + 16 * i; cs[i] = (t < SEQ) ? t : SEQ - 1;
    }

    for (int k0 = 0; k0 < HID; k0 += 32) {
        for (int i = tid; i < SEQ * 32; i += 256) {
            int s = i >> 5, j = i & 31;
            work[s][j]      = q[s * HID + k0 + j];
            work[s][33 + j] = k[s * HID + k0 + j];
        }
        __syncthreads();
#pragma unroll 4
        for (int j = 0; j < 32; j++) {
            float qv[5], kv[5];
#pragma unroll
            for (int i = 0; i < 5; i++) qv[i] = work[rs[i]][j];
#pragma unroll
            for (int i = 0; i < 5; i++) kv[i] = work[cs[i]][33 + j];
#pragma unroll
            for (int i = 0; i < 5; i++)
#pragma unroll
                for (int jj = 0; jj < 5; jj++) acc[i][jj] += qv[i] * kv[jj];
        }
        __syncthreads();
    }

#pragma unroll
    for (int i = 0; i < 5; i++) {
        int s = ty + 16 * i;
        if (s < SEQ) {
#pragma unroll
            for (int jj = 0; jj < 5; jj++) {
                int t = tx + 16 * jj;
                if (t < SEQ) sc[s][t] = acc[i][jj];
            }
        }
    }
    __syncthreads();

    if (tid < SEQ) {
        const float scale = 1.0f / (512.0f * 512.0f);
        float m = -1e30f;
        for (int t = 0; t < SEQ; t++) m = fmaxf(m, sc[tid][t] * scale);
        float sum = 0.f;
        for (int t = 0; t < SEQ; t++) {
            float e = __expf(sc[tid][t] * scale - m);
            sc[tid][t] = e; sum += e;
        }
        float rr = 1.0f / sum;
        for (int t = 0; t < SEQ; t++) sc[tid][t] *= rr;
    }
    __syncthreads();

    for (int e0 = 0; e0 < HID; e0 += 64) {
        for (int i = tid; i < SEQ * 64; i += 256) {
            int t = i >> 6, j = i & 63;
            work[t][j] = v[t * HID + e0 + j];
        }
        __syncthreads();
        float acc2[5][4];
#pragma unroll
        for (int i = 0; i < 5; i++)
#pragma unroll
            for (int j = 0; j < 4; j++) acc2[i][j] = 0.f;

        for (int t = 0; t < SEQ; t++) {
            float sv[5], vv[4];
#pragma unroll
            for (int i = 0; i < 5; i++) sv[i] = sc[rs[i]][t];
#pragma unroll
            for (int j = 0; j < 4; j++) vv[j] = work[t][tx + 16 * j];
#pragma unroll
            for (int i = 0; i < 5; i++)
#pragma unroll
                for (int j = 0; j < 4; j++) acc2[i][j] += sv[i] * vv[j];
        }
#pragma unroll
        for (int i = 0; i < 5; i++) {
            int s = ty + 16 * i;
            if (s < SEQ) {
#pragma unroll
                for (int j = 0; j < 4; j++) {
                    float val = acc2[i][j];
                    long o = (long)s * (HEADS * HID) + e0 + tx + 16 * j;
                    __nv_bfloat16 hv = __float2bfloat16(val);
                    oh[o] = hv;
                    ol[o] = __float2bfloat16(val - __bfloat162float(hv));
                }
            }
        }
        __syncthreads();
    }
}

// ---------------- classification head ----------------
__global__ void head_kernel(const float* __restrict__ Wh, const float* __restrict__ bh,
                            float* __restrict__ out)
{
    const int n = blockIdx.x;
    const int o = threadIdx.y;
    const int lane = threadIdx.x;
    const float* z = g_Z + (long)n * SEQ * HID;
    float a = 0.f;
    for (int e = lane; e < HID; e += 32) a += z[e] * Wh[e * OUTD + o];
#pragma unroll
    for (int off = 16; off; off >>= 1) a += __shfl_down_sync(0xffffffffu, a, off);
    if (lane == 0) out[n * OUTD + o] = tanhf(a + bh[o]);
}

// ---------------- host launcher ----------------
static float* sym_addr(const void* symbol)
{
    void* p = nullptr;
    cudaGetSymbolAddress(&p, symbol);
    return (float*)p;
}
static __nv_bfloat16* sym_addr_b(const void* symbol)
{
    void* p = nullptr;
    cudaGetSymbolAddress(&p, symbol);
    return (__nv_bfloat16*)p;
}

extern "C" void kernel_launch(void* const* d_in, const int* in_sizes, int n_in,
                              void* d_out, int out_size)
{
    const float* X    = (const float*)d_in[0];
    const float* Wp   = (const float*)d_in[1];
    const float* bp   = (const float*)d_in[2];
    const float* cls  = (const float*)d_in[3];
    const float* pos  = (const float*)d_in[4];
    const float* ln1w = (const float*)d_in[5];
    const float* ln1b = (const float*)d_in[6];
    const float* Wq   = (const float*)d_in[7];
    const float* bq   = (const float*)d_in[8];
    const float* Wk   = (const float*)d_in[9];
    const float* bk   = (const float*)d_in[10];
    const float* Wv   = (const float*)d_in[11];
    const float* bv   = (const float*)d_in[12];
    const float* Wo   = (const float*)d_in[13];
    const float* bo   = (const float*)d_in[14];
    const float* ln2w = (const float*)d_in[15];
    const float* ln2b = (const float*)d_in[16];
    const float* W2   = (const float*)d_in[17];
    const float* b2   = (const float*)d_in[18];
    const float* Wh   = (const float*)d_in[19];
    const float* bh   = (const float*)d_in[20];
    float* out = (float*)d_out;

    float* Z  = sym_addr(g_Z);
    float* R  = sym_addr(g_R);
    float* E  = sym_addr(g_E);
    float* Q  = sym_addr(g_Q);
    float* Kb = sym_addr(g_K);
    float* V  = sym_addr(g_V);
    __nv_bfloat16* Ah  = sym_addr_b(g_Ah);
    __nv_bfloat16* Al  = sym_addr_b(g_Al);
    __nv_bfloat16* Wph = sym_addr_b(g_Wph), *Wpl = sym_addr_b(g_Wpl);
    __nv_bfloat16* Wqh = sym_addr_b(g_Wqh), *Wql = sym_addr_b(g_Wql);
    __nv_bfloat16* Wkh = sym_addr_b(g_Wkh), *Wkl = sym_addr_b(g_Wkl);
    __nv_bfloat16* Wvh = sym_addr_b(g_Wvh), *Wvl = sym_addr_b(g_Wvl);
    __nv_bfloat16* Woh = sym_addr_b(g_Woh), *Wol = sym_addr_b(g_Wol);
    __nv_bfloat16* W2h = sym_addr_b(g_W2h), *W2l = sym_addr_b(g_W2l);

    const int GSM1 = 2 * (APL + BPL);          // 37888
    const int GSM3 = 2 * (2 * APL + 2 * BPL);  // 75776
    cudaFuncSetAttribute(gemm_t<1>, cudaFuncAttributeMaxDynamicSharedMemorySize, GSM1);
    cudaFuncSetAttribute(gemm_t<3>, cudaFuncAttributeMaxDynamicSharedMemorySize, GSM3);

    const long WSTRIDE = (long)HID * HID;
    const long QSTRIDE = (long)ROWS * HID;

    // ---- weight conversions (elementwise, [K,N] layout preserved) ----
    conva<<<(PDIM * HID / 4 + 255) / 256, 256>>>(Wp, Wph, Wpl, PDIM * HID / 4);
    conva<<<(HEADS * HID * HID / 4 + 255) / 256, 256>>>(Wq, Wqh, Wql, (long)HEADS * HID * HID / 4);
    conva<<<(HEADS * HID * HID / 4 + 255) / 256, 256>>>(Wk, Wkh, Wkl, (long)HEADS * HID * HID / 4);
    conva<<<(HEADS * HID * HID / 4 + 255) / 256, 256>>>(Wv, Wvh, Wvl, (long)HEADS * HID * HID / 4);
    conva<<<(HEADS * HID * HID / 4 + 255) / 256, 256>>>(Wo, Woh, Wol, (long)HEADS * HID * HID / 4);
    conva<<<(HID * HID / 4 + 255) / 256, 256>>>(W2, W2h, W2l, HID * HID / 4);

    // ---- patch embed: E = X(as [16384,256]) @ Wp + bp ----
    {
        long n4 = (long)NB * NP * PDIM / 4;
        conva<<<(unsigned)((n4 + 255) / 256), 256>>>(X, Ah, Al, n4);
        gemm_t<3><<<dim3((NB * NP) / 128, HID / 128, 1), 256, GSM3>>>(
            Ah, Al, Wph, Wpl, E, PDIM, HID, HID, bp, 0, nullptr, 0, 0, 0);
    }
    // ---- Z = concat(cls, E) + pos ----
    {
        long total = (long)NB * SEQ * HID;
        assemble_kernel<<<(unsigned)((total + 255) / 256), 256>>>(cls, pos);
    }

    dim3 gQKV(ROWS / 128, HID / 128, HEADS);
    dim3 gRow(ROWS / 128, HID / 128, 1);

    for (int blk = 0; blk < 6; blk++) {
        // LN1: Z -> bf16 planes
        ln_split<<<NB, 1024>>>(Z, Ah, Al, ln1w, ln1b);

        // Q/K single-term bf16 (softmax-insensitive), V full 3-term
        gemm_t<1><<<gQKV, 256, GSM1>>>(Ah, Al, Wqh, Wql, Q, HID, HID, HID,
                                       bq, HID, nullptr, 0, WSTRIDE, QSTRIDE);
        gemm_t<1><<<gQKV, 256, GSM1>>>(Ah, Al, Wkh, Wkl, Kb, HID, HID, HID,
                                       bk, HID, nullptr, 0, WSTRIDE, QSTRIDE);
        gemm_t<3><<<gQKV, 256, GSM3>>>(Ah, Al, Wvh, Wvl, V, HID, HID, HID,
                                       bv, HID, nullptr, 0, WSTRIDE, QSTRIDE);

        // attention -> Hc planes (bf16 hi/lo, direct)
        attn_kernel<<<dim3(HEADS, NB), 256>>>();

        // R = Hc @ Wo + bo + Z (fused residual), K = 4096
        gemm_t<3><<<gRow, 256, GSM3>>>(Ah, Al, Woh, Wol, R, HEADS * HID, HID, HID,
                                       bo, 0, Z, HID, 0, 0);

        // LN2: R -> planes; Z = planes @ W2 + b2
        ln_split<<<NB, 1024>>>(R, Ah, Al, ln2w, ln2b);
        gemm_t<3><<<gRow, 256, GSM3>>>(Ah, Al, W2h, W2l, Z, HID, HID, HID,
                                       b2, 0, nullptr, 0, 0, 0);
    }

    // head: out = tanh(Z[:,0] @ Wh + bh)
    head_kernel<<<NB, dim3(32, 10)>>>(Wh, bh, out);
    (void)in_sizes; (void)n_in; (void)out_size;
}

// round 12
// speedup vs baseline: 7.4265x; 1.2421x over previous
#include <cuda_runtime.h>
#include <cuda_bf16.h>
#include <cstdint>

#define NB      256      // batch
#define SEQ     65
#define HID     512
#define HEADS   8
#define NP      64       // patches
#define PDIM    256
#define ROWS    (NB*SEQ) // 16640
#define OUTD    10

// ---------------- fp32 scratch ----------------
__device__ float g_Z [NB*SEQ*HID];
__device__ float g_R [NB*SEQ*HID];
__device__ float g_E [NB*NP*HID];
__device__ float g_T [HEADS*ROWS*HID];   // T = Zn @ G_h
__device__ float g_P [HEADS*ROWS*HID];   // P = Zn @ U_h
__device__ float g_O [HEADS*ROWS*HID];   // O_h = attn_h @ P_h
__device__ float g_Gf[HEADS*HID*HID];    // G = Wq Wk^T (fp32)
__device__ float g_Uf[HEADS*HID*HID];    // U = Wv Wo_h (fp32)
__device__ float g_u [HEADS*HID];        // Wq @ bk
__device__ float g_w [HEADS*HID];        // Wk @ bq
__device__ float g_d [HEADS];            // bq . bk
__device__ float g_cvec[HID];            // sum_h bv_h @ Wo_h + bo

// ---------------- bf16 hi/lo planes ----------------
__device__ __nv_bfloat16 g_Ah[ROWS*HID],          g_Al[ROWS*HID];       // activations
__device__ __nv_bfloat16 g_Wph[PDIM*HID],         g_Wpl[PDIM*HID];
__device__ __nv_bfloat16 g_Wqh[HEADS*HID*HID],    g_Wql[HEADS*HID*HID];
__device__ __nv_bfloat16 g_WkTh[HEADS*HID*HID],   g_WkTl[HEADS*HID*HID]; // Wk transposed
__device__ __nv_bfloat16 g_Wvh[HEADS*HID*HID],    g_Wvl[HEADS*HID*HID];
__device__ __nv_bfloat16 g_Woh[HEADS*HID*HID],    g_Wol[HEADS*HID*HID];
__device__ __nv_bfloat16 g_W2h[HID*HID],          g_W2l[HID*HID];
__device__ __nv_bfloat16 g_Gh[HEADS*HID*HID],     g_Gl[HEADS*HID*HID];
__device__ __nv_bfloat16 g_Uh[HEADS*HID*HID],     g_Ul[HEADS*HID*HID];

// ---------------- PTX helpers ----------------
__device__ __forceinline__ uint32_t s2u(const void* p)
{
    uint32_t a;
    asm("{ .reg .u64 t; cvta.to.shared.u64 t, %1; cvt.u32.u64 %0, t; }" : "=r"(a) : "l"(p));
    return a;
}

__device__ __forceinline__ void cp16(uint32_t dst, const void* src)
{
    asm volatile("cp.async.cg.shared.global [%0], [%1], 16;" :: "r"(dst), "l"(src));
}

__device__ __forceinline__ void ldsm4(uint32_t& r0, uint32_t& r1, uint32_t& r2, uint32_t& r3,
                                      uint32_t addr)
{
    asm volatile("ldmatrix.sync.aligned.m8n8.x4.shared.b16 {%0,%1,%2,%3}, [%4];"
                 : "=r"(r0), "=r"(r1), "=r"(r2), "=r"(r3) : "r"(addr));
}

__device__ __forceinline__ void ldsm4t(uint32_t& r0, uint32_t& r1, uint32_t& r2, uint32_t& r3,
                                       uint32_t addr)
{
    asm volatile("ldmatrix.sync.aligned.m8n8.x4.trans.shared.b16 {%0,%1,%2,%3}, [%4];"
                 : "=r"(r0), "=r"(r1), "=r"(r2), "=r"(r3) : "r"(addr));
}

__device__ __forceinline__ void mma_bf16(float c[4], const uint32_t a[4], const uint32_t b[2])
{
    asm volatile(
        "mma.sync.aligned.m16n8k16.row.col.f32.bf16.bf16.f32 "
        "{%0,%1,%2,%3},{%4,%5,%6,%7},{%8,%9},{%0,%1,%2,%3};"
        : "+f"(c[0]), "+f"(c[1]), "+f"(c[2]), "+f"(c[3])
        : "r"(a[0]), "r"(a[1]), "r"(a[2]), "r"(a[3]),
          "r"(b[0]), "r"(b[1]));
}

// ---------------- bf16 GEMM, templated compensation depth ----------------
#define APL  10240            // A plane bytes: 128 * 40 elems * 2B
#define BPL  8704             // B plane bytes: 32 * 136 elems * 2B

template<int TERMS>
__global__ __launch_bounds__(256)
void gemm_t(const __nv_bfloat16* __restrict__ Ah, const __nv_bfloat16* __restrict__ Al,
            const __nv_bfloat16* __restrict__ Bh, const __nv_bfloat16* __restrict__ Bl,
            float* __restrict__ C, int K, int ldb, int ldc,
            const float* __restrict__ bias, long biasStride,
            const float* __restrict__ res, int ldres,
            long strideA, long strideB, long strideC)
{
    constexpr int NPL = (TERMS == 3) ? 2 : 1;
    constexpr uint32_t BOFF = NPL * APL;
    constexpr uint32_t STG = NPL * (APL + BPL);

    extern __shared__ __align__(16) char smem[];
    const uint32_t sb = s2u(smem);

    const int tid = threadIdx.x, lane = tid & 31, wid = tid >> 5;
    const int warp_m = wid >> 2, warp_n = wid & 3;
    const int m0 = blockIdx.x * 128, n0 = blockIdx.y * 128;

    const __nv_bfloat16* Ahz = Ah + (long)blockIdx.z * strideA;
    const __nv_bfloat16* Alz = Al + (long)blockIdx.z * strideA;
    const __nv_bfloat16* Bhz = Bh + (long)blockIdx.z * strideB;
    const __nv_bfloat16* Blz = Bl + (long)blockIdx.z * strideB;
    float* Cz = C + (long)blockIdx.z * strideC;
    const float* bz = bias ? (bias + (long)blockIdx.z * biasStride) : nullptr;

    const int lrow = (lane & 7) + ((lane >> 3) & 1) * 8;
    const int lcol = (lane >> 4) * 8;

    float acc[4][4][4];
#pragma unroll
    for (int mi = 0; mi < 4; mi++)
#pragma unroll
        for (int ni = 0; ni < 4; ni++)
#pragma unroll
            for (int j = 0; j < 4; j++) acc[mi][ni][j] = 0.f;

    const int NCH = K >> 5;

    auto issue = [&](int c) {
        const uint32_t st = sb + (uint32_t)(c & 1) * STG;
        const int k0 = c << 5;
#pragma unroll
        for (int l = 0; l < 2 * NPL; l++) {
            int idx = l * 256 + tid;
            int p = idx >> 9, rem = idx & 511, row = rem >> 2, ch = rem & 3;
            const __nv_bfloat16* src = (p ? Alz : Ahz) + (long)(m0 + row) * K + k0 + ch * 8;
            cp16(st + (uint32_t)(p * APL + row * 80 + ch * 16), src);
        }
#pragma unroll
        for (int l = 0; l < 2 * NPL; l++) {
            int idx = l * 256 + tid;
            int p = idx >> 9, rem = idx & 511, kr = rem >> 4, ch = rem & 15;
            const __nv_bfloat16* src = (p ? Blz : Bhz) + (long)(k0 + kr) * ldb + n0 + ch * 8;
            cp16(st + (uint32_t)(BOFF + p * BPL + kr * 272 + ch * 16), src);
        }
    };

    issue(0);
    asm volatile("cp.async.commit_group;" ::: "memory");

    for (int c = 0; c < NCH; c++) {
        if (c + 1 < NCH) issue(c + 1);
        asm volatile("cp.async.commit_group;" ::: "memory");
        asm volatile("cp.async.wait_group 1;" ::: "memory");
        __syncthreads();

        const uint32_t st = sb + (uint32_t)(c & 1) * STG;
        const uint32_t aS = st + (uint32_t)((warp_m * 64 + lrow) * 80 + lcol * 2);
        const uint32_t bS = st + BOFF + (uint32_t)(lrow * 272 + (warp_n * 32 + lcol) * 2);

#pragma unroll
        for (int ks = 0; ks < 2; ks++) {
            uint32_t ah[4][4], al[4][4], bh[4][2], bl[4][2];
#pragma unroll
            for (int mi = 0; mi < 4; mi++) {
                ldsm4(ah[mi][0], ah[mi][1], ah[mi][2], ah[mi][3], aS + mi * (16 * 80) + ks * 32);
                if (TERMS == 3)
                    ldsm4(al[mi][0], al[mi][1], al[mi][2], al[mi][3],
                          aS + APL + mi * (16 * 80) + ks * 32);
            }
#pragma unroll
            for (int nb = 0; nb < 2; nb++) {
                uint32_t r0, r1, r2, r3;
                ldsm4t(r0, r1, r2, r3, bS + nb * 32 + ks * (16 * 272));
                bh[nb * 2 + 0][0] = r0; bh[nb * 2 + 0][1] = r1;
                bh[nb * 2 + 1][0] = r2; bh[nb * 2 + 1][1] = r3;
                if (TERMS == 3) {
                    ldsm4t(r0, r1, r2, r3, bS + BPL + nb * 32 + ks * (16 * 272));
                    bl[nb * 2 + 0][0] = r0; bl[nb * 2 + 0][1] = r1;
                    bl[nb * 2 + 1][0] = r2; bl[nb * 2 + 1][1] = r3;
                }
            }
#pragma unroll
            for (int mi = 0; mi < 4; mi++)
#pragma unroll
                for (int ni = 0; ni < 4; ni++) {
                    if (TERMS == 3) {
                        mma_bf16(acc[mi][ni], al[mi], bh[ni]);
                        mma_bf16(acc[mi][ni], ah[mi], bl[ni]);
                    }
                    mma_bf16(acc[mi][ni], ah[mi], bh[ni]);
                }
        }
        __syncthreads();
    }

    const int r = lane >> 2, c2 = (lane & 3) << 1;
#pragma unroll
    for (int mi = 0; mi < 4; mi++) {
#pragma unroll
        for (int hh = 0; hh < 2; hh++) {
            int m = m0 + warp_m * 64 + mi * 16 + hh * 8 + r;
#pragma unroll
            for (int ni = 0; ni < 4; ni++) {
                int col = n0 + warp_n * 32 + ni * 8 + c2;
                float x0 = acc[mi][ni][hh * 2 + 0];
                float x1 = acc[mi][ni][hh * 2 + 1];
                if (bz) { x0 += bz[col]; x1 += bz[col + 1]; }
                if (res) {
                    float2 rr = *(const float2*)&res[(long)m * ldres + col];
                    x0 += rr.x; x1 += rr.y;
                }
                float2 o; o.x = x0; o.y = x1;
                *(float2*)&Cz[(long)m * ldc + col] = o;
            }
        }
    }
}

// ---------------- elementwise fp32 -> bf16 hi/lo planes ----------------
__global__ void conva(const float* __restrict__ A, __nv_bfloat16* __restrict__ hi,
                      __nv_bfloat16* __restrict__ lo, long n4)
{
    long i = (long)blockIdx.x * 256 + threadIdx.x;
    if (i >= n4) return;
    float4 f = ((const float4*)A)[i];
    float v[4] = {f.x, f.y, f.z, f.w};
    uint32_t hw[2], lw[2];
#pragma unroll
    for (int p = 0; p < 2; p++) {
        __nv_bfloat16 h0 = __float2bfloat16(v[p * 2 + 0]);
        __nv_bfloat16 h1 = __float2bfloat16(v[p * 2 + 1]);
        __nv_bfloat16 l0 = __float2bfloat16(v[p * 2 + 0] - __bfloat162float(h0));
        __nv_bfloat16 l1 = __float2bfloat16(v[p * 2 + 1] - __bfloat162float(h1));
        hw[p] = (uint32_t)__bfloat16_as_ushort(h0) | ((uint32_t)__bfloat16_as_ushort(h1) << 16);
        lw[p] = (uint32_t)__bfloat16_as_ushort(l0) | ((uint32_t)__bfloat16_as_ushort(l1) << 16);
    }
    ((uint2*)hi)[i] = make_uint2(hw[0], hw[1]);
    ((uint2*)lo)[i] = make_uint2(lw[0], lw[1]);
}

// ---------------- transpose-convert: W[z][d][e] (e-contig) -> planes [z][e][d] ----------------
__global__ void convwT(const float* __restrict__ W, __nv_bfloat16* __restrict__ hi,
                       __nv_bfloat16* __restrict__ lo, int D, int E, long str)
{
    __shared__ float t[32][33];
    const float* Wz = W + (long)blockIdx.z * str;
    __nv_bfloat16* hz = hi + (long)blockIdx.z * str;
    __nv_bfloat16* lz = lo + (long)blockIdx.z * str;
    int d0 = blockIdx.x * 32, e0 = blockIdx.y * 32;
    for (int r = threadIdx.y; r < 32; r += 8)
        t[r][threadIdx.x] = Wz[(long)(d0 + r) * E + e0 + threadIdx.x];
    __syncthreads();
    for (int r = threadIdx.y; r < 32; r += 8) {
        float v = t[threadIdx.x][r];   // element (d0+tx, e0+r)
        __nv_bfloat16 h = __float2bfloat16(v);
        long o = (long)(e0 + r) * D + d0 + threadIdx.x;
        hz[o] = h;
        lz[o] = __float2bfloat16(v - __bfloat162float(h));
    }
}

// ---------------- bias precompute: u, w, d, cvec ----------------
__global__ void prep_bias(const float* __restrict__ Wq, const float* __restrict__ bq,
                          const float* __restrict__ Wk, const float* __restrict__ bk,
                          const float* __restrict__ bv, const float* __restrict__ Wo,
                          const float* __restrict__ bo)
{
    int h = blockIdx.x, t = threadIdx.x;
    if (h < HEADS) {
        const float* wq = Wq + (long)h * HID * HID + (long)t * HID;
        const float* wk = Wk + (long)h * HID * HID + (long)t * HID;
        const float* bkh = bk + h * HID;
        const float* bqh = bq + h * HID;
        float a = 0.f, b = 0.f;
        for (int e = 0; e < HID; e++) { a += wq[e] * bkh[e]; b += wk[e] * bqh[e]; }
        g_u[h * HID + t] = a;
        g_w[h * HID + t] = b;
        if (t == 0) {
            float dd = 0.f;
            for (int e = 0; e < HID; e++) dd += bqh[e] * bkh[e];
            g_d[h] = dd;
        }
    } else {
        float a = bo[t];
        for (int he = 0; he < HEADS * HID; he++) a += bv[he] * Wo[(long)he * HID + t];
        g_cvec[t] = a;
    }
}

// ---------------- assemble Z = concat(cls, E) + pos ----------------
__global__ void assemble_kernel(const float* __restrict__ cls, const float* __restrict__ pos)
{
    long idx = (long)blockIdx.x * 256 + threadIdx.x;
    if (idx >= (long)NB * SEQ * HID) return;
    int e = (int)(idx % HID);
    long r = idx / HID;
    int s = (int)(r % SEQ);
    long n = r / SEQ;
    float v = pos[s * HID + e];
    if (s == 0) v += cls[e];
    else        v += g_E[(n * NP + (s - 1)) * (long)HID + e];
    g_Z[idx] = v;
}

// ---------------- LayerNorm -> bf16 hi/lo planes directly ----------------
__global__ __launch_bounds__(1024)
void ln_split(const float* __restrict__ in,
              __nv_bfloat16* __restrict__ oh, __nv_bfloat16* __restrict__ ol,
              const float* __restrict__ w, const float* __restrict__ b)
{
    const int n = blockIdx.x;
    const float* x = in + (long)n * SEQ * HID;
    __nv_bfloat16* yh = oh + (long)n * SEQ * HID;
    __nv_bfloat16* yl = ol + (long)n * SEQ * HID;
    float s = 0.f, ss = 0.f;
    for (int i = threadIdx.x; i < SEQ * HID; i += 1024) {
        float v = x[i]; s += v; ss += v * v;
    }
    __shared__ float red[64];
#pragma unroll
    for (int o = 16; o; o >>= 1) {
        s  += __shfl_down_sync(0xffffffffu, s, o);
        ss += __shfl_down_sync(0xffffffffu, ss, o);
    }
    int wid = threadIdx.x >> 5, lane = threadIdx.x & 31;
    if (lane == 0) { red[wid] = s; red[32 + wid] = ss; }
    __syncthreads();
    if (threadIdx.x == 0) {
        float S = 0.f, SS = 0.f;
        for (int i = 0; i < 32; i++) { S += red[i]; SS += red[32 + i]; }
        float inv = 1.0f / (SEQ * HID);
        float mu = S * inv;
        float var = SS * inv - mu * mu;
        red[0] = mu; red[1] = rsqrtf(var + 1e-5f);
    }
    __syncthreads();
    float mu = red[0], rinv = red[1];
    for (int i = threadIdx.x; i < SEQ * HID; i += 1024) {
        float y = (x[i] - mu) * rinv * w[i] + b[i];
        __nv_bfloat16 h = __float2bfloat16(y);
        yh[i] = h;
        yl[i] = __float2bfloat16(y - __bfloat162float(h));
    }
}

// ---------------- attention per (h, n): scores = T.Zn^T (+bias) -> softmax -> O = attn @ P ----------------
__global__ __launch_bounds__(256)
void attn_kernel()
{
    const int h = blockIdx.x, n = blockIdx.y;
    const float* Tm = g_T + ((long)h * ROWS + (long)n * SEQ) * HID;
    const __nv_bfloat16* Zn = g_Ah + (long)n * SEQ * HID;
    const float* P = g_P + ((long)h * ROWS + (long)n * SEQ) * HID;
    float* out = g_O + ((long)h * ROWS + (long)n * SEQ) * HID;
    const float* uh = g_u + h * HID;
    const float* wh = g_w + h * HID;

    __shared__ float sc[SEQ][SEQ + 3];
    __shared__ float work[SEQ][66];
    __shared__ float eq[SEQ], ek[SEQ];

    const int tid = threadIdx.x;
    const int tx = tid & 15, ty = tid >> 4;

    float acc[5][5];
#pragma unroll
    for (int i = 0; i < 5; i++)
#pragma unroll
        for (int j = 0; j < 5; j++) acc[i][j] = 0.f;

    int rs[5], cs[5];
#pragma unroll
    for (int i = 0; i < 5; i++) {
        int s = ty + 16 * i; rs[i] = (s < SEQ) ? s : SEQ - 1;
        int t = tx + 16 * i; cs[i] = (t < SEQ) ? t : SEQ - 1;
    }

    // rank-1 bias terms: eq[s] = Zn_s . u_h ; ek[t] = Zn_t . w_h
    if (tid < SEQ) {
        float a = 0.f, b = 0.f;
        const __nv_bfloat16* zr = Zn + (long)tid * HID;
        for (int j = 0; j < HID; j++) {
            float z = __bfloat162float(zr[j]);
            a += z * uh[j];
            b += z * wh[j];
        }
        eq[tid] = a; ek[tid] = b;
    }

    for (int k0 = 0; k0 < HID; k0 += 32) {
        for (int i = tid; i < SEQ * 32; i += 256) {
            int s = i >> 5, j = i & 31;
            work[s][j]      = Tm[s * HID + k0 + j];
            work[s][33 + j] = __bfloat162float(Zn[s * HID + k0 + j]);
        }
        __syncthreads();
#pragma unroll 4
        for (int j = 0; j < 32; j++) {
            float qv[5], kv[5];
#pragma unroll
            for (int i = 0; i < 5; i++) qv[i] = work[rs[i]][j];
#pragma unroll
            for (int i = 0; i < 5; i++) kv[i] = work[cs[i]][33 + j];
#pragma unroll
            for (int i = 0; i < 5; i++)
#pragma unroll
                for (int jj = 0; jj < 5; jj++) acc[i][jj] += qv[i] * kv[jj];
        }
        __syncthreads();
    }

#pragma unroll
    for (int i = 0; i < 5; i++) {
        int s = ty + 16 * i;
        if (s < SEQ) {
#pragma unroll
            for (int jj = 0; jj < 5; jj++) {
                int t = tx + 16 * jj;
                if (t < SEQ) sc[s][t] = acc[i][jj];
            }
        }
    }
    __syncthreads();

    if (tid < SEQ) {
        const float scale = 1.0f / (512.0f * 512.0f);
        const float dh = g_d[h];
        float m = -1e30f;
        for (int t = 0; t < SEQ; t++) {
            float l = (sc[tid][t] + eq[tid] + ek[t] + dh) * scale;
            sc[tid][t] = l;
            m = fmaxf(m, l);
        }
        float sum = 0.f;
        for (int t = 0; t < SEQ; t++) {
            float e = __expf(sc[tid][t] - m);
            sc[tid][t] = e; sum += e;
        }
        float rr = 1.0f / sum;
        for (int t = 0; t < SEQ; t++) sc[tid][t] *= rr;
    }
    __syncthreads();

    for (int e0 = 0; e0 < HID; e0 += 64) {
        for (int i = tid; i < SEQ * 64; i += 256) {
            int t = i >> 6, j = i & 63;
            work[t][j] = P[t * HID + e0 + j];
        }
        __syncthreads();
        float acc2[5][4];
#pragma unroll
        for (int i = 0; i < 5; i++)
#pragma unroll
            for (int j = 0; j < 4; j++) acc2[i][j] = 0.f;

        for (int t = 0; t < SEQ; t++) {
            float sv[5], vv[4];
#pragma unroll
            for (int i = 0; i < 5; i++) sv[i] = sc[rs[i]][t];
#pragma unroll
            for (int j = 0; j < 4; j++) vv[j] = work[t][tx + 16 * j];
#pragma unroll
            for (int i = 0; i < 5; i++)
#pragma unroll
                for (int j = 0; j < 4; j++) acc2[i][j] += sv[i] * vv[j];
        }
#pragma unroll
        for (int i = 0; i < 5; i++) {
            int s = ty + 16 * i;
            if (s < SEQ) {
#pragma unroll
                for (int j = 0; j < 4; j++)
                    out[(long)s * HID + e0 + tx + 16 * j] = acc2[i][j];
            }
        }
        __syncthreads();
    }
}

// ---------------- reduce: R = sum_h O_h + cvec + Z ----------------
__global__ void reduce_kernel()
{
    long i4 = (long)blockIdx.x * 256 + threadIdx.x;   // over ROWS*HID/4
    if (i4 >= (long)ROWS * HID / 4) return;
    int e4 = (int)(i4 & (HID / 4 - 1));
    float4 a = ((const float4*)g_Z)[i4];
    float4 cv = ((const float4*)g_cvec)[e4];
    a.x += cv.x; a.y += cv.y; a.z += cv.z; a.w += cv.w;
#pragma unroll
    for (int h = 0; h < HEADS; h++) {
        float4 o = ((const float4*)g_O)[(long)h * (ROWS * HID / 4) + i4];
        a.x += o.x; a.y += o.y; a.z += o.z; a.w += o.w;
    }
    ((float4*)g_R)[i4] = a;
}

// ---------------- classification head ----------------
__global__ void head_kernel(const float* __restrict__ Wh, const float* __restrict__ bh,
                            float* __restrict__ out)
{
    const int n = blockIdx.x;
    const int o = threadIdx.y;
    const int lane = threadIdx.x;
    const float* z = g_Z + (long)n * SEQ * HID;
    float a = 0.f;
    for (int e = lane; e < HID; e += 32) a += z[e] * Wh[e * OUTD + o];
#pragma unroll
    for (int off = 16; off; off >>= 1) a += __shfl_down_sync(0xffffffffu, a, off);
    if (lane == 0) out[n * OUTD + o] = tanhf(a + bh[o]);
}

// ---------------- host launcher ----------------
static float* sym_addr(const void* symbol)
{
    void* p = nullptr;
    cudaGetSymbolAddress(&p, symbol);
    return (float*)p;
}
static __nv_bfloat16* sym_addr_b(const void* symbol)
{
    void* p = nullptr;
    cudaGetSymbolAddress(&p, symbol);
    return (__nv_bfloat16*)p;
}

extern "C" void kernel_launch(void* const* d_in, const int* in_sizes, int n_in,
                              void* d_out, int out_size)
{
    const float* X    = (const float*)d_in[0];
    const float* Wp   = (const float*)d_in[1];
    const float* bp   = (const float*)d_in[2];
    const float* cls  = (const float*)d_in[3];
    const float* pos  = (const float*)d_in[4];
    const float* ln1w = (const float*)d_in[5];
    const float* ln1b = (const float*)d_in[6];
    const float* Wq   = (const float*)d_in[7];
    const float* bq   = (const float*)d_in[8];
    const float* Wk   = (const float*)d_in[9];
    const float* bk   = (const float*)d_in[10];
    const float* Wv   = (const float*)d_in[11];
    const float* bv   = (const float*)d_in[12];
    const float* Wo   = (const float*)d_in[13];
    const float* bo   = (const float*)d_in[14];
    const float* ln2w = (const float*)d_in[15];
    const float* ln2b = (const float*)d_in[16];
    const float* W2   = (const float*)d_in[17];
    const float* b2   = (const float*)d_in[18];
    const float* Wh   = (const float*)d_in[19];
    const float* bh   = (const float*)d_in[20];
    float* out = (float*)d_out;

    float* Z   = sym_addr(g_Z);
    float* R   = sym_addr(g_R);
    float* E   = sym_addr(g_E);
    float* T   = sym_addr(g_T);
    float* P   = sym_addr(g_P);
    float* Gf  = sym_addr(g_Gf);
    float* Uf  = sym_addr(g_Uf);
    __nv_bfloat16* Ah   = sym_addr_b(g_Ah),   *Al   = sym_addr_b(g_Al);
    __nv_bfloat16* Wph  = sym_addr_b(g_Wph),  *Wpl  = sym_addr_b(g_Wpl);
    __nv_bfloat16* Wqh  = sym_addr_b(g_Wqh),  *Wql  = sym_addr_b(g_Wql);
    __nv_bfloat16* WkTh = sym_addr_b(g_WkTh), *WkTl = sym_addr_b(g_WkTl);
    __nv_bfloat16* Wvh  = sym_addr_b(g_Wvh),  *Wvl  = sym_addr_b(g_Wvl);
    __nv_bfloat16* Woh  = sym_addr_b(g_Woh),  *Wol  = sym_addr_b(g_Wol);
    __nv_bfloat16* W2h  = sym_addr_b(g_W2h),  *W2l  = sym_addr_b(g_W2l);
    __nv_bfloat16* Gh   = sym_addr_b(g_Gh),   *Gl   = sym_addr_b(g_Gl);
    __nv_bfloat16* Uh   = sym_addr_b(g_Uh),   *Ul   = sym_addr_b(g_Ul);

    const int GSM1 = 2 * (APL + BPL);
    const int GSM3 = 2 * (2 * APL + 2 * BPL);
    cudaFuncSetAttribute(gemm_t<1>, cudaFuncAttributeMaxDynamicSharedMemorySize, GSM1);
    cudaFuncSetAttribute(gemm_t<3>, cudaFuncAttributeMaxDynamicSharedMemorySize, GSM3);

    const long WS = (long)HID * HID;         // per-head weight stride
    const long QS = (long)ROWS * HID;        // per-head activation stride
    const long W4 = (long)HEADS * HID * HID / 4;

    // ---- weight plane conversions ----
    conva<<<(PDIM * HID / 4 + 255) / 256, 256>>>(Wp, Wph, Wpl, PDIM * HID / 4);
    conva<<<(unsigned)((W4 + 255) / 256), 256>>>(Wq, Wqh, Wql, W4);
    convwT<<<dim3(HID / 32, HID / 32, HEADS), dim3(32, 8)>>>(Wk, WkTh, WkTl, HID, HID, WS);
    conva<<<(unsigned)((W4 + 255) / 256), 256>>>(Wv, Wvh, Wvl, W4);
    conva<<<(unsigned)((W4 + 255) / 256), 256>>>(Wo, Woh, Wol, W4);
    conva<<<(HID * HID / 4 + 255) / 256, 256>>>(W2, W2h, W2l, HID * HID / 4);

    // ---- folded weights: G = Wq WkT, U = Wv Wo_h (3-term, once) ----
    gemm_t<3><<<dim3(4, 4, HEADS), 256, GSM3>>>(Wqh, Wql, WkTh, WkTl, Gf, HID, HID, HID,
                                                nullptr, 0, nullptr, 0, WS, WS, WS);
    gemm_t<3><<<dim3(4, 4, HEADS), 256, GSM3>>>(Wvh, Wvl, Woh, Wol, Uf, HID, HID, HID,
                                                nullptr, 0, nullptr, 0, WS, WS, WS);
    conva<<<(unsigned)((W4 + 255) / 256), 256>>>(Gf, Gh, Gl, W4);
    conva<<<(unsigned)((W4 + 255) / 256), 256>>>(Uf, Uh, Ul, W4);

    // ---- bias folds ----
    prep_bias<<<HEADS + 1, HID>>>(Wq, bq, Wk, bk, bv, Wo, bo);

    // ---- patch embed: E = X(as [16384,256]) @ Wp + bp ----
    {
        long n4 = (long)NB * NP * PDIM / 4;
        conva<<<(unsigned)((n4 + 255) / 256), 256>>>(X, Ah, Al, n4);
        gemm_t<3><<<dim3((NB * NP) / 128, HID / 128, 1), 256, GSM3>>>(
            Ah, Al, Wph, Wpl, E, PDIM, HID, HID, bp, 0, nullptr, 0, 0, 0, 0);
    }
    // ---- Z = concat(cls, E) + pos ----
    {
        long total = (long)NB * SEQ * HID;
        assemble_kernel<<<(unsigned)((total + 255) / 256), 256>>>(cls, pos);
    }

    dim3 gProj(ROWS / 128, HID / 128, HEADS);
    dim3 gRow(ROWS / 128, HID / 128, 1);
    unsigned redGrid = (unsigned)((ROWS * HID / 4 + 255) / 256);

    for (int blk = 0; blk < 6; blk++) {
        // LN1: Z -> bf16 planes
        ln_split<<<NB, 1024>>>(Z, Ah, Al, ln1w, ln1b);

        // T = Zn @ G (1-term), P = Zn @ U (3-term)
        gemm_t<1><<<gProj, 256, GSM1>>>(Ah, Al, Gh, Gl, T, HID, HID, HID,
                                        nullptr, 0, nullptr, 0, 0, WS, QS);
        gemm_t<3><<<gProj, 256, GSM3>>>(Ah, Al, Uh, Ul, P, HID, HID, HID,
                                        nullptr, 0, nullptr, 0, 0, WS, QS);

        // attention: scores = T.Zn^T -> softmax -> O_h = attn @ P_h
        attn_kernel<<<dim3(HEADS, NB), 256>>>();

        // R = sum_h O_h + cvec + Z
        reduce_kernel<<<redGrid, 256>>>();

        // LN2: R -> planes; Z = planes @ W2 + b2
        ln_split<<<NB, 1024>>>(R, Ah, Al, ln2w, ln2b);
        gemm_t<3><<<gRow, 256, GSM3>>>(Ah, Al, W2h, W2l, Z, HID, HID, HID,
                                       b2, 0, nullptr, 0, 0, 0, 0);
    }

    // head: out = tanh(Z[:,0] @ Wh + bh)
    head_kernel<<<NB, dim3(32, 10)>>>(Wh, bh, out);
    (void)in_sizes; (void)n_in; (void)out_size;
}

// round 15
// speedup vs baseline: 8.5451x; 1.1506x over previous
#include <cuda_runtime.h>
#include <cuda_bf16.h>
#include <cstdint>

#define NB      256      // batch
#define SEQ     65
#define HID     512
#define HEADS   8
#define NP      64       // patches
#define PDIM    256
#define ROWS    (NB*SEQ) // 16640
#define OUTD    10

// ---------------- fp32 scratch ----------------
__device__ float g_Z [NB*SEQ*HID];
__device__ float g_R [NB*SEQ*HID];
__device__ float g_E [NB*NP*HID];
__device__ float g_O [HEADS*ROWS*HID];   // O_h = attn_h @ P_h
__device__ float g_Gf[HEADS*HID*HID];    // G = Wq Wk^T (fp32)
__device__ float g_Uf[HEADS*HID*HID];    // U = Wv Wo_h (fp32)
__device__ float g_u [HEADS*HID];        // Wq @ bk
__device__ float g_w [HEADS*HID];        // Wk @ bq
__device__ float g_d [HEADS];            // bq . bk
__device__ float g_cvec[HID];            // sum_h bv_h @ Wo_h + bo

// ---------------- bf16 planes ----------------
__device__ __nv_bfloat16 g_Ah[ROWS*HID],          g_Al[ROWS*HID];        // Zn planes
__device__ __nv_bfloat16 g_Th[HEADS*ROWS*HID];                           // T hi (scores only)
__device__ __nv_bfloat16 g_Ph[HEADS*ROWS*HID],    g_Pl[HEADS*ROWS*HID];  // P planes
__device__ __nv_bfloat16 g_Wph[PDIM*HID],         g_Wpl[PDIM*HID];
__device__ __nv_bfloat16 g_Wqh[HEADS*HID*HID],    g_Wql[HEADS*HID*HID];
__device__ __nv_bfloat16 g_WkTh[HEADS*HID*HID],   g_WkTl[HEADS*HID*HID];
__device__ __nv_bfloat16 g_Wvh[HEADS*HID*HID],    g_Wvl[HEADS*HID*HID];
__device__ __nv_bfloat16 g_Woh[HEADS*HID*HID],    g_Wol[HEADS*HID*HID];
__device__ __nv_bfloat16 g_W2h[HID*HID],          g_W2l[HID*HID];
__device__ __nv_bfloat16 g_Gh[HEADS*HID*HID],     g_Gl[HEADS*HID*HID];
__device__ __nv_bfloat16 g_Uh[HEADS*HID*HID],     g_Ul[HEADS*HID*HID];

// ---------------- PTX helpers ----------------
__device__ __forceinline__ uint32_t s2u(const void* p)
{
    uint32_t a;
    asm("{ .reg .u64 t; cvta.to.shared.u64 t, %1; cvt.u32.u64 %0, t; }" : "=r"(a) : "l"(p));
    return a;
}

__device__ __forceinline__ void cp16(uint32_t dst, const void* src)
{
    asm volatile("cp.async.cg.shared.global [%0], [%1], 16;" :: "r"(dst), "l"(src));
}

__device__ __forceinline__ void ldsm4(uint32_t& r0, uint32_t& r1, uint32_t& r2, uint32_t& r3,
                                      uint32_t addr)
{
    asm volatile("ldmatrix.sync.aligned.m8n8.x4.shared.b16 {%0,%1,%2,%3}, [%4];"
                 : "=r"(r0), "=r"(r1), "=r"(r2), "=r"(r3) : "r"(addr));
}

__device__ __forceinline__ void ldsm2(uint32_t& r0, uint32_t& r1, uint32_t addr)
{
    asm volatile("ldmatrix.sync.aligned.m8n8.x2.shared.b16 {%0,%1}, [%2];"
                 : "=r"(r0), "=r"(r1) : "r"(addr));
}

__device__ __forceinline__ void ldsm4t(uint32_t& r0, uint32_t& r1, uint32_t& r2, uint32_t& r3,
                                       uint32_t addr)
{
    asm volatile("ldmatrix.sync.aligned.m8n8.x4.trans.shared.b16 {%0,%1,%2,%3}, [%4];"
                 : "=r"(r0), "=r"(r1), "=r"(r2), "=r"(r3) : "r"(addr));
}

__device__ __forceinline__ void mma_bf16(float c[4], const uint32_t a[4], const uint32_t b[2])
{
    asm volatile(
        "mma.sync.aligned.m16n8k16.row.col.f32.bf16.bf16.f32 "
        "{%0,%1,%2,%3},{%4,%5,%6,%7},{%8,%9},{%0,%1,%2,%3};"
        : "+f"(c[0]), "+f"(c[1]), "+f"(c[2]), "+f"(c[3])
        : "r"(a[0]), "r"(a[1]), "r"(a[2]), "r"(a[3]),
          "r"(b[0]), "r"(b[1]));
}

__device__ __forceinline__ uint32_t packbf(float x0, float x1)
{
    __nv_bfloat16 h0 = __float2bfloat16(x0);
    __nv_bfloat16 h1 = __float2bfloat16(x1);
    return (uint32_t)__bfloat16_as_ushort(h0) | ((uint32_t)__bfloat16_as_ushort(h1) << 16);
}

// ---------------- bf16 GEMM, templated compensation depth + output mode ----------------
#define APL  10240            // A plane bytes: 128 * 40 elems * 2B
#define BPL  8704             // B plane bytes: 32 * 136 elems * 2B

template<int TERMS, int OUTBF>
__global__ __launch_bounds__(256)
void gemm_t(const __nv_bfloat16* __restrict__ Ah, const __nv_bfloat16* __restrict__ Al,
            const __nv_bfloat16* __restrict__ Bh, const __nv_bfloat16* __restrict__ Bl,
            void* __restrict__ Cv, void* __restrict__ Clv,
            int K, int ldb, int ldc,
            const float* __restrict__ bias, long biasStride,
            const float* __restrict__ res, int ldres,
            long strideA, long strideB, long strideC)
{
    constexpr int NPL = (TERMS == 3) ? 2 : 1;
    constexpr uint32_t BOFF = NPL * APL;
    constexpr uint32_t STG = NPL * (APL + BPL);

    extern __shared__ __align__(16) char smem[];
    const uint32_t sb = s2u(smem);

    const int tid = threadIdx.x, lane = tid & 31, wid = tid >> 5;
    const int warp_m = wid >> 2, warp_n = wid & 3;
    const int m0 = blockIdx.x * 128, n0 = blockIdx.y * 128;

    const __nv_bfloat16* Ahz = Ah + (long)blockIdx.z * strideA;
    const __nv_bfloat16* Alz = Al + (long)blockIdx.z * strideA;
    const __nv_bfloat16* Bhz = Bh + (long)blockIdx.z * strideB;
    const __nv_bfloat16* Blz = Bl + (long)blockIdx.z * strideB;
    const float* bz = bias ? (bias + (long)blockIdx.z * biasStride) : nullptr;

    const int lrow = (lane & 7) + ((lane >> 3) & 1) * 8;
    const int lcol = (lane >> 4) * 8;

    float acc[4][4][4];
#pragma unroll
    for (int mi = 0; mi < 4; mi++)
#pragma unroll
        for (int ni = 0; ni < 4; ni++)
#pragma unroll
            for (int j = 0; j < 4; j++) acc[mi][ni][j] = 0.f;

    const int NCH = K >> 5;

    auto issue = [&](int c) {
        const uint32_t st = sb + (uint32_t)(c & 1) * STG;
        const int k0 = c << 5;
        for (int l = 0; l < 2 * NPL; l++) {
            int idx = l * 256 + tid;
            int p = idx >> 9, rem = idx & 511, row = rem >> 2, ch = rem & 3;
            const __nv_bfloat16* src = (p ? Alz : Ahz) + (long)(m0 + row) * K + k0 + ch * 8;
            cp16(st + (uint32_t)(p * APL + row * 80 + ch * 16), src);
        }
        for (int l = 0; l < 2 * NPL; l++) {
            int idx = l * 256 + tid;
            int p = idx >> 9, rem = idx & 511, kr = rem >> 4, ch = rem & 15;
            const __nv_bfloat16* src = (p ? Blz : Bhz) + (long)(k0 + kr) * ldb + n0 + ch * 8;
            cp16(st + (uint32_t)(BOFF + p * BPL + kr * 272 + ch * 16), src);
        }
    };

    issue(0);
    asm volatile("cp.async.commit_group;" ::: "memory");

    for (int c = 0; c < NCH; c++) {
        if (c + 1 < NCH) issue(c + 1);
        asm volatile("cp.async.commit_group;" ::: "memory");
        asm volatile("cp.async.wait_group 1;" ::: "memory");
        __syncthreads();

        const uint32_t st = sb + (uint32_t)(c & 1) * STG;
        const uint32_t aS = st + (uint32_t)((warp_m * 64 + lrow) * 80 + lcol * 2);
        const uint32_t bS = st + BOFF + (uint32_t)(lrow * 272 + (warp_n * 32 + lcol) * 2);

#pragma unroll
        for (int ks = 0; ks < 2; ks++) {
            uint32_t ah[4][4], al[4][4], bh[4][2], bl[4][2];
#pragma unroll
            for (int mi = 0; mi < 4; mi++) {
                ldsm4(ah[mi][0], ah[mi][1], ah[mi][2], ah[mi][3], aS + mi * (16 * 80) + ks * 32);
                if (TERMS == 3)
                    ldsm4(al[mi][0], al[mi][1], al[mi][2], al[mi][3],
                          aS + APL + mi * (16 * 80) + ks * 32);
            }
#pragma unroll
            for (int nb = 0; nb < 2; nb++) {
                uint32_t r0, r1, r2, r3;
                ldsm4t(r0, r1, r2, r3, bS + nb * 32 + ks * (16 * 272));
                bh[nb * 2 + 0][0] = r0; bh[nb * 2 + 0][1] = r1;
                bh[nb * 2 + 1][0] = r2; bh[nb * 2 + 1][1] = r3;
                if (TERMS == 3) {
                    ldsm4t(r0, r1, r2, r3, bS + BPL + nb * 32 + ks * (16 * 272));
                    bl[nb * 2 + 0][0] = r0; bl[nb * 2 + 0][1] = r1;
                    bl[nb * 2 + 1][0] = r2; bl[nb * 2 + 1][1] = r3;
                }
            }
#pragma unroll
            for (int mi = 0; mi < 4; mi++)
#pragma unroll
                for (int ni = 0; ni < 4; ni++) {
                    if (TERMS == 3) {
                        mma_bf16(acc[mi][ni], al[mi], bh[ni]);
                        mma_bf16(acc[mi][ni], ah[mi], bl[ni]);
                    }
                    mma_bf16(acc[mi][ni], ah[mi], bh[ni]);
                }
        }
        __syncthreads();
    }

    const int r = lane >> 2, c2 = (lane & 3) << 1;
    if (OUTBF) {
        __nv_bfloat16* Ch = (__nv_bfloat16*)Cv + (long)blockIdx.z * strideC;
        __nv_bfloat16* Cl = Clv ? ((__nv_bfloat16*)Clv + (long)blockIdx.z * strideC) : nullptr;
#pragma unroll
        for (int mi = 0; mi < 4; mi++) {
#pragma unroll
            for (int hh = 0; hh < 2; hh++) {
                int m = m0 + warp_m * 64 + mi * 16 + hh * 8 + r;
#pragma unroll
                for (int ni = 0; ni < 4; ni++) {
                    int col = n0 + warp_n * 32 + ni * 8 + c2;
                    float x0 = acc[mi][ni][hh * 2 + 0];
                    float x1 = acc[mi][ni][hh * 2 + 1];
                    __nv_bfloat16 h0 = __float2bfloat16(x0);
                    __nv_bfloat16 h1 = __float2bfloat16(x1);
                    uint32_t hw = (uint32_t)__bfloat16_as_ushort(h0) |
                                  ((uint32_t)__bfloat16_as_ushort(h1) << 16);
                    *(uint32_t*)&Ch[(long)m * ldc + col] = hw;
                    if (Cl) {
                        uint32_t lw = packbf(x0 - __bfloat162float(h0),
                                             x1 - __bfloat162float(h1));
                        *(uint32_t*)&Cl[(long)m * ldc + col] = lw;
                    }
                }
            }
        }
    } else {
        float* Cz = (float*)Cv + (long)blockIdx.z * strideC;
#pragma unroll
        for (int mi = 0; mi < 4; mi++) {
#pragma unroll
            for (int hh = 0; hh < 2; hh++) {
                int m = m0 + warp_m * 64 + mi * 16 + hh * 8 + r;
#pragma unroll
                for (int ni = 0; ni < 4; ni++) {
                    int col = n0 + warp_n * 32 + ni * 8 + c2;
                    float x0 = acc[mi][ni][hh * 2 + 0];
                    float x1 = acc[mi][ni][hh * 2 + 1];
                    if (bz) { x0 += bz[col]; x1 += bz[col + 1]; }
                    if (res) {
                        float2 rr = *(const float2*)&res[(long)m * ldres + col];
                        x0 += rr.x; x1 += rr.y;
                    }
                    float2 o; o.x = x0; o.y = x1;
                    *(float2*)&Cz[(long)m * ldc + col] = o;
                }
            }
        }
    }
}

// ---------------- elementwise fp32 -> bf16 hi/lo planes ----------------
__global__ void conva(const float* __restrict__ A, __nv_bfloat16* __restrict__ hi,
                      __nv_bfloat16* __restrict__ lo, long n4)
{
    long i = (long)blockIdx.x * 256 + threadIdx.x;
    if (i >= n4) return;
    float4 f = ((const float4*)A)[i];
    float v[4] = {f.x, f.y, f.z, f.w};
    uint32_t hw[2], lw[2];
#pragma unroll
    for (int p = 0; p < 2; p++) {
        __nv_bfloat16 h0 = __float2bfloat16(v[p * 2 + 0]);
        __nv_bfloat16 h1 = __float2bfloat16(v[p * 2 + 1]);
        __nv_bfloat16 l0 = __float2bfloat16(v[p * 2 + 0] - __bfloat162float(h0));
        __nv_bfloat16 l1 = __float2bfloat16(v[p * 2 + 1] - __bfloat162float(h1));
        hw[p] = (uint32_t)__bfloat16_as_ushort(h0) | ((uint32_t)__bfloat16_as_ushort(h1) << 16);
        lw[p] = (uint32_t)__bfloat16_as_ushort(l0) | ((uint32_t)__bfloat16_as_ushort(l1) << 16);
    }
    ((uint2*)hi)[i] = make_uint2(hw[0], hw[1]);
    ((uint2*)lo)[i] = make_uint2(lw[0], lw[1]);
}

// ---------------- transpose-convert: W[z][d][e] -> planes [z][e][d] ----------------
__global__ void convwT(const float* __restrict__ W, __nv_bfloat16* __restrict__ hi,
                       __nv_bfloat16* __restrict__ lo, int D, int E, long str)
{
    __shared__ float t[32][33];
    const float* Wz = W + (long)blockIdx.z * str;
    __nv_bfloat16* hz = hi + (long)blockIdx.z * str;
    __nv_bfloat16* lz = lo + (long)blockIdx.z * str;
    int d0 = blockIdx.x * 32, e0 = blockIdx.y * 32;
    for (int r = threadIdx.y; r < 32; r += 8)
        t[r][threadIdx.x] = Wz[(long)(d0 + r) * E + e0 + threadIdx.x];
    __syncthreads();
    for (int r = threadIdx.y; r < 32; r += 8) {
        float v = t[threadIdx.x][r];
        __nv_bfloat16 h = __float2bfloat16(v);
        long o = (long)(e0 + r) * D + d0 + threadIdx.x;
        hz[o] = h;
        lz[o] = __float2bfloat16(v - __bfloat162float(h));
    }
}

// ---------------- bias precompute ----------------
__global__ void prep_bias(const float* __restrict__ Wq, const float* __restrict__ bq,
                          const float* __restrict__ Wk, const float* __restrict__ bk,
                          const float* __restrict__ bv, const float* __restrict__ Wo,
                          const float* __restrict__ bo)
{
    int h = blockIdx.x, t = threadIdx.x;
    if (h < HEADS) {
        const float* wq = Wq + (long)h * HID * HID + (long)t * HID;
        const float* wk = Wk + (long)h * HID * HID + (long)t * HID;
        const float* bkh = bk + h * HID;
        const float* bqh = bq + h * HID;
        float a = 0.f, b = 0.f;
        for (int e = 0; e < HID; e++) { a += wq[e] * bkh[e]; b += wk[e] * bqh[e]; }
        g_u[h * HID + t] = a;
        g_w[h * HID + t] = b;
        if (t == 0) {
            float dd = 0.f;
            for (int e = 0; e < HID; e++) dd += bqh[e] * bkh[e];
            g_d[h] = dd;
        }
    } else {
        float a = bo[t];
        for (int he = 0; he < HEADS * HID; he++) a += bv[he] * Wo[(long)he * HID + t];
        g_cvec[t] = a;
    }
}

// ---------------- assemble Z = concat(cls, E) + pos ----------------
__global__ void assemble_kernel(const float* __restrict__ cls, const float* __restrict__ pos)
{
    long idx = (long)blockIdx.x * 256 + threadIdx.x;
    if (idx >= (long)NB * SEQ * HID) return;
    int e = (int)(idx % HID);
    long r = idx / HID;
    int s = (int)(r % SEQ);
    long n = r / SEQ;
    float v = pos[s * HID + e];
    if (s == 0) v += cls[e];
    else        v += g_E[(n * NP + (s - 1)) * (long)HID + e];
    g_Z[idx] = v;
}

// ---------------- LayerNorm -> bf16 hi/lo planes ----------------
__global__ __launch_bounds__(1024)
void ln_split(const float* __restrict__ in,
              __nv_bfloat16* __restrict__ oh, __nv_bfloat16* __restrict__ ol,
              const float* __restrict__ w, const float* __restrict__ b)
{
    const int n = blockIdx.x;
    const float* x = in + (long)n * SEQ * HID;
    __nv_bfloat16* yh = oh + (long)n * SEQ * HID;
    __nv_bfloat16* yl = ol + (long)n * SEQ * HID;
    float s = 0.f, ss = 0.f;
    for (int i = threadIdx.x; i < SEQ * HID; i += 1024) {
        float v = x[i]; s += v; ss += v * v;
    }
    __shared__ float red[64];
#pragma unroll
    for (int o = 16; o; o >>= 1) {
        s  += __shfl_down_sync(0xffffffffu, s, o);
        ss += __shfl_down_sync(0xffffffffu, ss, o);
    }
    int wid = threadIdx.x >> 5, lane = threadIdx.x & 31;
    if (lane == 0) { red[wid] = s; red[32 + wid] = ss; }
    __syncthreads();
    if (threadIdx.x == 0) {
        float S = 0.f, SS = 0.f;
        for (int i = 0; i < 32; i++) { S += red[i]; SS += red[32 + i]; }
        float inv = 1.0f / (SEQ * HID);
        float mu = S * inv;
        float var = SS * inv - mu * mu;
        red[0] = mu; red[1] = rsqrtf(var + 1e-5f);
    }
    __syncthreads();
    float mu = red[0], rinv = red[1];
    for (int i = threadIdx.x; i < SEQ * HID; i += 1024) {
        float y = (x[i] - mu) * rinv * w[i] + b[i];
        __nv_bfloat16 h = __float2bfloat16(y);
        yh[i] = h;
        yl[i] = __float2bfloat16(y - __bfloat162float(h));
    }
}

// ---------------- tensor-core attention per (h, n) ----------------
// scores = Th . Znh^T (bf16 1-term) + rank-1 bias  -> softmax (fp32)
// O = attn(hi/lo) @ P(hi/lo) 3-term  -> g_O fp32
#define AT_SMEM 86976

__global__ __launch_bounds__(256)
void attn_mma()
{
    extern __shared__ __align__(16) char sm[];
    const int h = blockIdx.x, n = blockIdx.y;
    const int tid = threadIdx.x, lane = tid & 31, wid = tid >> 5;
    const int lane15 = lane & 15, laneHi = lane >> 4;

    __nv_bfloat16* sT  = (__nv_bfloat16*)(sm);               // [80][40]
    __nv_bfloat16* sZ  = (__nv_bfloat16*)(sm + 6400);        // [80][40]
    __nv_bfloat16* sAh = (__nv_bfloat16*)(sm + 12800);       // [80][88]
    __nv_bfloat16* sAl = (__nv_bfloat16*)(sm + 26880);       // [80][88]
    float*         sS  = (float*)(sm + 40960);               // [80][81] (overlaps sPh)
    __nv_bfloat16* sPh = (__nv_bfloat16*)(sm + 40960);       // [80][136]
    __nv_bfloat16* sPl = (__nv_bfloat16*)(sm + 62720);       // [80][136]
    float* sEqP = (float*)(sm + 84480);                      // [68][4]
    float* sEkP = (float*)(sm + 85568);                      // [68][4]
    float* sEkS = (float*)(sm + 86656);                      // [80]

    const long tb = (long)h * ROWS + (long)n * SEQ;
    const __nv_bfloat16* ZnB = g_Ah + (long)n * SEQ * HID;
    const float* uh = g_u + h * HID;
    const float* wh = g_w + h * HID;

    // ---- rank-1 bias partials ----
    {
        int s = tid >> 2, q = tid & 3;
        const __nv_bfloat16* zr = ZnB + (long)s * HID + q * 128;
        const float* up = uh + q * 128;
        const float* wp = wh + q * 128;
        float a = 0.f, b = 0.f;
        for (int j = 0; j < 128; j++) {
            float z = __bfloat162float(zr[j]);
            a += z * up[j]; b += z * wp[j];
        }
        sEqP[s * 4 + q] = a; sEkP[s * 4 + q] = b;
        if (tid < 4) {
            const __nv_bfloat16* zr2 = ZnB + (long)64 * HID + tid * 128;
            const float* up2 = uh + tid * 128;
            const float* wp2 = wh + tid * 128;
            float a2 = 0.f, b2 = 0.f;
            for (int j = 0; j < 128; j++) {
                float z = __bfloat162float(zr2[j]);
                a2 += z * up2[j]; b2 += z * wp2[j];
            }
            sEqP[64 * 4 + tid] = a2; sEkP[64 * 4 + tid] = b2;
        }
    }

    // ---- score phase: 50 m16n8 units over 8 warps, 7 slots each ----
    float acc[7][4];
#pragma unroll
    for (int i = 0; i < 7; i++)
#pragma unroll
        for (int j = 0; j < 4; j++) acc[i][j] = 0.f;

    const uint32_t sTb = s2u(sT), sZb = s2u(sZ);

    for (int kc = 0; kc < 16; kc++) {
        for (int t2 = tid; t2 < 640; t2 += 256) {
            int half = (t2 >= 320) ? 1 : 0;
            int j = t2 - half * 320;
            int r = j >> 2, ch = j & 3;
            int rr = (r < 65) ? r : 64;
            const __nv_bfloat16* src = half
                ? (ZnB + (long)rr * HID + kc * 32 + ch * 8)
                : (g_Th + (tb + rr) * HID + kc * 32 + ch * 8);
            __nv_bfloat16* dst = (half ? sZ : sT) + r * 40 + ch * 8;
            *(uint4*)dst = *(const uint4*)src;
        }
        __syncthreads();
#pragma unroll
        for (int i = 0; i < 7; i++) {
            int u = wid + 8 * i;
            if (u < 50) {
                int mt = u / 10, nt = u - mt * 10;
#pragma unroll
                for (int ks = 0; ks < 2; ks++) {
                    uint32_t a[4], b[2];
                    ldsm4(a[0], a[1], a[2], a[3],
                          sTb + (uint32_t)((mt * 16 + lane15) * 80 + ks * 32 + laneHi * 16));
                    ldsm2(b[0], b[1],
                          sZb + (uint32_t)((nt * 8 + (lane & 7)) * 80 + ks * 32 + ((lane >> 3) & 1) * 16));
                    mma_bf16(acc[i], a, b);
                }
            }
        }
        __syncthreads();
    }

    // ---- write scores to sS ----
    {
        int r0 = lane >> 2, c0 = (lane & 3) * 2;
#pragma unroll
        for (int i = 0; i < 7; i++) {
            int u = wid + 8 * i;
            if (u < 50) {
                int mt = u / 10, nt = u - mt * 10;
                int rr = mt * 16 + r0, cc = nt * 8 + c0;
                sS[rr * 81 + cc] = acc[i][0];
                sS[rr * 81 + cc + 1] = acc[i][1];
                sS[(rr + 8) * 81 + cc] = acc[i][2];
                sS[(rr + 8) * 81 + cc + 1] = acc[i][3];
            }
        }
    }
    __syncthreads();

    if (tid < 65)
        sEkS[tid] = sEkP[tid * 4] + sEkP[tid * 4 + 1] + sEkP[tid * 4 + 2] + sEkP[tid * 4 + 3];
    __syncthreads();

    // ---- softmax rows + bf16 split of attn ----
    if (tid < 65) {
        const float scale = 1.0f / (512.0f * 512.0f);
        const float dh = g_d[h];
        float eqv = sEqP[tid * 4] + sEqP[tid * 4 + 1] + sEqP[tid * 4 + 2] + sEqP[tid * 4 + 3];
        float m = -1e30f;
        for (int t = 0; t < 65; t++) {
            float l = (sS[tid * 81 + t] + eqv + sEkS[t] + dh) * scale;
            sS[tid * 81 + t] = l;
            m = fmaxf(m, l);
        }
        float sum = 0.f;
        for (int t = 0; t < 65; t++) {
            float e = __expf(sS[tid * 81 + t] - m);
            sS[tid * 81 + t] = e; sum += e;
        }
        float rr = 1.0f / sum;
        for (int t = 0; t < 65; t++) {
            float p = sS[tid * 81 + t] * rr;
            __nv_bfloat16 hv = __float2bfloat16(p);
            sAh[tid * 88 + t] = hv;
            sAl[tid * 88 + t] = __float2bfloat16(p - __bfloat162float(hv));
        }
        for (int t = 65; t < 80; t++) {
            sAh[tid * 88 + t] = __float2bfloat16(0.f);
            sAl[tid * 88 + t] = __float2bfloat16(0.f);
        }
    }

    // ---- AV phase: O = attn @ P, 4 n-chunks of 128 ----
    const uint32_t sAhB = s2u(sAh), sAlB = s2u(sAl);
    const uint32_t sPhB = s2u(sPh), sPlB = s2u(sPl);

    for (int c = 0; c < 4; c++) {
        __syncthreads();
        for (int t2 = tid; t2 < 2560; t2 += 256) {
            int half = (t2 >= 1280) ? 1 : 0;
            int j = t2 - half * 1280;
            int r = j >> 4, ch = j & 15;
            int rr = (r < 65) ? r : 64;
            const __nv_bfloat16* src = (half ? g_Pl : g_Ph) + (tb + rr) * HID + c * 128 + ch * 8;
            __nv_bfloat16* dst = (half ? sPl : sPh) + r * 136 + ch * 8;
            *(uint4*)dst = *(const uint4*)src;
        }
        __syncthreads();

        float acc2[5][2][4];
#pragma unroll
        for (int mt = 0; mt < 5; mt++)
#pragma unroll
            for (int f = 0; f < 2; f++)
#pragma unroll
                for (int j = 0; j < 4; j++) acc2[mt][f][j] = 0.f;

#pragma unroll
        for (int kt = 0; kt < 5; kt++) {
            uint32_t bh[4], bl[4];
            uint32_t boff = (uint32_t)((kt * 16 + lane15) * 272 + wid * 32 + laneHi * 16);
            ldsm4t(bh[0], bh[1], bh[2], bh[3], sPhB + boff);
            ldsm4t(bl[0], bl[1], bl[2], bl[3], sPlB + boff);
            uint32_t b0h[2] = {bh[0], bh[1]}, b1h[2] = {bh[2], bh[3]};
            uint32_t b0l[2] = {bl[0], bl[1]}, b1l[2] = {bl[2], bl[3]};
#pragma unroll
            for (int mt = 0; mt < 5; mt++) {
                uint32_t ah[4], al[4];
                uint32_t aoff = (uint32_t)((mt * 16 + lane15) * 176 + kt * 32 + laneHi * 16);
                ldsm4(ah[0], ah[1], ah[2], ah[3], sAhB + aoff);
                ldsm4(al[0], al[1], al[2], al[3], sAlB + aoff);
                mma_bf16(acc2[mt][0], al, b0h);
                mma_bf16(acc2[mt][0], ah, b0l);
                mma_bf16(acc2[mt][0], ah, b0h);
                mma_bf16(acc2[mt][1], al, b1h);
                mma_bf16(acc2[mt][1], ah, b1l);
                mma_bf16(acc2[mt][1], ah, b1h);
            }
        }

        int r0 = lane >> 2;
        int cb = c * 128 + wid * 16 + (lane & 3) * 2;
#pragma unroll
        for (int mt = 0; mt < 5; mt++) {
            int s0 = mt * 16 + r0, s1 = s0 + 8;
#pragma unroll
            for (int f = 0; f < 2; f++) {
                int col = cb + f * 8;
                if (s0 < 65) {
                    float2 o; o.x = acc2[mt][f][0]; o.y = acc2[mt][f][1];
                    *(float2*)&g_O[(tb + s0) * HID + col] = o;
                }
                if (s1 < 65) {
                    float2 o; o.x = acc2[mt][f][2]; o.y = acc2[mt][f][3];
                    *(float2*)&g_O[(tb + s1) * HID + col] = o;
                }
            }
        }
    }
}

// ---------------- reduce: R = sum_h O_h + cvec + Z ----------------
__global__ void reduce_kernel()
{
    long i4 = (long)blockIdx.x * 256 + threadIdx.x;
    if (i4 >= (long)ROWS * HID / 4) return;
    int e4 = (int)(i4 & (HID / 4 - 1));
    float4 a = ((const float4*)g_Z)[i4];
    float4 cv = ((const float4*)g_cvec)[e4];
    a.x += cv.x; a.y += cv.y; a.z += cv.z; a.w += cv.w;
#pragma unroll
    for (int h = 0; h < HEADS; h++) {
        float4 o = ((const float4*)g_O)[(long)h * (ROWS * HID / 4) + i4];
        a.x += o.x; a.y += o.y; a.z += o.z; a.w += o.w;
    }
    ((float4*)g_R)[i4] = a;
}

// ---------------- classification head ----------------
__global__ void head_kernel(const float* __restrict__ Wh, const float* __restrict__ bh,
                            float* __restrict__ out)
{
    const int n = blockIdx.x;
    const int o = threadIdx.y;
    const int lane = threadIdx.x;
    const float* z = g_Z + (long)n * SEQ * HID;
    float a = 0.f;
    for (int e = lane; e < HID; e += 32) a += z[e] * Wh[e * OUTD + o];
#pragma unroll
    for (int off = 16; off; off >>= 1) a += __shfl_down_sync(0xffffffffu, a, off);
    if (lane == 0) out[n * OUTD + o] = tanhf(a + bh[o]);
}

// ---------------- host launcher ----------------
static float* sym_addr(const void* symbol)
{
    void* p = nullptr;
    cudaGetSymbolAddress(&p, symbol);
    return (float*)p;
}
static __nv_bfloat16* sym_addr_b(const void* symbol)
{
    void* p = nullptr;
    cudaGetSymbolAddress(&p, symbol);
    return (__nv_bfloat16*)p;
}

extern "C" void kernel_launch(void* const* d_in, const int* in_sizes, int n_in,
                              void* d_out, int out_size)
{
    const float* X    = (const float*)d_in[0];
    const float* Wp   = (const float*)d_in[1];
    const float* bp   = (const float*)d_in[2];
    const float* cls  = (const float*)d_in[3];
    const float* pos  = (const float*)d_in[4];
    const float* ln1w = (const float*)d_in[5];
    const float* ln1b = (const float*)d_in[6];
    const float* Wq   = (const float*)d_in[7];
    const float* bq   = (const float*)d_in[8];
    const float* Wk   = (const float*)d_in[9];
    const float* bk   = (const float*)d_in[10];
    const float* Wv   = (const float*)d_in[11];
    const float* bv   = (const float*)d_in[12];
    const float* Wo   = (const float*)d_in[13];
    const float* bo   = (const float*)d_in[14];
    const float* ln2w = (const float*)d_in[15];
    const float* ln2b = (const float*)d_in[16];
    const float* W2   = (const float*)d_in[17];
    const float* b2   = (const float*)d_in[18];
    const float* Wh   = (const float*)d_in[19];
    const float* bh   = (const float*)d_in[20];
    float* out = (float*)d_out;

    float* Z   = sym_addr(g_Z);
    float* R   = sym_addr(g_R);
    float* E   = sym_addr(g_E);
    float* Gf  = sym_addr(g_Gf);
    float* Uf  = sym_addr(g_Uf);
    __nv_bfloat16* Ah   = sym_addr_b(g_Ah),   *Al   = sym_addr_b(g_Al);
    __nv_bfloat16* Th   = sym_addr_b(g_Th);
    __nv_bfloat16* Ph   = sym_addr_b(g_Ph),   *Pl   = sym_addr_b(g_Pl);
    __nv_bfloat16* Wph  = sym_addr_b(g_Wph),  *Wpl  = sym_addr_b(g_Wpl);
    __nv_bfloat16* Wqh  = sym_addr_b(g_Wqh),  *Wql  = sym_addr_b(g_Wql);
    __nv_bfloat16* WkTh = sym_addr_b(g_WkTh), *WkTl = sym_addr_b(g_WkTl);
    __nv_bfloat16* Wvh  = sym_addr_b(g_Wvh),  *Wvl  = sym_addr_b(g_Wvl);
    __nv_bfloat16* Woh  = sym_addr_b(g_Woh),  *Wol  = sym_addr_b(g_Wol);
    __nv_bfloat16* W2h  = sym_addr_b(g_W2h),  *W2l  = sym_addr_b(g_W2l);
    __nv_bfloat16* Gh   = sym_addr_b(g_Gh),   *Gl   = sym_addr_b(g_Gl);
    __nv_bfloat16* Uh   = sym_addr_b(g_Uh),   *Ul   = sym_addr_b(g_Ul);

    const int GSM1 = 2 * (APL + BPL);
    const int GSM3 = 2 * (2 * APL + 2 * BPL);
    cudaFuncSetAttribute(gemm_t<1, 1>, cudaFuncAttributeMaxDynamicSharedMemorySize, GSM1);
    cudaFuncSetAttribute(gemm_t<3, 1>, cudaFuncAttributeMaxDynamicSharedMemorySize, GSM3);
    cudaFuncSetAttribute(gemm_t<3, 0>, cudaFuncAttributeMaxDynamicSharedMemorySize, GSM3);
    cudaFuncSetAttribute(attn_mma, cudaFuncAttributeMaxDynamicSharedMemorySize, AT_SMEM);

    const long WS = (long)HID * HID;
    const long QS = (long)ROWS * HID;
    const long W4 = (long)HEADS * HID * HID / 4;

    // ---- weight plane conversions ----
    conva<<<(PDIM * HID / 4 + 255) / 256, 256>>>(Wp, Wph, Wpl, PDIM * HID / 4);
    conva<<<(unsigned)((W4 + 255) / 256), 256>>>(Wq, Wqh, Wql, W4);
    convwT<<<dim3(HID / 32, HID / 32, HEADS), dim3(32, 8)>>>(Wk, WkTh, WkTl, HID, HID, WS);
    conva<<<(unsigned)((W4 + 255) / 256), 256>>>(Wv, Wvh, Wvl, W4);
    conva<<<(unsigned)((W4 + 255) / 256), 256>>>(Wo, Woh, Wol, W4);
    conva<<<(HID * HID / 4 + 255) / 256, 256>>>(W2, W2h, W2l, HID * HID / 4);

    // ---- folded weights: G = Wq WkT, U = Wv Wo_h ----
    gemm_t<3, 0><<<dim3(4, 4, HEADS), 256, GSM3>>>(Wqh, Wql, WkTh, WkTl, Gf, nullptr,
                                                   HID, HID, HID, nullptr, 0, nullptr, 0,
                                                   WS, WS, WS);
    gemm_t<3, 0><<<dim3(4, 4, HEADS), 256, GSM3>>>(Wvh, Wvl, Woh, Wol, Uf, nullptr,
                                                   HID, HID, HID, nullptr, 0, nullptr, 0,
                                                   WS, WS, WS);
    conva<<<(unsigned)((W4 + 255) / 256), 256>>>(Gf, Gh, Gl, W4);
    conva<<<(unsigned)((W4 + 255) / 256), 256>>>(Uf, Uh, Ul, W4);

    prep_bias<<<HEADS + 1, HID>>>(Wq, bq, Wk, bk, bv, Wo, bo);

    // ---- patch embed ----
    {
        long n4 = (long)NB * NP * PDIM / 4;
        conva<<<(unsigned)((n4 + 255) / 256), 256>>>(X, Ah, Al, n4);
        gemm_t<3, 0><<<dim3((NB * NP) / 128, HID / 128, 1), 256, GSM3>>>(
            Ah, Al, Wph, Wpl, E, nullptr, PDIM, HID, HID, bp, 0, nullptr, 0, 0, 0, 0);
    }
    {
        long total = (long)NB * SEQ * HID;
        assemble_kernel<<<(unsigned)((total + 255) / 256), 256>>>(cls, pos);
    }

    dim3 gProj(ROWS / 128, HID / 128, HEADS);
    dim3 gRow(ROWS / 128, HID / 128, 1);
    unsigned redGrid = (unsigned)((ROWS * HID / 4 + 255) / 256);

    for (int blk = 0; blk < 6; blk++) {
        ln_split<<<NB, 1024>>>(Z, Ah, Al, ln1w, ln1b);

        // T = Zn @ G (1-term, bf16-hi out), P = Zn @ U (3-term, bf16 planes out)
        gemm_t<1, 1><<<gProj, 256, GSM1>>>(Ah, Al, Gh, Gl, Th, nullptr,
                                           HID, HID, HID, nullptr, 0, nullptr, 0,
                                           0, WS, QS);
        gemm_t<3, 1><<<gProj, 256, GSM3>>>(Ah, Al, Uh, Ul, Ph, Pl,
                                           HID, HID, HID, nullptr, 0, nullptr, 0,
                                           0, WS, QS);

        // tensor-core attention
        attn_mma<<<dim3(HEADS, NB), 256, AT_SMEM>>>();

        // R = sum_h O_h + cvec + Z
        reduce_kernel<<<redGrid, 256>>>();

        // LN2 + W2
        ln_split<<<NB, 1024>>>(R, Ah, Al, ln2w, ln2b);
        gemm_t<3, 0><<<gRow, 256, GSM3>>>(Ah, Al, W2h, W2l, Z, nullptr,
                                          HID, HID, HID, b2, 0, nullptr, 0, 0, 0, 0);
    }

    head_kernel<<<NB, dim3(32, 10)>>>(Wh, bh, out);
    (void)in_sizes; (void)n_in; (void)out_size;
}

// round 17
// speedup vs baseline: 8.8395x; 1.0345x over previous
#include <cuda_runtime.h>
#include <cuda_bf16.h>
#include <cstdint>

#define NB      256      // batch
#define SEQ     65
#define HID     512
#define HEADS   8
#define NP      64       // patches
#define PDIM    256
#define ROWS    (NB*SEQ) // 16640
#define OUTD    10

// ---------------- fp32 scratch ----------------
__device__ float g_Z [NB*SEQ*HID];
__device__ float g_R [NB*SEQ*HID];
__device__ float g_E [NB*NP*HID];
__device__ float g_Gf[HEADS*HID*HID];    // G = Wq Wk^T (fp32)
__device__ float g_Uf[HEADS*HID*HID];    // U = Wv Wo_h (fp32)
__device__ float g_u [HEADS*HID];        // Wq @ bk
__device__ float g_w [HEADS*HID];        // Wk @ bq
__device__ float g_d [HEADS];            // bq . bk
__device__ float g_cvec[HID];            // sum_h bv_h @ Wo_h + bo

// ---------------- bf16 planes ----------------
__device__ __nv_bfloat16 g_Ah[ROWS*HID],          g_Al[ROWS*HID];        // Zn planes
__device__ __nv_bfloat16 g_Th[HEADS*ROWS*HID];                           // T hi (scores only)
__device__ __nv_bfloat16 g_Ph[HEADS*ROWS*HID],    g_Pl[HEADS*ROWS*HID];  // P planes
__device__ __nv_bfloat16 g_Sh[(long)HEADS*NB*6400];                      // probs hi [h][n][80][80]
__device__ __nv_bfloat16 g_Sl[(long)HEADS*NB*6400];                      // probs lo
__device__ __nv_bfloat16 g_Wph[PDIM*HID],         g_Wpl[PDIM*HID];
__device__ __nv_bfloat16 g_Wqh[HEADS*HID*HID],    g_Wql[HEADS*HID*HID];
__device__ __nv_bfloat16 g_WkTh[HEADS*HID*HID],   g_WkTl[HEADS*HID*HID];
__device__ __nv_bfloat16 g_Wvh[HEADS*HID*HID],    g_Wvl[HEADS*HID*HID];
__device__ __nv_bfloat16 g_Woh[HEADS*HID*HID],    g_Wol[HEADS*HID*HID];
__device__ __nv_bfloat16 g_W2h[HID*HID],          g_W2l[HID*HID];
__device__ __nv_bfloat16 g_Gh[HEADS*HID*HID],     g_Gl[HEADS*HID*HID];
__device__ __nv_bfloat16 g_Uh[HEADS*HID*HID],     g_Ul[HEADS*HID*HID];

// ---------------- PTX helpers ----------------
__device__ __forceinline__ uint32_t s2u(const void* p)
{
    uint32_t a;
    asm("{ .reg .u64 t; cvta.to.shared.u64 t, %1; cvt.u32.u64 %0, t; }" : "=r"(a) : "l"(p));
    return a;
}

__device__ __forceinline__ void cp16(uint32_t dst, const void* src)
{
    asm volatile("cp.async.cg.shared.global [%0], [%1], 16;" :: "r"(dst), "l"(src));
}

__device__ __forceinline__ void ldsm4(uint32_t& r0, uint32_t& r1, uint32_t& r2, uint32_t& r3,
                                      uint32_t addr)
{
    asm volatile("ldmatrix.sync.aligned.m8n8.x4.shared.b16 {%0,%1,%2,%3}, [%4];"
                 : "=r"(r0), "=r"(r1), "=r"(r2), "=r"(r3) : "r"(addr));
}

__device__ __forceinline__ void ldsm2(uint32_t& r0, uint32_t& r1, uint32_t addr)
{
    asm volatile("ldmatrix.sync.aligned.m8n8.x2.shared.b16 {%0,%1}, [%2];"
                 : "=r"(r0), "=r"(r1) : "r"(addr));
}

__device__ __forceinline__ void ldsm4t(uint32_t& r0, uint32_t& r1, uint32_t& r2, uint32_t& r3,
                                       uint32_t addr)
{
    asm volatile("ldmatrix.sync.aligned.m8n8.x4.trans.shared.b16 {%0,%1,%2,%3}, [%4];"
                 : "=r"(r0), "=r"(r1), "=r"(r2), "=r"(r3) : "r"(addr));
}

__device__ __forceinline__ void mma_bf16(float c[4], const uint32_t a[4], const uint32_t b[2])
{
    asm volatile(
        "mma.sync.aligned.m16n8k16.row.col.f32.bf16.bf16.f32 "
        "{%0,%1,%2,%3},{%4,%5,%6,%7},{%8,%9},{%0,%1,%2,%3};"
        : "+f"(c[0]), "+f"(c[1]), "+f"(c[2]), "+f"(c[3])
        : "r"(a[0]), "r"(a[1]), "r"(a[2]), "r"(a[3]),
          "r"(b[0]), "r"(b[1]));
}

__device__ __forceinline__ uint32_t packbf(float x0, float x1)
{
    __nv_bfloat16 h0 = __float2bfloat16(x0);
    __nv_bfloat16 h1 = __float2bfloat16(x1);
    return (uint32_t)__bfloat16_as_ushort(h0) | ((uint32_t)__bfloat16_as_ushort(h1) << 16);
}

// ---------------- bf16 GEMM, templated compensation depth + output mode ----------------
#define APL  10240            // A plane bytes: 128 * 40 elems * 2B
#define BPL  8704             // B plane bytes: 32 * 136 elems * 2B

template<int TERMS, int OUTBF>
__global__ __launch_bounds__(256)
void gemm_t(const __nv_bfloat16* __restrict__ Ah, const __nv_bfloat16* __restrict__ Al,
            const __nv_bfloat16* __restrict__ Bh, const __nv_bfloat16* __restrict__ Bl,
            void* __restrict__ Cv, void* __restrict__ Clv,
            int K, int ldb, int ldc,
            const float* __restrict__ bias, long biasStride,
            const float* __restrict__ res, int ldres,
            long strideA, long strideB, long strideC)
{
    constexpr int NPL = (TERMS == 3) ? 2 : 1;
    constexpr uint32_t BOFF = NPL * APL;
    constexpr uint32_t STG = NPL * (APL + BPL);

    extern __shared__ __align__(16) char smem[];
    const uint32_t sb = s2u(smem);

    const int tid = threadIdx.x, lane = tid & 31, wid = tid >> 5;
    const int warp_m = wid >> 2, warp_n = wid & 3;
    const int m0 = blockIdx.x * 128, n0 = blockIdx.y * 128;

    const __nv_bfloat16* Ahz = Ah + (long)blockIdx.z * strideA;
    const __nv_bfloat16* Alz = Al + (long)blockIdx.z * strideA;
    const __nv_bfloat16* Bhz = Bh + (long)blockIdx.z * strideB;
    const __nv_bfloat16* Blz = Bl + (long)blockIdx.z * strideB;
    const float* bz = bias ? (bias + (long)blockIdx.z * biasStride) : nullptr;

    const int lrow = (lane & 7) + ((lane >> 3) & 1) * 8;
    const int lcol = (lane >> 4) * 8;

    float acc[4][4][4];
#pragma unroll
    for (int mi = 0; mi < 4; mi++)
#pragma unroll
        for (int ni = 0; ni < 4; ni++)
#pragma unroll
            for (int j = 0; j < 4; j++) acc[mi][ni][j] = 0.f;

    const int NCH = K >> 5;

    auto issue = [&](int c) {
        const uint32_t st = sb + (uint32_t)(c & 1) * STG;
        const int k0 = c << 5;
        for (int l = 0; l < 2 * NPL; l++) {
            int idx = l * 256 + tid;
            int p = idx >> 9, rem = idx & 511, row = rem >> 2, ch = rem & 3;
            const __nv_bfloat16* src = (p ? Alz : Ahz) + (long)(m0 + row) * K + k0 + ch * 8;
            cp16(st + (uint32_t)(p * APL + row * 80 + ch * 16), src);
        }
        for (int l = 0; l < 2 * NPL; l++) {
            int idx = l * 256 + tid;
            int p = idx >> 9, rem = idx & 511, kr = rem >> 4, ch = rem & 15;
            const __nv_bfloat16* src = (p ? Blz : Bhz) + (long)(k0 + kr) * ldb + n0 + ch * 8;
            cp16(st + (uint32_t)(BOFF + p * BPL + kr * 272 + ch * 16), src);
        }
    };

    issue(0);
    asm volatile("cp.async.commit_group;" ::: "memory");

    for (int c = 0; c < NCH; c++) {
        if (c + 1 < NCH) issue(c + 1);
        asm volatile("cp.async.commit_group;" ::: "memory");
        asm volatile("cp.async.wait_group 1;" ::: "memory");
        __syncthreads();

        const uint32_t st = sb + (uint32_t)(c & 1) * STG;
        const uint32_t aS = st + (uint32_t)((warp_m * 64 + lrow) * 80 + lcol * 2);
        const uint32_t bS = st + BOFF + (uint32_t)(lrow * 272 + (warp_n * 32 + lcol) * 2);

#pragma unroll
        for (int ks = 0; ks < 2; ks++) {
            uint32_t ah[4][4], al[4][4], bh[4][2], bl[4][2];
#pragma unroll
            for (int mi = 0; mi < 4; mi++) {
                ldsm4(ah[mi][0], ah[mi][1], ah[mi][2], ah[mi][3], aS + mi * (16 * 80) + ks * 32);
                if (TERMS == 3)
                    ldsm4(al[mi][0], al[mi][1], al[mi][2], al[mi][3],
                          aS + APL + mi * (16 * 80) + ks * 32);
            }
#pragma unroll
            for (int nb = 0; nb < 2; nb++) {
                uint32_t r0, r1, r2, r3;
                ldsm4t(r0, r1, r2, r3, bS + nb * 32 + ks * (16 * 272));
                bh[nb * 2 + 0][0] = r0; bh[nb * 2 + 0][1] = r1;
                bh[nb * 2 + 1][0] = r2; bh[nb * 2 + 1][1] = r3;
                if (TERMS == 3) {
                    ldsm4t(r0, r1, r2, r3, bS + BPL + nb * 32 + ks * (16 * 272));
                    bl[nb * 2 + 0][0] = r0; bl[nb * 2 + 0][1] = r1;
                    bl[nb * 2 + 1][0] = r2; bl[nb * 2 + 1][1] = r3;
                }
            }
#pragma unroll
            for (int mi = 0; mi < 4; mi++)
#pragma unroll
                for (int ni = 0; ni < 4; ni++) {
                    if (TERMS == 3) {
                        mma_bf16(acc[mi][ni], al[mi], bh[ni]);
                        mma_bf16(acc[mi][ni], ah[mi], bl[ni]);
                    }
                    mma_bf16(acc[mi][ni], ah[mi], bh[ni]);
                }
        }
        __syncthreads();
    }

    const int r = lane >> 2, c2 = (lane & 3) << 1;
    if (OUTBF) {
        __nv_bfloat16* Ch = (__nv_bfloat16*)Cv + (long)blockIdx.z * strideC;
        __nv_bfloat16* Cl = Clv ? ((__nv_bfloat16*)Clv + (long)blockIdx.z * strideC) : nullptr;
#pragma unroll
        for (int mi = 0; mi < 4; mi++) {
#pragma unroll
            for (int hh = 0; hh < 2; hh++) {
                int m = m0 + warp_m * 64 + mi * 16 + hh * 8 + r;
#pragma unroll
                for (int ni = 0; ni < 4; ni++) {
                    int col = n0 + warp_n * 32 + ni * 8 + c2;
                    float x0 = acc[mi][ni][hh * 2 + 0];
                    float x1 = acc[mi][ni][hh * 2 + 1];
                    __nv_bfloat16 h0 = __float2bfloat16(x0);
                    __nv_bfloat16 h1 = __float2bfloat16(x1);
                    uint32_t hw = (uint32_t)__bfloat16_as_ushort(h0) |
                                  ((uint32_t)__bfloat16_as_ushort(h1) << 16);
                    *(uint32_t*)&Ch[(long)m * ldc + col] = hw;
                    if (Cl) {
                        uint32_t lw = packbf(x0 - __bfloat162float(h0),
                                             x1 - __bfloat162float(h1));
                        *(uint32_t*)&Cl[(long)m * ldc + col] = lw;
                    }
                }
            }
        }
    } else {
        float* Cz = (float*)Cv + (long)blockIdx.z * strideC;
#pragma unroll
        for (int mi = 0; mi < 4; mi++) {
#pragma unroll
            for (int hh = 0; hh < 2; hh++) {
                int m = m0 + warp_m * 64 + mi * 16 + hh * 8 + r;
#pragma unroll
                for (int ni = 0; ni < 4; ni++) {
                    int col = n0 + warp_n * 32 + ni * 8 + c2;
                    float x0 = acc[mi][ni][hh * 2 + 0];
                    float x1 = acc[mi][ni][hh * 2 + 1];
                    if (bz) { x0 += bz[col]; x1 += bz[col + 1]; }
                    if (res) {
                        float2 rr = *(const float2*)&res[(long)m * ldres + col];
                        x0 += rr.x; x1 += rr.y;
                    }
                    float2 o; o.x = x0; o.y = x1;
                    *(float2*)&Cz[(long)m * ldc + col] = o;
                }
            }
        }
    }
}

// ---------------- elementwise fp32 -> bf16 hi/lo planes ----------------
__global__ void conva(const float* __restrict__ A, __nv_bfloat16* __restrict__ hi,
                      __nv_bfloat16* __restrict__ lo, long n4)
{
    long i = (long)blockIdx.x * 256 + threadIdx.x;
    if (i >= n4) return;
    float4 f = ((const float4*)A)[i];
    float v[4] = {f.x, f.y, f.z, f.w};
    uint32_t hw[2], lw[2];
#pragma unroll
    for (int p = 0; p < 2; p++) {
        __nv_bfloat16 h0 = __float2bfloat16(v[p * 2 + 0]);
        __nv_bfloat16 h1 = __float2bfloat16(v[p * 2 + 1]);
        __nv_bfloat16 l0 = __float2bfloat16(v[p * 2 + 0] - __bfloat162float(h0));
        __nv_bfloat16 l1 = __float2bfloat16(v[p * 2 + 1] - __bfloat162float(h1));
        hw[p] = (uint32_t)__bfloat16_as_ushort(h0) | ((uint32_t)__bfloat16_as_ushort(h1) << 16);
        lw[p] = (uint32_t)__bfloat16_as_ushort(l0) | ((uint32_t)__bfloat16_as_ushort(l1) << 16);
    }
    ((uint2*)hi)[i] = make_uint2(hw[0], hw[1]);
    ((uint2*)lo)[i] = make_uint2(lw[0], lw[1]);
}

// ---------------- transpose-convert: W[z][d][e] -> planes [z][e][d] ----------------
__global__ void convwT(const float* __restrict__ W, __nv_bfloat16* __restrict__ hi,
                       __nv_bfloat16* __restrict__ lo, int D, int E, long str)
{
    __shared__ float t[32][33];
    const float* Wz = W + (long)blockIdx.z * str;
    __nv_bfloat16* hz = hi + (long)blockIdx.z * str;
    __nv_bfloat16* lz = lo + (long)blockIdx.z * str;
    int d0 = blockIdx.x * 32, e0 = blockIdx.y * 32;
    for (int r = threadIdx.y; r < 32; r += 8)
        t[r][threadIdx.x] = Wz[(long)(d0 + r) * E + e0 + threadIdx.x];
    __syncthreads();
    for (int r = threadIdx.y; r < 32; r += 8) {
        float v = t[threadIdx.x][r];
        __nv_bfloat16 h = __float2bfloat16(v);
        long o = (long)(e0 + r) * D + d0 + threadIdx.x;
        hz[o] = h;
        lz[o] = __float2bfloat16(v - __bfloat162float(h));
    }
}

// ---------------- bias precompute ----------------
__global__ void prep_bias(const float* __restrict__ Wq, const float* __restrict__ bq,
                          const float* __restrict__ Wk, const float* __restrict__ bk,
                          const float* __restrict__ bv, const float* __restrict__ Wo,
                          const float* __restrict__ bo)
{
    int h = blockIdx.x, t = threadIdx.x;
    if (h < HEADS) {
        const float* wq = Wq + (long)h * HID * HID + (long)t * HID;
        const float* wk = Wk + (long)h * HID * HID + (long)t * HID;
        const float* bkh = bk + h * HID;
        const float* bqh = bq + h * HID;
        float a = 0.f, b = 0.f;
        for (int e = 0; e < HID; e++) { a += wq[e] * bkh[e]; b += wk[e] * bqh[e]; }
        g_u[h * HID + t] = a;
        g_w[h * HID + t] = b;
        if (t == 0) {
            float dd = 0.f;
            for (int e = 0; e < HID; e++) dd += bqh[e] * bkh[e];
            g_d[h] = dd;
        }
    } else {
        float a = bo[t];
        for (int he = 0; he < HEADS * HID; he++) a += bv[he] * Wo[(long)he * HID + t];
        g_cvec[t] = a;
    }
}

// ---------------- assemble Z = concat(cls, E) + pos ----------------
__global__ void assemble_kernel(const float* __restrict__ cls, const float* __restrict__ pos)
{
    long idx = (long)blockIdx.x * 256 + threadIdx.x;
    if (idx >= (long)NB * SEQ * HID) return;
    int e = (int)(idx % HID);
    long r = idx / HID;
    int s = (int)(r % SEQ);
    long n = r / SEQ;
    float v = pos[s * HID + e];
    if (s == 0) v += cls[e];
    else        v += g_E[(n * NP + (s - 1)) * (long)HID + e];
    g_Z[idx] = v;
}

// ---------------- LayerNorm -> bf16 hi/lo planes ----------------
__global__ __launch_bounds__(1024)
void ln_split(const float* __restrict__ in,
              __nv_bfloat16* __restrict__ oh, __nv_bfloat16* __restrict__ ol,
              const float* __restrict__ w, const float* __restrict__ b)
{
    const int n = blockIdx.x;
    const float* x = in + (long)n * SEQ * HID;
    __nv_bfloat16* yh = oh + (long)n * SEQ * HID;
    __nv_bfloat16* yl = ol + (long)n * SEQ * HID;
    float s = 0.f, ss = 0.f;
    for (int i = threadIdx.x; i < SEQ * HID; i += 1024) {
        float v = x[i]; s += v; ss += v * v;
    }
    __shared__ float red[64];
#pragma unroll
    for (int o = 16; o; o >>= 1) {
        s  += __shfl_down_sync(0xffffffffu, s, o);
        ss += __shfl_down_sync(0xffffffffu, ss, o);
    }
    int wid = threadIdx.x >> 5, lane = threadIdx.x & 31;
    if (lane == 0) { red[wid] = s; red[32 + wid] = ss; }
    __syncthreads();
    if (threadIdx.x == 0) {
        float S = 0.f, SS = 0.f;
        for (int i = 0; i < 32; i++) { S += red[i]; SS += red[32 + i]; }
        float inv = 1.0f / (SEQ * HID);
        float mu = S * inv;
        float var = SS * inv - mu * mu;
        red[0] = mu; red[1] = rsqrtf(var + 1e-5f);
    }
    __syncthreads();
    float mu = red[0], rinv = red[1];
    for (int i = threadIdx.x; i < SEQ * HID; i += 1024) {
        float y = (x[i] - mu) * rinv * w[i] + b[i];
        __nv_bfloat16 h = __float2bfloat16(y);
        yh[i] = h;
        yl[i] = __float2bfloat16(y - __bfloat162float(h));
    }
}

// ---------------- attention scores per (h, n) -> probs bf16 hi/lo to global ----------------
// scores = Th . Znh^T (bf16 1-term) + rank-1 bias -> softmax (fp32) -> g_Sh/g_Sl [80][80]
__global__ __launch_bounds__(256)
void attn_score()
{
    __shared__ __nv_bfloat16 sT[80 * 40];
    __shared__ __nv_bfloat16 sZ[80 * 40];
    __shared__ float sS[80 * 81];
    __shared__ float sEqP[68 * 4];
    __shared__ float sEkP[68 * 4];
    __shared__ float sEkS[80];

    const int h = blockIdx.x, n = blockIdx.y;
    const int tid = threadIdx.x, lane = tid & 31, wid = tid >> 5;
    const int lane15 = lane & 15, laneHi = lane >> 4;

    const long tb = (long)h * ROWS + (long)n * SEQ;
    const __nv_bfloat16* ZnB = g_Ah + (long)n * SEQ * HID;
    const float* uh = g_u + h * HID;
    const float* wh = g_w + h * HID;

    // rank-1 bias partials
    {
        int s = tid >> 2, q = tid & 3;
        const __nv_bfloat16* zr = ZnB + (long)s * HID + q * 128;
        const float* up = uh + q * 128;
        const float* wp = wh + q * 128;
        float a = 0.f, b = 0.f;
        for (int j = 0; j < 128; j++) {
            float z = __bfloat162float(zr[j]);
            a += z * up[j]; b += z * wp[j];
        }
        sEqP[s * 4 + q] = a; sEkP[s * 4 + q] = b;
        if (tid < 4) {
            const __nv_bfloat16* zr2 = ZnB + (long)64 * HID + tid * 128;
            const float* up2 = uh + tid * 128;
            const float* wp2 = wh + tid * 128;
            float a2 = 0.f, b2 = 0.f;
            for (int j = 0; j < 128; j++) {
                float z = __bfloat162float(zr2[j]);
                a2 += z * up2[j]; b2 += z * wp2[j];
            }
            sEqP[64 * 4 + tid] = a2; sEkP[64 * 4 + tid] = b2;
        }
    }

    // score MMA: 50 m16n8 units over 8 warps
    float acc[7][4];
#pragma unroll
    for (int i = 0; i < 7; i++)
#pragma unroll
        for (int j = 0; j < 4; j++) acc[i][j] = 0.f;

    const uint32_t sTb = s2u(sT), sZb = s2u(sZ);

    for (int kc = 0; kc < 16; kc++) {
        for (int t2 = tid; t2 < 640; t2 += 256) {
            int half = (t2 >= 320) ? 1 : 0;
            int j = t2 - half * 320;
            int r = j >> 2, ch = j & 3;
            int rr = (r < 65) ? r : 64;
            const __nv_bfloat16* src = half
                ? (ZnB + (long)rr * HID + kc * 32 + ch * 8)
                : (g_Th + (tb + rr) * HID + kc * 32 + ch * 8);
            __nv_bfloat16* dst = (half ? sZ : sT) + r * 40 + ch * 8;
            *(uint4*)dst = *(const uint4*)src;
        }
        __syncthreads();
#pragma unroll
        for (int i = 0; i < 7; i++) {
            int u = wid + 8 * i;
            if (u < 50) {
                int mt = u / 10, nt = u - mt * 10;
#pragma unroll
                for (int ks = 0; ks < 2; ks++) {
                    uint32_t a[4], b[2];
                    ldsm4(a[0], a[1], a[2], a[3],
                          sTb + (uint32_t)((mt * 16 + lane15) * 80 + ks * 32 + laneHi * 16));
                    ldsm2(b[0], b[1],
                          sZb + (uint32_t)((nt * 8 + (lane & 7)) * 80 + ks * 32 + ((lane >> 3) & 1) * 16));
                    mma_bf16(acc[i], a, b);
                }
            }
        }
        __syncthreads();
    }

    // scores to sS
    {
        int r0 = lane >> 2, c0 = (lane & 3) * 2;
#pragma unroll
        for (int i = 0; i < 7; i++) {
            int u = wid + 8 * i;
            if (u < 50) {
                int mt = u / 10, nt = u - mt * 10;
                int rr = mt * 16 + r0, cc = nt * 8 + c0;
                sS[rr * 81 + cc] = acc[i][0];
                sS[rr * 81 + cc + 1] = acc[i][1];
                sS[(rr + 8) * 81 + cc] = acc[i][2];
                sS[(rr + 8) * 81 + cc + 1] = acc[i][3];
            }
        }
    }
    __syncthreads();

    if (tid < 65)
        sEkS[tid] = sEkP[tid * 4] + sEkP[tid * 4 + 1] + sEkP[tid * 4 + 2] + sEkP[tid * 4 + 3];
    __syncthreads();

    // softmax, normalized probs stored back into sS
    if (tid < 65) {
        const float scale = 1.0f / (512.0f * 512.0f);
        const float dh = g_d[h];
        float eqv = sEqP[tid * 4] + sEqP[tid * 4 + 1] + sEqP[tid * 4 + 2] + sEqP[tid * 4 + 3];
        float m = -1e30f;
        for (int t = 0; t < 65; t++) {
            float l = (sS[tid * 81 + t] + eqv + sEkS[t] + dh) * scale;
            sS[tid * 81 + t] = l;
            m = fmaxf(m, l);
        }
        float sum = 0.f;
        for (int t = 0; t < 65; t++) {
            float e = __expf(sS[tid * 81 + t] - m);
            sS[tid * 81 + t] = e; sum += e;
        }
        float rr = 1.0f / sum;
        for (int t = 0; t < 65; t++) sS[tid * 81 + t] *= rr;
    }
    __syncthreads();

    // cooperative split+store to global [80][80]
    {
        long gb = ((long)h * NB + n) * 6400;
        for (int idx = tid; idx < 6400; idx += 256) {
            int row = idx / 80, col = idx - row * 80;
            float p = (row < 65 && col < 65) ? sS[row * 81 + col] : 0.f;
            __nv_bfloat16 hv = __float2bfloat16(p);
            g_Sh[gb + idx] = hv;
            g_Sl[gb + idx] = __float2bfloat16(p - __bfloat162float(hv));
        }
    }
}

// ---------------- AV + head-sum + residual: R = sum_h attn_h @ P_h + Z + cvec ----------------
// grid (4 col-chunks, NB). SMEM: sAh/sAl [80][88], sPh/sPl [80][136].
#define AV_SMEM (2*(80*88*2) + 2*(80*136*2))   // 71680

__global__ __launch_bounds__(256)
void av_reduce()
{
    extern __shared__ __align__(16) char sm[];
    __nv_bfloat16* sAh = (__nv_bfloat16*)(sm);
    __nv_bfloat16* sAl = (__nv_bfloat16*)(sm + 14080);
    __nv_bfloat16* sPh = (__nv_bfloat16*)(sm + 28160);
    __nv_bfloat16* sPl = (__nv_bfloat16*)(sm + 49920);

    const int c = blockIdx.x, n = blockIdx.y;
    const int tid = threadIdx.x, lane = tid & 31, wid = tid >> 5;
    const int lane15 = lane & 15, laneHi = lane >> 4;

    const uint32_t sAhB = s2u(sAh), sAlB = s2u(sAl);
    const uint32_t sPhB = s2u(sPh), sPlB = s2u(sPl);

    float acc2[5][2][4];
#pragma unroll
    for (int mt = 0; mt < 5; mt++)
#pragma unroll
        for (int f = 0; f < 2; f++)
#pragma unroll
            for (int j = 0; j < 4; j++) acc2[mt][f][j] = 0.f;

    for (int h = 0; h < HEADS; h++) {
        __syncthreads();
        // probs: [80][80] global -> [80][88] smem (conflict-free stride)
        {
            long pb = ((long)h * NB + n) * 6400;
            for (int t2 = tid; t2 < 1600; t2 += 256) {
                int half = (t2 >= 800) ? 1 : 0;
                int j = t2 - half * 800;
                int r = j / 10, ch = j - r * 10;
                const __nv_bfloat16* src = (half ? g_Sl : g_Sh) + pb + (long)r * 80 + ch * 8;
                __nv_bfloat16* dst = (half ? sAl : sAh) + r * 88 + ch * 8;
                *(uint4*)dst = *(const uint4*)src;
            }
        }
        // P chunk: rows clamped (padding rows multiply zero prob cols)
        {
            long tb = (long)h * ROWS + (long)n * SEQ;
            for (int t2 = tid; t2 < 2560; t2 += 256) {
                int half = (t2 >= 1280) ? 1 : 0;
                int j = t2 - half * 1280;
                int r = j >> 4, ch = j & 15;
                int rr = (r < 65) ? r : 64;
                const __nv_bfloat16* src = (half ? g_Pl : g_Ph) + (tb + rr) * HID + c * 128 + ch * 8;
                __nv_bfloat16* dst = (half ? sPl : sPh) + r * 136 + ch * 8;
                *(uint4*)dst = *(const uint4*)src;
            }
        }
        __syncthreads();

#pragma unroll
        for (int kt = 0; kt < 5; kt++) {
            uint32_t bh[4], bl[4];
            uint32_t boff = (uint32_t)((kt * 16 + lane15) * 272 + wid * 32 + laneHi * 16);
            ldsm4t(bh[0], bh[1], bh[2], bh[3], sPhB + boff);
            ldsm4t(bl[0], bl[1], bl[2], bl[3], sPlB + boff);
            uint32_t b0h[2] = {bh[0], bh[1]}, b1h[2] = {bh[2], bh[3]};
            uint32_t b0l[2] = {bl[0], bl[1]}, b1l[2] = {bl[2], bl[3]};
#pragma unroll
            for (int mt = 0; mt < 5; mt++) {
                uint32_t ah[4], al[4];
                uint32_t aoff = (uint32_t)((mt * 16 + lane15) * 176 + kt * 32 + laneHi * 16);
                ldsm4(ah[0], ah[1], ah[2], ah[3], sAhB + aoff);
                ldsm4(al[0], al[1], al[2], al[3], sAlB + aoff);
                mma_bf16(acc2[mt][0], al, b0h);
                mma_bf16(acc2[mt][0], ah, b0l);
                mma_bf16(acc2[mt][0], ah, b0h);
                mma_bf16(acc2[mt][1], al, b1h);
                mma_bf16(acc2[mt][1], ah, b1l);
                mma_bf16(acc2[mt][1], ah, b1h);
            }
        }
    }

    // epilogue: R = acc + Z + cvec
    int r0 = lane >> 2;
    int cb = c * 128 + wid * 16 + (lane & 3) * 2;
    const long zb = (long)n * SEQ * HID;
#pragma unroll
    for (int mt = 0; mt < 5; mt++) {
        int s0 = mt * 16 + r0, s1 = s0 + 8;
#pragma unroll
        for (int f = 0; f < 2; f++) {
            int col = cb + f * 8;
            float2 cv = *(const float2*)&g_cvec[col];
            if (s0 < 65) {
                float2 z = *(const float2*)&g_Z[zb + (long)s0 * HID + col];
                float2 o;
                o.x = acc2[mt][f][0] + z.x + cv.x;
                o.y = acc2[mt][f][1] + z.y + cv.y;
                *(float2*)&g_R[zb + (long)s0 * HID + col] = o;
            }
            if (s1 < 65) {
                float2 z = *(const float2*)&g_Z[zb + (long)s1 * HID + col];
                float2 o;
                o.x = acc2[mt][f][2] + z.x + cv.x;
                o.y = acc2[mt][f][3] + z.y + cv.y;
                *(float2*)&g_R[zb + (long)s1 * HID + col] = o;
            }
        }
    }
}

// ---------------- classification head ----------------
__global__ void head_kernel(const float* __restrict__ Wh, const float* __restrict__ bh,
                            float* __restrict__ out)
{
    const int n = blockIdx.x;
    const int o = threadIdx.y;
    const int lane = threadIdx.x;
    const float* z = g_Z + (long)n * SEQ * HID;
    float a = 0.f;
    for (int e = lane; e < HID; e += 32) a += z[e] * Wh[e * OUTD + o];
#pragma unroll
    for (int off = 16; off; off >>= 1) a += __shfl_down_sync(0xffffffffu, a, off);
    if (lane == 0) out[n * OUTD + o] = tanhf(a + bh[o]);
}

// ---------------- host launcher ----------------
static float* sym_addr(const void* symbol)
{
    void* p = nullptr;
    cudaGetSymbolAddress(&p, symbol);
    return (float*)p;
}
static __nv_bfloat16* sym_addr_b(const void* symbol)
{
    void* p = nullptr;
    cudaGetSymbolAddress(&p, symbol);
    return (__nv_bfloat16*)p;
}

extern "C" void kernel_launch(void* const* d_in, const int* in_sizes, int n_in,
                              void* d_out, int out_size)
{
    const float* X    = (const float*)d_in[0];
    const float* Wp   = (const float*)d_in[1];
    const float* bp   = (const float*)d_in[2];
    const float* cls  = (const float*)d_in[3];
    const float* pos  = (const float*)d_in[4];
    const float* ln1w = (const float*)d_in[5];
    const float* ln1b = (const float*)d_in[6];
    const float* Wq   = (const float*)d_in[7];
    const float* bq   = (const float*)d_in[8];
    const float* Wk   = (const float*)d_in[9];
    const float* bk   = (const float*)d_in[10];
    const float* Wv   = (const float*)d_in[11];
    const float* bv   = (const float*)d_in[12];
    const float* Wo   = (const float*)d_in[13];
    const float* bo   = (const float*)d_in[14];
    const float* ln2w = (const float*)d_in[15];
    const float* ln2b = (const float*)d_in[16];
    const float* W2   = (const float*)d_in[17];
    const float* b2   = (const float*)d_in[18];
    const float* Wh   = (const float*)d_in[19];
    const float* bh   = (const float*)d_in[20];
    float* out = (float*)d_out;

    float* Z   = sym_addr(g_Z);
    float* R   = sym_addr(g_R);
    float* E   = sym_addr(g_E);
    float* Gf  = sym_addr(g_Gf);
    float* Uf  = sym_addr(g_Uf);
    __nv_bfloat16* Ah   = sym_addr_b(g_Ah),   *Al   = sym_addr_b(g_Al);
    __nv_bfloat16* Th   = sym_addr_b(g_Th);
    __nv_bfloat16* Ph   = sym_addr_b(g_Ph),   *Pl   = sym_addr_b(g_Pl);
    __nv_bfloat16* Wph  = sym_addr_b(g_Wph),  *Wpl  = sym_addr_b(g_Wpl);
    __nv_bfloat16* Wqh  = sym_addr_b(g_Wqh),  *Wql  = sym_addr_b(g_Wql);
    __nv_bfloat16* WkTh = sym_addr_b(g_WkTh), *WkTl = sym_addr_b(g_WkTl);
    __nv_bfloat16* Wvh  = sym_addr_b(g_Wvh),  *Wvl  = sym_addr_b(g_Wvl);
    __nv_bfloat16* Woh  = sym_addr_b(g_Woh),  *Wol  = sym_addr_b(g_Wol);
    __nv_bfloat16* W2h  = sym_addr_b(g_W2h),  *W2l  = sym_addr_b(g_W2l);
    __nv_bfloat16* Gh   = sym_addr_b(g_Gh),   *Gl   = sym_addr_b(g_Gl);
    __nv_bfloat16* Uh   = sym_addr_b(g_Uh),   *Ul   = sym_addr_b(g_Ul);

    const int GSM1 = 2 * (APL + BPL);
    const int GSM3 = 2 * (2 * APL + 2 * BPL);
    cudaFuncSetAttribute(gemm_t<1, 1>, cudaFuncAttributeMaxDynamicSharedMemorySize, GSM1);
    cudaFuncSetAttribute(gemm_t<3, 1>, cudaFuncAttributeMaxDynamicSharedMemorySize, GSM3);
    cudaFuncSetAttribute(gemm_t<3, 0>, cudaFuncAttributeMaxDynamicSharedMemorySize, GSM3);
    cudaFuncSetAttribute(av_reduce, cudaFuncAttributeMaxDynamicSharedMemorySize, AV_SMEM);

    const long WS = (long)HID * HID;
    const long QS = (long)ROWS * HID;
    const long W4 = (long)HEADS * HID * HID / 4;

    // ---- weight plane conversions ----
    conva<<<(PDIM * HID / 4 + 255) / 256, 256>>>(Wp, Wph, Wpl, PDIM * HID / 4);
    conva<<<(unsigned)((W4 + 255) / 256), 256>>>(Wq, Wqh, Wql, W4);
    convwT<<<dim3(HID / 32, HID / 32, HEADS), dim3(32, 8)>>>(Wk, WkTh, WkTl, HID, HID, WS);
    conva<<<(unsigned)((W4 + 255) / 256), 256>>>(Wv, Wvh, Wvl, W4);
    conva<<<(unsigned)((W4 + 255) / 256), 256>>>(Wo, Woh, Wol, W4);
    conva<<<(HID * HID / 4 + 255) / 256, 256>>>(W2, W2h, W2l, HID * HID / 4);

    // ---- folded weights: G = Wq WkT, U = Wv Wo_h ----
    gemm_t<3, 0><<<dim3(4, 4, HEADS), 256, GSM3>>>(Wqh, Wql, WkTh, WkTl, Gf, nullptr,
                                                   HID, HID, HID, nullptr, 0, nullptr, 0,
                                                   WS, WS, WS);
    gemm_t<3, 0><<<dim3(4, 4, HEADS), 256, GSM3>>>(Wvh, Wvl, Woh, Wol, Uf, nullptr,
                                                   HID, HID, HID, nullptr, 0, nullptr, 0,
                                                   WS, WS, WS);
    conva<<<(unsigned)((W4 + 255) / 256), 256>>>(Gf, Gh, Gl, W4);
    conva<<<(unsigned)((W4 + 255) / 256), 256>>>(Uf, Uh, Ul, W4);

    prep_bias<<<HEADS + 1, HID>>>(Wq, bq, Wk, bk, bv, Wo, bo);

    // ---- patch embed ----
    {
        long n4 = (long)NB * NP * PDIM / 4;
        conva<<<(unsigned)((n4 + 255) / 256), 256>>>(X, Ah, Al, n4);
        gemm_t<3, 0><<<dim3((NB * NP) / 128, HID / 128, 1), 256, GSM3>>>(
            Ah, Al, Wph, Wpl, E, nullptr, PDIM, HID, HID, bp, 0, nullptr, 0, 0, 0, 0);
    }
    {
        long total = (long)NB * SEQ * HID;
        assemble_kernel<<<(unsigned)((total + 255) / 256), 256>>>(cls, pos);
    }

    dim3 gProj(ROWS / 128, HID / 128, HEADS);
    dim3 gRow(ROWS / 128, HID / 128, 1);

    for (int blk = 0; blk < 6; blk++) {
        ln_split<<<NB, 1024>>>(Z, Ah, Al, ln1w, ln1b);

        // T = Zn @ G (1-term, bf16-hi out), P = Zn @ U (3-term, bf16 planes out)
        gemm_t<1, 1><<<gProj, 256, GSM1>>>(Ah, Al, Gh, Gl, Th, nullptr,
                                           HID, HID, HID, nullptr, 0, nullptr, 0,
                                           0, WS, QS);
        gemm_t<3, 1><<<gProj, 256, GSM3>>>(Ah, Al, Uh, Ul, Ph, Pl,
                                           HID, HID, HID, nullptr, 0, nullptr, 0,
                                           0, WS, QS);

        // scores + softmax -> probs planes
        attn_score<<<dim3(HEADS, NB), 256>>>();

        // AV + head-sum + residual -> R
        av_reduce<<<dim3(4, NB), 256, AV_SMEM>>>();

        // LN2 + W2
        ln_split<<<NB, 1024>>>(R, Ah, Al, ln2w, ln2b);
        gemm_t<3, 0><<<gRow, 256, GSM3>>>(Ah, Al, W2h, W2l, Z, nullptr,
                                          HID, HID, HID, b2, 0, nullptr, 0, 0, 0, 0);
    }

    head_kernel<<<NB, dim3(32, 10)>>>(Wh, bh, out);
    (void)in_sizes; (void)n_in; (void)out_size;
}